// round 8
// baseline (speedup 1.0000x reference)
#include <cuda_runtime.h>
#include <cuda_bf16.h>
#include <math.h>
#include <float.h>
#include <stdint.h>

#define BB 8
#define NQ 4096
#define QD 1280
#define CD 1024
#define CTX 85
#define NHEADS 20
#define DHEAD 64
#define INNER (NHEADS*DHEAD)   // 1280
#define MKV 768
#define NBH (BB*NHEADS)        // 160

typedef unsigned short ushort_t;

// ---------------- scratch (static device globals; no allocation) -------------
__device__ float g_k [(size_t)MKV*INNER];
__device__ float g_v [(size_t)MKV*INNER];
__device__ __nv_bfloat16 g_qhi[(size_t)BB*NQ*INNER];
__device__ __nv_bfloat16 g_qlo[(size_t)BB*NQ*INNER];
__device__ __nv_bfloat16 g_ao_hi[(size_t)BB*NQ*INNER];
__device__ __nv_bfloat16 g_ao_lo[(size_t)BB*NQ*INNER];
__device__ __nv_bfloat16 g_wqt_hi[(size_t)INNER*QD];
__device__ __nv_bfloat16 g_wqt_lo[(size_t)INNER*QD];
__device__ __nv_bfloat16 g_wkt_hi[(size_t)INNER*CD];
__device__ __nv_bfloat16 g_wkt_lo[(size_t)INNER*CD];
__device__ __nv_bfloat16 g_wvt_hi[(size_t)INNER*CD];
__device__ __nv_bfloat16 g_wvt_lo[(size_t)INNER*CD];
__device__ __nv_bfloat16 g_wot_hi[(size_t)QD*INNER];
__device__ __nv_bfloat16 g_wot_lo[(size_t)QD*INNER];
__device__ __nv_bfloat16 g_kimg_hi[(size_t)NBH*96*64];
__device__ __nv_bfloat16 g_kimg_lo[(size_t)NBH*96*64];
__device__ __nv_bfloat16 g_vimg_hi[(size_t)NBH*64*128];
__device__ __nv_bfloat16 g_vimg_lo[(size_t)NBH*64*128];
__device__ unsigned char g_fg[BB*NQ];

// ============================ PTX helpers ====================================
__device__ __forceinline__ uint32_t smem_to_u32(const void* p) {
    uint32_t a;
    asm("{ .reg .u64 t; cvta.to.shared.u64 t, %1; cvt.u32.u64 %0, t; }"
        : "=r"(a) : "l"(p));
    return a;
}

#if defined(__CUDA_ARCH_FEAT_SM103_ALL)
#define HAS_TCGEN05 1
#else
#define HAS_TCGEN05 0
#endif

#if HAS_TCGEN05
__device__ __forceinline__ uint32_t elect_one_pred() {
    uint32_t pred;
    asm volatile(
        "{\n\t.reg .pred p;\n\t"
        "elect.sync _|p, 0xFFFFFFFF;\n\t"
        "selp.b32 %0, 1, 0, p;\n\t}"
        : "=r"(pred));
    return pred;
}
#define TCGEN05_ALLOC(sa, n) \
    asm volatile("tcgen05.alloc.cta_group::1.sync.aligned.shared::cta.b32 [%0], %1;" \
        :: "r"((uint32_t)(sa)), "r"((uint32_t)(n)) : "memory")
#define TCGEN05_DEALLOC(t, n) \
    asm volatile("tcgen05.dealloc.cta_group::1.sync.aligned.b32 %0, %1;" :: "r"(t), "r"((uint32_t)(n)))
#define TCGEN05_RELINQ() \
    asm volatile("tcgen05.relinquish_alloc_permit.cta_group::1.sync.aligned;")
#define TCGEN05_COMMIT(mb) \
    asm volatile("tcgen05.commit.cta_group::1.mbarrier::arrive::one.shared::cluster.b64 [%0];" \
        :: "r"((uint32_t)(mb)) : "memory")
#define TCGEN05_FENCE_AFTER() asm volatile("tcgen05.fence::after_thread_sync;" ::: "memory")
#define TCGEN05_FENCE_BEFORE() asm volatile("tcgen05.fence::before_thread_sync;" ::: "memory")
#define TCGEN05_WAIT_LD() asm volatile("tcgen05.wait::ld.sync.aligned;" ::: "memory")
#define FENCE_ASYNC() asm volatile("fence.proxy.async.shared::cta;" ::: "memory")
#define MBARRIER_INIT(mb, c) \
    asm volatile("mbarrier.init.shared.b64 [%0], %1;" :: "r"((uint32_t)(mb)), "r"((uint32_t)(c)) : "memory")
#define MBARRIER_WAIT_PARITY(mb, ph) do { \
    uint32_t _m = (uint32_t)(mb), _p = (uint32_t)(ph), _d; \
    asm volatile("{\n\t.reg .pred p;\n\t" \
        "mbarrier.try_wait.parity.acquire.cta.shared::cta.b64 p, [%1], %2;\n\t" \
        "selp.b32 %0, 1, 0, p;\n\t}" : "=r"(_d) : "r"(_m), "r"(_p) : "memory"); \
    if (!_d) { \
        asm volatile("{\n\t.reg .pred P1;\n\t" \
            "WL_%=:\n\t" \
            "mbarrier.try_wait.parity.acquire.cta.shared::cta.b64 P1, [%0], %1, 0x989680;\n\t" \
            "@P1 bra.uni WD_%=;\n\t" \
            "bra.uni WL_%=;\n\t" \
            "WD_%=:\n\t}" :: "r"(_m), "r"(_p) : "memory"); \
    } \
} while (0)
#define TCGEN05_LD_32X32B_X32(r, ta) \
    asm volatile("tcgen05.ld.sync.aligned.32x32b.x32.b32 " \
        "{%0, %1, %2, %3, %4, %5, %6, %7, %8, %9, %10, %11, %12, %13, %14, %15, " \
        " %16, %17, %18, %19, %20, %21, %22, %23, %24, %25, %26, %27, %28, %29, %30, %31}, [%32];" \
        : "=r"((r)[0]),  "=r"((r)[1]),  "=r"((r)[2]),  "=r"((r)[3]), \
          "=r"((r)[4]),  "=r"((r)[5]),  "=r"((r)[6]),  "=r"((r)[7]), \
          "=r"((r)[8]),  "=r"((r)[9]),  "=r"((r)[10]), "=r"((r)[11]), \
          "=r"((r)[12]), "=r"((r)[13]), "=r"((r)[14]), "=r"((r)[15]), \
          "=r"((r)[16]), "=r"((r)[17]), "=r"((r)[18]), "=r"((r)[19]), \
          "=r"((r)[20]), "=r"((r)[21]), "=r"((r)[22]), "=r"((r)[23]), \
          "=r"((r)[24]), "=r"((r)[25]), "=r"((r)[26]), "=r"((r)[27]), \
          "=r"((r)[28]), "=r"((r)[29]), "=r"((r)[30]), "=r"((r)[31]) \
        : "r"(ta))

__device__ __forceinline__ void mma_f16_ss(uint32_t d_tmem, uint64_t a_desc,
                                           uint64_t b_desc, uint32_t idesc, bool acc)
{
    uint32_t en = acc ? 1u : 0u;
    asm volatile(
        "{\n\t.reg .pred p;\n\t"
        "setp.ne.u32 p, %5, 0;\n\t"
        "tcgen05.mma.cta_group::1.kind::f16 [%0], %1, %2, %3, {%4, %4, %4, %4}, p;\n\t}"
        :: "r"(d_tmem), "l"(a_desc), "l"(b_desc), "r"(idesc), "r"(0u), "r"(en)
        : "memory");
}
#endif // HAS_TCGEN05

static constexpr uint64_t SMEM_DESC_BASE_SW128 =
    (uint64_t(2)  << 61) | (uint64_t(1) << 46) | (uint64_t(64) << 32) | (uint64_t(1) << 16);
static constexpr uint64_t SMEM_DESC_BASE_SW64 =
    (uint64_t(4)  << 61) | (uint64_t(1) << 46) | (uint64_t(32) << 32) | (uint64_t(1) << 16);
#define MAKE_SMEM_DESC(ba)   (SMEM_DESC_BASE_SW128 | ((uint64_t)((ba) >> 4) & 0x3FFF))
#define MAKE_SMEM_DESC64(ba) (SMEM_DESC_BASE_SW64  | ((uint64_t)((ba) >> 4) & 0x3FFF))
#define SMEM_SWIZZLE_128B(bo) ((bo) ^ (((bo) >> 3) & 0x70))
#define SMEM_SWIZZLE_64B(bo)  ((bo) ^ (((bo) >> 3) & 0x30))

__device__ __forceinline__ void bf16split(float f, ushort_t& h, ushort_t& l)
{
    __nv_bfloat16 hh = __float2bfloat16(f);
    __nv_bfloat16 ll = __float2bfloat16(f - __bfloat162float(hh));
    h = __bfloat16_as_ushort(hh);
    l = __bfloat16_as_ushort(ll);
}

// ---------------- mask: exact integer bicubic-threshold ----------------------
__global__ void mask_kernel(const int* __restrict__ mask)
{
    int idx = blockIdx.x * blockDim.x + threadIdx.x;
    if (idx >= BB*NQ) return;
    int b = idx / NQ, n = idx % NQ;
    int o = n >> 6, p = n & 63;
    const int iw[4] = {-3, 19, 19, -3};
    const int* mb = mask + (size_t)b * 256 * 256;
    int acc = 0;
#pragma unroll
    for (int s = 0; s < 4; s++) {
        const int* row = mb + (4*o + s) * 256 + 4*p;
        int rw = iw[s];
#pragma unroll
        for (int t = 0; t < 4; t++) acc += rw * iw[t] * row[t];
    }
    g_fg[idx] = (acc != 0) ? 1 : 0;
}

// ---------------- weight transpose + bf16 split -------------------------------
__global__ void wtrans_kernel(const float* __restrict__ W,
                              __nv_bfloat16* __restrict__ Thi,
                              __nv_bfloat16* __restrict__ Tlo, int K, int N)
{
    __shared__ float t[32][33];
    int k0 = blockIdx.x * 32, n0 = blockIdx.y * 32;
    int tx = threadIdx.x, ty = threadIdx.y;
    for (int r = ty; r < 32; r += 8)
        t[r][tx] = W[(size_t)(k0 + r)*N + n0 + tx];
    __syncthreads();
    for (int r = ty; r < 32; r += 8) {
        float v = t[tx][r];
        ushort_t h, l; bf16split(v, h, l);
        Thi[(size_t)(n0 + r)*K + k0 + tx] = __ushort_as_bfloat16(h);
        Tlo[(size_t)(n0 + r)*K + k0 + tx] = __ushort_as_bfloat16(l);
    }
}

// ================= bf16x3 tcgen05 GEMM: C = A@B^T (+bias) ====================
// BK=32 (SW64 rows), 48KB stage, double-buffered -> 2 CTAs resident per SM.
// Register-prefetched: chunk c+1's global loads issue right after MMA commit c.
#define G_BM 128
#define G_BN 256
#define G_BK 32
#define G_BUFSZ 49152      // Ahi 8K | Alo 8K | Bhi 16K | Blo 16K
#define G_SMEM  (2048 + 2*G_BUFSZ)   // 100352 -> 2 CTAs/SM
#define G_IDESC 0x08400490u   // F32 acc, BF16xBF16, N=256, M=128

__global__ void __launch_bounds__(256, 2)
gemm_bf16x3(const float* __restrict__ Af,
            const __nv_bfloat16* __restrict__ Ahi, const __nv_bfloat16* __restrict__ Alo,
            const __nv_bfloat16* __restrict__ Bhi, const __nv_bfloat16* __restrict__ Blo,
            const float* __restrict__ bias, float* __restrict__ C,
            __nv_bfloat16* __restrict__ Chi, __nv_bfloat16* __restrict__ Clo,
            int Mvalid, int N, int K)
{
#if HAS_TCGEN05
    extern __shared__ char smem[];
    const uint32_t sb = smem_to_u32(smem);
    const uint32_t ab = (sb + 1024 + 1023) & ~1023u;
    char* abp = smem + (ab - sb);
    const int tid = threadIdx.x;
    const int wid = tid >> 5, lane = tid & 31;
    const int brow = blockIdx.y * G_BM;
    const int bcol = blockIdx.x * G_BN;

    if (wid == 0) TCGEN05_ALLOC(sb, 256);
    __syncthreads();
    uint32_t tmem;
    asm volatile("ld.shared.b32 %0, [%1];" : "=r"(tmem) : "r"(sb));
    if (wid == 0) TCGEN05_RELINQ();
    if (tid == 0) { MBARRIER_INIT(sb + 8, 1); MBARRIER_INIT(sb + 16, 1); }
    __syncthreads();

    const int KCH = K / G_BK;
    int par0 = 0, par1 = 0;

    // per-thread mapping: A row = tid>>1, half = tid&1 (16 fp32 / 32B bf16);
    // B row = tid (64B hi + 64B lo).
    const int a_row = tid >> 1;
    const int a_half = tid & 1;

    uint4 pah[2], pal[2], pbh[4], pbl[4];

    auto load_chunk = [&](int c) {
        const int k0 = c * G_BK;
        int gr = brow + a_row;
        if (Af) {
            float fa[16];
            if (gr < Mvalid) {
                const float4* src = (const float4*)(Af + (size_t)gr*K + k0 + a_half*16);
                float4 a0 = src[0], a1 = src[1], a2 = src[2], a3 = src[3];
                fa[0]=a0.x; fa[1]=a0.y; fa[2]=a0.z; fa[3]=a0.w;
                fa[4]=a1.x; fa[5]=a1.y; fa[6]=a1.z; fa[7]=a1.w;
                fa[8]=a2.x; fa[9]=a2.y; fa[10]=a2.z; fa[11]=a2.w;
                fa[12]=a3.x; fa[13]=a3.y; fa[14]=a3.z; fa[15]=a3.w;
            } else {
#pragma unroll
                for (int e = 0; e < 16; ++e) fa[e] = 0.f;
            }
#pragma unroll
            for (int q = 0; q < 2; ++q) {
                uint32_t hw[4], lw[4];
#pragma unroll
                for (int e = 0; e < 4; ++e) {
                    ushort_t h0, l0, h1, l1;
                    bf16split(fa[q*8 + 2*e],   h0, l0);
                    bf16split(fa[q*8 + 2*e+1], h1, l1);
                    hw[e] = ((uint32_t)h1 << 16) | h0;
                    lw[e] = ((uint32_t)l1 << 16) | l0;
                }
                pah[q] = make_uint4(hw[0], hw[1], hw[2], hw[3]);
                pal[q] = make_uint4(lw[0], lw[1], lw[2], lw[3]);
            }
        } else {
            const uint4* srch = (const uint4*)(Ahi + (size_t)gr*K + k0 + a_half*16);
            const uint4* srcl = (const uint4*)(Alo + (size_t)gr*K + k0 + a_half*16);
            pah[0] = srch[0]; pah[1] = srch[1];
            pal[0] = srcl[0]; pal[1] = srcl[1];
        }
        {
            const uint4* bh = (const uint4*)(Bhi + (size_t)(bcol + tid)*K + k0);
            const uint4* bl = (const uint4*)(Blo + (size_t)(bcol + tid)*K + k0);
#pragma unroll
            for (int j = 0; j < 4; ++j) { pbh[j] = bh[j]; pbl[j] = bl[j]; }
        }
    };

    load_chunk(0);

    for (int c = 0; c < KCH; ++c) {
        int p = c & 1;
        if (c >= 2) {
            if (p == 0) { MBARRIER_WAIT_PARITY(sb + 8, par0); par0 ^= 1; }
            else        { MBARRIER_WAIT_PARITY(sb + 16, par1); par1 ^= 1; }
        }
        char* base = abp + p * G_BUFSZ;

        // A: 64B rows, SW64
#pragma unroll
        for (int j = 0; j < 2; ++j) {
            uint32_t so = SMEM_SWIZZLE_64B((uint32_t)(a_row*64 + a_half*32 + j*16));
            *(uint4*)(base + so) = pah[j];
            *(uint4*)(base + 8192 + so) = pal[j];
        }
        // B: 64B rows, SW64
#pragma unroll
        for (int j = 0; j < 4; ++j) {
            uint32_t so = SMEM_SWIZZLE_64B((uint32_t)(tid*64 + j*16));
            *(uint4*)(base + 16384 + so) = pbh[j];
            *(uint4*)(base + 32768 + so) = pbl[j];
        }
        __syncthreads();

        if (wid == 0 && elect_one_pred()) {
            FENCE_ASYNC();
            uint32_t bu = ab + p * G_BUFSZ;
            uint64_t dah = MAKE_SMEM_DESC64(bu);
            uint64_t dal = MAKE_SMEM_DESC64(bu + 8192);
            uint64_t dbh = MAKE_SMEM_DESC64(bu + 16384);
            uint64_t dbl = MAKE_SMEM_DESC64(bu + 32768);
#pragma unroll
            for (int ks = 0; ks < 2; ++ks)
                mma_f16_ss(tmem, dah + ks*2, dbh + ks*2, G_IDESC, !(c == 0 && ks == 0));
#pragma unroll
            for (int ks = 0; ks < 2; ++ks)
                mma_f16_ss(tmem, dah + ks*2, dbl + ks*2, G_IDESC, true);
#pragma unroll
            for (int ks = 0; ks < 2; ++ks)
                mma_f16_ss(tmem, dal + ks*2, dbh + ks*2, G_IDESC, true);
            TCGEN05_COMMIT(sb + 8 + p*8);
        }

        if (c + 1 < KCH) load_chunk(c + 1);
    }
    MBARRIER_WAIT_PARITY(sb + 8, par0);
    MBARRIER_WAIT_PARITY(sb + 16, par1);
    TCGEN05_FENCE_AFTER();

    if (wid < 4) {
        int row = brow + wid*32 + lane;
#pragma unroll
        for (int cb = 0; cb < G_BN/32; ++cb) {
            uint32_t r[32];
            TCGEN05_LD_32X32B_X32(r, tmem + cb*32);
            TCGEN05_WAIT_LD();
            int col0 = bcol + cb*32;
            if (Chi) {
                uint32_t hp[16], lp[16];
#pragma unroll
                for (int m = 0; m < 16; ++m) {
                    ushort_t h0, l0, h1, l1;
                    bf16split(__uint_as_float(r[2*m]),   h0, l0);
                    bf16split(__uint_as_float(r[2*m+1]), h1, l1);
                    hp[m] = ((uint32_t)h1 << 16) | h0;
                    lp[m] = ((uint32_t)l1 << 16) | l0;
                }
                uint32_t* dh = (uint32_t*)(Chi + (size_t)row*N + col0);
                uint32_t* dl = (uint32_t*)(Clo + (size_t)row*N + col0);
#pragma unroll
                for (int m = 0; m < 16; ++m) { dh[m] = hp[m]; dl[m] = lp[m]; }
            } else {
                float* cp = C + (size_t)row*N + col0;
                if (bias) {
#pragma unroll
                    for (int i = 0; i < 32; ++i) cp[i] = __uint_as_float(r[i]) + bias[col0 + i];
                } else {
#pragma unroll
                    for (int i = 0; i < 32; ++i) cp[i] = __uint_as_float(r[i]);
                }
            }
        }
        TCGEN05_FENCE_BEFORE();
    }
    __syncthreads();
    if (wid == 0) TCGEN05_DEALLOC(tmem, 256);
#endif
}

// ---------------- K / V^T image bake (swizzled SMEM images) -------------------
__global__ void __launch_bounds__(128) kv_image_kernel()
{
    int bh = blockIdx.x;
    int b = bh / NHEADS, h = bh % NHEADS;
    int tid = threadIdx.x;
    char* kh = (char*)(g_kimg_hi + (size_t)bh*96*64);
    char* kl = (char*)(g_kimg_lo + (size_t)bh*96*64);
    char* vh = (char*)(g_vimg_hi + (size_t)bh*64*128);
    char* vl = (char*)(g_vimg_lo + (size_t)bh*64*128);

    for (int u = tid; u < 96*64; u += 128) {
        int j = u >> 6, d = u & 63;
        float f = (j < CTX) ? g_k[(size_t)(b*CTX + j)*INNER + h*DHEAD + d] : 0.f;
        ushort_t hh, ll; bf16split(f, hh, ll);
        uint32_t so = SMEM_SWIZZLE_128B((uint32_t)(j*128 + d*2));
        *(ushort_t*)(kh + so) = hh;
        *(ushort_t*)(kl + so) = ll;
    }
    for (int u = tid; u < 64*128; u += 128) {
        int d = u >> 7, j = u & 127;
        float f = (j < CTX) ? g_v[(size_t)(b*CTX + j)*INNER + h*DHEAD + d] : 0.f;
        ushort_t hh, ll; bf16split(f, hh, ll);
        uint32_t addr = (uint32_t)(((d >> 3) + (j >> 6)*8)*1024 + (d & 7)*128 + (j & 63)*2);
        uint32_t so = SMEM_SWIZZLE_128B(addr);
        *(ushort_t*)(vh + so) = hh;
        *(ushort_t*)(vl + so) = ll;
    }
}

// ---------------- tcgen05 fused masked attention ------------------------------
#define ATT_QT 4
#define A_QHI 0
#define A_QLO 16384
#define A_KHI 32768
#define A_KLO 45056
#define A_VHI 57344
#define A_VLO 73728
#define A_PHI 90112
#define A_PLO 122880
#define ATTN_SMEM (2048 + 155648)
#define IDESC_S 0x08180490u   // M=128, N=96
#define IDESC_O 0x08100490u   // M=128, N=64

__global__ void __launch_bounds__(128) attn_tc()
{
#if HAS_TCGEN05
    extern __shared__ char smem[];
    const uint32_t sb = smem_to_u32(smem);
    const uint32_t ab = (sb + 1024 + 1023) & ~1023u;
    char* abp = smem + (ab - sb);
    int tid = threadIdx.x, wid = tid >> 5;
    int b = blockIdx.z, h = blockIdx.y, qg = blockIdx.x;
    int bh = b*NHEADS + h;

    if (wid == 0) TCGEN05_ALLOC(sb, 256);
    __syncthreads();
    uint32_t tmem;
    asm volatile("ld.shared.b32 %0, [%1];" : "=r"(tmem) : "r"(sb));
    if (wid == 0) TCGEN05_RELINQ();
    if (tid == 0) { MBARRIER_INIT(sb + 8, 1); MBARRIER_INIT(sb + 16, 1); }
    __syncthreads();

    {
        const uint4* skh = (const uint4*)(g_kimg_hi + (size_t)bh*96*64);
        const uint4* skl = (const uint4*)(g_kimg_lo + (size_t)bh*96*64);
        for (int u = tid; u < 768; u += 128) {
            ((uint4*)(abp + A_KHI))[u] = skh[u];
            ((uint4*)(abp + A_KLO))[u] = skl[u];
        }
        const uint4* svh = (const uint4*)(g_vimg_hi + (size_t)bh*64*128);
        const uint4* svl = (const uint4*)(g_vimg_lo + (size_t)bh*64*128);
        for (int u = tid; u < 1024; u += 128) {
            ((uint4*)(abp + A_VHI))[u] = svh[u];
            ((uint4*)(abp + A_VLO))[u] = svl[u];
        }
    }

    int par0 = 0, par1 = 0;
    for (int qt = 0; qt < ATT_QT; ++qt) {
        int qbase = (qg*ATT_QT + qt)*128;
        size_t qrow = (size_t)(b*NQ + qbase + tid)*INNER + h*DHEAD;
        {
            const uint4* qh = (const uint4*)(g_qhi + qrow);
            const uint4* ql = (const uint4*)(g_qlo + qrow);
#pragma unroll
            for (int v = 0; v < 8; ++v) {
                uint32_t so = SMEM_SWIZZLE_128B((uint32_t)(tid*128 + v*16));
                *(uint4*)(abp + A_QHI + so) = qh[v];
                *(uint4*)(abp + A_QLO + so) = ql[v];
            }
        }
        __syncthreads();
        if (wid == 0 && elect_one_pred()) {
            FENCE_ASYNC();
            uint64_t dqh = MAKE_SMEM_DESC(ab + A_QHI);
            uint64_t dql = MAKE_SMEM_DESC(ab + A_QLO);
            uint64_t dkh = MAKE_SMEM_DESC(ab + A_KHI);
            uint64_t dkl = MAKE_SMEM_DESC(ab + A_KLO);
#pragma unroll
            for (int ks = 0; ks < 4; ++ks)
                mma_f16_ss(tmem, dqh + ks*2, dkh + ks*2, IDESC_S, ks > 0);
#pragma unroll
            for (int ks = 0; ks < 4; ++ks)
                mma_f16_ss(tmem, dqh + ks*2, dkl + ks*2, IDESC_S, true);
#pragma unroll
            for (int ks = 0; ks < 4; ++ks)
                mma_f16_ss(tmem, dql + ks*2, dkh + ks*2, IDESC_S, true);
            TCGEN05_COMMIT(sb + 8);
        }
        MBARRIER_WAIT_PARITY(sb + 8, par0); par0 ^= 1;
        TCGEN05_FENCE_AFTER();

        float s[96];
#pragma unroll
        for (int cb = 0; cb < 3; ++cb) {
            uint32_t rr[32];
            TCGEN05_LD_32X32B_X32(rr, tmem + cb*32);
            TCGEN05_WAIT_LD();
#pragma unroll
            for (int i = 0; i < 32; ++i) s[cb*32 + i] = __uint_as_float(rr[i]);
        }
        TCGEN05_FENCE_BEFORE();
        int fg = g_fg[b*NQ + qbase + tid];
        float mx = -FLT_MAX;
#pragma unroll
        for (int j = 0; j < CTX; ++j) {
            float a = s[j] * 0.125f;
            bool valid = (j < 77) || ((j < 81) ? (fg != 0) : (fg == 0));
            a = valid ? a : -FLT_MAX;
            s[j] = a;
            mx = fmaxf(mx, a);
        }
        float sum = 0.f;
#pragma unroll
        for (int j = 0; j < CTX; ++j) {
            float e = (s[j] > -3.0e38f) ? __expf(s[j] - mx) : 0.f;
            s[j] = e;
            sum += e;
        }
        float inv = 1.f / sum;
#pragma unroll
        for (int j = CTX; j < 96; ++j) s[j] = 0.f;

        {
            int r = tid;
#pragma unroll
            for (int g = 0; g < 16; ++g) {
                int c0 = g*8;
                uint32_t hv[4], lv[4];
#pragma unroll
                for (int pe = 0; pe < 4; ++pe) {
                    int c = c0 + 2*pe;
                    float f0 = (c < 96) ? s[c] : 0.f;
                    float f1 = (c+1 < 96) ? s[c+1] : 0.f;
                    ushort_t h0, l0, h1, l1;
                    bf16split(f0, h0, l0);
                    bf16split(f1, h1, l1);
                    hv[pe] = ((uint32_t)h1 << 16) | h0;
                    lv[pe] = ((uint32_t)l1 << 16) | l0;
                }
                uint32_t addr = (uint32_t)(((r >> 3) + (c0 >> 6)*16)*1024 + (r & 7)*128 + (c0 & 63)*2);
                uint32_t so = SMEM_SWIZZLE_128B(addr);
                *(uint4*)(abp + A_PHI + so) = make_uint4(hv[0], hv[1], hv[2], hv[3]);
                *(uint4*)(abp + A_PLO + so) = make_uint4(lv[0], lv[1], lv[2], lv[3]);
            }
        }
        __syncthreads();
        if (wid == 0 && elect_one_pred()) {
            FENCE_ASYNC();
            uint64_t dph = MAKE_SMEM_DESC(ab + A_PHI);
            uint64_t dpl = MAKE_SMEM_DESC(ab + A_PLO);
            uint64_t dvh = MAKE_SMEM_DESC(ab + A_VHI);
            uint64_t dvl = MAKE_SMEM_DESC(ab + A_VLO);
#pragma unroll
            for (int ks = 0; ks < 8; ++ks) {
                uint64_t aoff = (ks < 4) ? ks*2 : 1024 + (ks-4)*2;
                uint64_t boff = (ks < 4) ? ks*2 : 512 + (ks-4)*2;
                mma_f16_ss(tmem + 96, dph + aoff, dvh + boff, IDESC_O, ks > 0);
            }
#pragma unroll
            for (int ks = 0; ks < 8; ++ks) {
                uint64_t aoff = (ks < 4) ? ks*2 : 1024 + (ks-4)*2;
                uint64_t boff = (ks < 4) ? ks*2 : 512 + (ks-4)*2;
                mma_f16_ss(tmem + 96, dph + aoff, dvl + boff, IDESC_O, true);
            }
#pragma unroll
            for (int ks = 0; ks < 8; ++ks) {
                uint64_t aoff = (ks < 4) ? ks*2 : 1024 + (ks-4)*2;
                uint64_t boff = (ks < 4) ? ks*2 : 512 + (ks-4)*2;
                mma_f16_ss(tmem + 96, dpl + aoff, dvh + boff, IDESC_O, true);
            }
            TCGEN05_COMMIT(sb + 16);
        }
        MBARRIER_WAIT_PARITY(sb + 16, par1); par1 ^= 1;
        TCGEN05_FENCE_AFTER();

        size_t obase = (size_t)(b*NQ + qbase + tid)*INNER + h*DHEAD;
#pragma unroll
        for (int cb = 0; cb < 2; ++cb) {
            uint32_t rr[32];
            TCGEN05_LD_32X32B_X32(rr, tmem + 96 + cb*32);
            TCGEN05_WAIT_LD();
#pragma unroll
            for (int g = 0; g < 4; ++g) {
                uint32_t hv[4], lv[4];
#pragma unroll
                for (int pe = 0; pe < 4; ++pe) {
                    float f0 = __uint_as_float(rr[g*8 + 2*pe])     * inv;
                    float f1 = __uint_as_float(rr[g*8 + 2*pe + 1]) * inv;
                    ushort_t h0, l0, h1, l1;
                    bf16split(f0, h0, l0);
                    bf16split(f1, h1, l1);
                    hv[pe] = ((uint32_t)h1 << 16) | h0;
                    lv[pe] = ((uint32_t)l1 << 16) | l0;
                }
                *(uint4*)(g_ao_hi + obase + cb*32 + g*8) = make_uint4(hv[0], hv[1], hv[2], hv[3]);
                *(uint4*)(g_ao_lo + obase + cb*32 + g*8) = make_uint4(lv[0], lv[1], lv[2], lv[3]);
            }
        }
        TCGEN05_FENCE_BEFORE();
        __syncthreads();
    }
    if (wid == 0) TCGEN05_DEALLOC(tmem, 256);
#endif
}

// ---------------- launch ------------------------------------------------------
extern "C" void kernel_launch(void* const* d_in, const int* in_sizes, int n_in,
                              void* d_out, int out_size)
{
    (void)in_sizes; (void)n_in; (void)out_size;
    const float* x    = (const float*)d_in[0];
    const float* ctxp = (const float*)d_in[1];
    const float* Wq   = (const float*)d_in[2];
    const float* Wk   = (const float*)d_in[3];
    const float* Wv   = (const float*)d_in[4];
    const float* Wo   = (const float*)d_in[5];
    const float* bo   = (const float*)d_in[6];
    const int*   mask = (const int*)d_in[7];
    float* out = (float*)d_out;

    float *k, *v;
    __nv_bfloat16 *qhi, *qlo, *aohi, *aolo;
    __nv_bfloat16 *wqth, *wqtl, *wkth, *wktl, *wvth, *wvtl, *woth, *wotl;
    cudaGetSymbolAddress((void**)&k,    g_k);
    cudaGetSymbolAddress((void**)&v,    g_v);
    cudaGetSymbolAddress((void**)&qhi,  g_qhi);
    cudaGetSymbolAddress((void**)&qlo,  g_qlo);
    cudaGetSymbolAddress((void**)&aohi, g_ao_hi);
    cudaGetSymbolAddress((void**)&aolo, g_ao_lo);
    cudaGetSymbolAddress((void**)&wqth, g_wqt_hi);
    cudaGetSymbolAddress((void**)&wqtl, g_wqt_lo);
    cudaGetSymbolAddress((void**)&wkth, g_wkt_hi);
    cudaGetSymbolAddress((void**)&wktl, g_wkt_lo);
    cudaGetSymbolAddress((void**)&wvth, g_wvt_hi);
    cudaGetSymbolAddress((void**)&wvtl, g_wvt_lo);
    cudaGetSymbolAddress((void**)&woth, g_wot_hi);
    cudaGetSymbolAddress((void**)&wotl, g_wot_lo);

    cudaFuncSetAttribute(gemm_bf16x3, cudaFuncAttributeMaxDynamicSharedMemorySize, G_SMEM);
    cudaFuncSetAttribute(attn_tc, cudaFuncAttributeMaxDynamicSharedMemorySize, ATTN_SMEM);

    dim3 blk(32, 8);

    // Profiler captures launch #4 -> keep the Q GEMM there.
    mask_kernel<<<(BB*NQ + 255)/256, 256>>>(mask);                              // 1
    wtrans_kernel<<<dim3(QD/32, INNER/32), blk>>>(Wq, wqth, wqtl, QD, INNER);   // 2
    wtrans_kernel<<<dim3(INNER/32, QD/32), blk>>>(Wo, woth, wotl, INNER, QD);   // 3

    // 4: Q projection (fp32 A, fused split) -> bf16 hi/lo   [PROFILED]
    gemm_bf16x3<<<dim3(INNER/G_BN, (BB*NQ)/G_BM), 256, G_SMEM>>>(
        x, nullptr, nullptr, wqth, wqtl, nullptr, nullptr, qhi, qlo,
        BB*NQ, INNER, QD);

    // 5,6: remaining weight transposes
    wtrans_kernel<<<dim3(CD/32, INNER/32), blk>>>(Wk, wkth, wktl, CD, INNER);   // 5
    wtrans_kernel<<<dim3(CD/32, INNER/32), blk>>>(Wv, wvth, wvtl, CD, INNER);   // 6

    // 7,8: K, V projections (fp32 ctx A, fused split + pad)
    gemm_bf16x3<<<dim3(INNER/G_BN, MKV/G_BM), 256, G_SMEM>>>(
        ctxp, nullptr, nullptr, wkth, wktl, nullptr, k, nullptr, nullptr,
        BB*CTX, INNER, CD);
    gemm_bf16x3<<<dim3(INNER/G_BN, MKV/G_BM), 256, G_SMEM>>>(
        ctxp, nullptr, nullptr, wvth, wvtl, nullptr, v, nullptr, nullptr,
        BB*CTX, INNER, CD);

    // 9: bake K / V^T swizzled images
    kv_image_kernel<<<NBH, 128>>>();

    // 10: tensor-core masked attention
    attn_tc<<<dim3(NQ/(ATT_QT*128), NHEADS, BB), 128, ATTN_SMEM>>>();

    // 11: output projection + bias
    gemm_bf16x3<<<dim3(QD/G_BN, (BB*NQ)/G_BM), 256, G_SMEM>>>(
        nullptr, aohi, aolo, woth, wotl, bo, out, nullptr, nullptr,
        BB*NQ, QD, INNER);
}

// round 9
// speedup vs baseline: 1.3399x; 1.3399x over previous
#include <cuda_runtime.h>
#include <cuda.h>
#include <cuda_bf16.h>
#include <math.h>
#include <float.h>
#include <stdint.h>

#define BB 8
#define NQ 4096
#define QD 1280
#define CD 1024
#define CTX 85
#define NHEADS 20
#define DHEAD 64
#define INNER (NHEADS*DHEAD)   // 1280
#define MKV 768
#define NBH (BB*NHEADS)        // 160

typedef unsigned short ushort_t;

// ---------------- scratch (static device globals; no allocation) -------------
__device__ float g_k [(size_t)MKV*INNER];
__device__ float g_v [(size_t)MKV*INNER];
__device__ __nv_bfloat16 g_qhi[(size_t)BB*NQ*INNER];
__device__ __nv_bfloat16 g_qlo[(size_t)BB*NQ*INNER];
__device__ __nv_bfloat16 g_ao_hi[(size_t)BB*NQ*INNER];
__device__ __nv_bfloat16 g_ao_lo[(size_t)BB*NQ*INNER];
__device__ __nv_bfloat16 g_wqt_hi[(size_t)INNER*QD];
__device__ __nv_bfloat16 g_wqt_lo[(size_t)INNER*QD];
__device__ __nv_bfloat16 g_wkt_hi[(size_t)INNER*CD];
__device__ __nv_bfloat16 g_wkt_lo[(size_t)INNER*CD];
__device__ __nv_bfloat16 g_wvt_hi[(size_t)INNER*CD];
__device__ __nv_bfloat16 g_wvt_lo[(size_t)INNER*CD];
__device__ __nv_bfloat16 g_wot_hi[(size_t)QD*INNER];
__device__ __nv_bfloat16 g_wot_lo[(size_t)QD*INNER];
__device__ __nv_bfloat16 g_kimg_hi[(size_t)NBH*96*64];
__device__ __nv_bfloat16 g_kimg_lo[(size_t)NBH*96*64];
__device__ __nv_bfloat16 g_vimg_hi[(size_t)NBH*64*128];
__device__ __nv_bfloat16 g_vimg_lo[(size_t)NBH*64*128];
__device__ unsigned char g_fg[BB*NQ];

// ============================ PTX helpers ====================================
__device__ __forceinline__ uint32_t smem_to_u32(const void* p) {
    uint32_t a;
    asm("{ .reg .u64 t; cvta.to.shared.u64 t, %1; cvt.u32.u64 %0, t; }"
        : "=r"(a) : "l"(p));
    return a;
}

#if defined(__CUDA_ARCH_FEAT_SM103_ALL)
#define HAS_TCGEN05 1
#else
#define HAS_TCGEN05 0
#endif

#if HAS_TCGEN05
__device__ __forceinline__ uint32_t elect_one_pred() {
    uint32_t pred;
    asm volatile(
        "{\n\t.reg .pred p;\n\t"
        "elect.sync _|p, 0xFFFFFFFF;\n\t"
        "selp.b32 %0, 1, 0, p;\n\t}"
        : "=r"(pred));
    return pred;
}
#define TCGEN05_ALLOC(sa, n) \
    asm volatile("tcgen05.alloc.cta_group::1.sync.aligned.shared::cta.b32 [%0], %1;" \
        :: "r"((uint32_t)(sa)), "r"((uint32_t)(n)) : "memory")
#define TCGEN05_DEALLOC(t, n) \
    asm volatile("tcgen05.dealloc.cta_group::1.sync.aligned.b32 %0, %1;" :: "r"(t), "r"((uint32_t)(n)))
#define TCGEN05_RELINQ() \
    asm volatile("tcgen05.relinquish_alloc_permit.cta_group::1.sync.aligned;")
#define TCGEN05_COMMIT(mb) \
    asm volatile("tcgen05.commit.cta_group::1.mbarrier::arrive::one.shared::cluster.b64 [%0];" \
        :: "r"((uint32_t)(mb)) : "memory")
#define TCGEN05_FENCE_AFTER() asm volatile("tcgen05.fence::after_thread_sync;" ::: "memory")
#define TCGEN05_FENCE_BEFORE() asm volatile("tcgen05.fence::before_thread_sync;" ::: "memory")
#define TCGEN05_WAIT_LD() asm volatile("tcgen05.wait::ld.sync.aligned;" ::: "memory")
#define FENCE_ASYNC() asm volatile("fence.proxy.async.shared::cta;" ::: "memory")
#define MBARRIER_INIT(mb, c) \
    asm volatile("mbarrier.init.shared.b64 [%0], %1;" :: "r"((uint32_t)(mb)), "r"((uint32_t)(c)) : "memory")
#define MBARRIER_EXPECT_TX(mb, tx) \
    asm volatile("mbarrier.arrive.expect_tx.shared.b64 _, [%0], %1;" \
        :: "r"((uint32_t)(mb)), "r"((uint32_t)(tx)) : "memory")
#define MBARRIER_WAIT_PARITY(mb, ph) do { \
    uint32_t _m = (uint32_t)(mb), _p = (uint32_t)(ph), _d; \
    asm volatile("{\n\t.reg .pred p;\n\t" \
        "mbarrier.try_wait.parity.acquire.cta.shared::cta.b64 p, [%1], %2;\n\t" \
        "selp.b32 %0, 1, 0, p;\n\t}" : "=r"(_d) : "r"(_m), "r"(_p) : "memory"); \
    if (!_d) { \
        asm volatile("{\n\t.reg .pred P1;\n\t" \
            "WL_%=:\n\t" \
            "mbarrier.try_wait.parity.acquire.cta.shared::cta.b64 P1, [%0], %1, 0x989680;\n\t" \
            "@P1 bra.uni WD_%=;\n\t" \
            "bra.uni WL_%=;\n\t" \
            "WD_%=:\n\t}" :: "r"(_m), "r"(_p) : "memory"); \
    } \
} while (0)
#define TMA_LOAD_2D(sa, mp, cx, cy, mb) \
    asm volatile("cp.async.bulk.tensor.2d.shared::cta.global.tile.mbarrier::complete_tx::bytes " \
        "[%0], [%1, {%2, %3}], [%4];" \
        :: "r"((uint32_t)(sa)), "l"(mp), "r"((int32_t)(cx)), "r"((int32_t)(cy)), \
           "r"((uint32_t)(mb)) : "memory")
#define TCGEN05_LD_32X32B_X32(r, ta) \
    asm volatile("tcgen05.ld.sync.aligned.32x32b.x32.b32 " \
        "{%0, %1, %2, %3, %4, %5, %6, %7, %8, %9, %10, %11, %12, %13, %14, %15, " \
        " %16, %17, %18, %19, %20, %21, %22, %23, %24, %25, %26, %27, %28, %29, %30, %31}, [%32];" \
        : "=r"((r)[0]),  "=r"((r)[1]),  "=r"((r)[2]),  "=r"((r)[3]), \
          "=r"((r)[4]),  "=r"((r)[5]),  "=r"((r)[6]),  "=r"((r)[7]), \
          "=r"((r)[8]),  "=r"((r)[9]),  "=r"((r)[10]), "=r"((r)[11]), \
          "=r"((r)[12]), "=r"((r)[13]), "=r"((r)[14]), "=r"((r)[15]), \
          "=r"((r)[16]), "=r"((r)[17]), "=r"((r)[18]), "=r"((r)[19]), \
          "=r"((r)[20]), "=r"((r)[21]), "=r"((r)[22]), "=r"((r)[23]), \
          "=r"((r)[24]), "=r"((r)[25]), "=r"((r)[26]), "=r"((r)[27]), \
          "=r"((r)[28]), "=r"((r)[29]), "=r"((r)[30]), "=r"((r)[31]) \
        : "r"(ta))

__device__ __forceinline__ void mma_f16_ss(uint32_t d_tmem, uint64_t a_desc,
                                           uint64_t b_desc, uint32_t idesc, bool acc)
{
    uint32_t en = acc ? 1u : 0u;
    asm volatile(
        "{\n\t.reg .pred p;\n\t"
        "setp.ne.u32 p, %5, 0;\n\t"
        "tcgen05.mma.cta_group::1.kind::f16 [%0], %1, %2, %3, {%4, %4, %4, %4}, p;\n\t}"
        :: "r"(d_tmem), "l"(a_desc), "l"(b_desc), "r"(idesc), "r"(0u), "r"(en)
        : "memory");
}
#endif // HAS_TCGEN05

static constexpr uint64_t SMEM_DESC_BASE_SW128 =
    (uint64_t(2)  << 61) | (uint64_t(1) << 46) | (uint64_t(64) << 32) | (uint64_t(1) << 16);
#define MAKE_SMEM_DESC(ba) (SMEM_DESC_BASE_SW128 | ((uint64_t)((ba) >> 4) & 0x3FFF))
#define SMEM_SWIZZLE_128B(bo) ((bo) ^ (((bo) >> 3) & 0x70))

__device__ __forceinline__ void bf16split(float f, ushort_t& h, ushort_t& l)
{
    __nv_bfloat16 hh = __float2bfloat16(f);
    __nv_bfloat16 ll = __float2bfloat16(f - __bfloat162float(hh));
    h = __bfloat16_as_ushort(hh);
    l = __bfloat16_as_ushort(ll);
}

// ---------------- mask: exact integer bicubic-threshold ----------------------
__global__ void mask_kernel(const int* __restrict__ mask)
{
    int idx = blockIdx.x * blockDim.x + threadIdx.x;
    if (idx >= BB*NQ) return;
    int b = idx / NQ, n = idx % NQ;
    int o = n >> 6, p = n & 63;
    const int iw[4] = {-3, 19, 19, -3};
    const int* mb = mask + (size_t)b * 256 * 256;
    int acc = 0;
#pragma unroll
    for (int s = 0; s < 4; s++) {
        const int* row = mb + (4*o + s) * 256 + 4*p;
        int rw = iw[s];
#pragma unroll
        for (int t = 0; t < 4; t++) acc += rw * iw[t] * row[t];
    }
    g_fg[idx] = (acc != 0) ? 1 : 0;
}

// ---------------- weight transpose + bf16 split -------------------------------
__global__ void wtrans_kernel(const float* __restrict__ W,
                              __nv_bfloat16* __restrict__ Thi,
                              __nv_bfloat16* __restrict__ Tlo, int K, int N)
{
    __shared__ float t[32][33];
    int k0 = blockIdx.x * 32, n0 = blockIdx.y * 32;
    int tx = threadIdx.x, ty = threadIdx.y;
    for (int r = ty; r < 32; r += 8)
        t[r][tx] = W[(size_t)(k0 + r)*N + n0 + tx];
    __syncthreads();
    for (int r = ty; r < 32; r += 8) {
        float v = t[tx][r];
        ushort_t h, l; bf16split(v, h, l);
        Thi[(size_t)(n0 + r)*K + k0 + tx] = __ushort_as_bfloat16(h);
        Tlo[(size_t)(n0 + r)*K + k0 + tx] = __ushort_as_bfloat16(l);
    }
}

// ================= bf16x3 tcgen05 GEMM: C = A@B^T (+bias) ====================
// BK=64, BM=128, BN=256 (R7 config), double-buffered 96KB stages.
// B tiles always via TMA. A: fp32 LDG + fused split (Af != null) or TMA (pre-split).
#define G_BM 128
#define G_BN 256
#define G_BK 64
#define G_BUFSZ 98304            // Ahi 16K | Alo 16K | Bhi 32K | Blo 32K
#define G_SMEM  (2048 + 2*G_BUFSZ)
#define G_IDESC 0x08400490u      // F32 acc, BF16xBF16, N=256, M=128

__global__ void __launch_bounds__(256)
gemm_bf16x3(const float* __restrict__ Af,
            const __grid_constant__ CUtensorMap tmAhi,
            const __grid_constant__ CUtensorMap tmAlo,
            const __grid_constant__ CUtensorMap tmBhi,
            const __grid_constant__ CUtensorMap tmBlo,
            const float* __restrict__ bias, float* __restrict__ C,
            __nv_bfloat16* __restrict__ Chi, __nv_bfloat16* __restrict__ Clo,
            int Mvalid, int N, int K)
{
#if HAS_TCGEN05
    extern __shared__ char smem[];
    const uint32_t sb = smem_to_u32(smem);
    const uint32_t ab = (sb + 1024 + 1023) & ~1023u;
    char* abp = smem + (ab - sb);
    const int tid = threadIdx.x;
    const int wid = tid >> 5, lane = tid & 31;
    const int brow = blockIdx.y * G_BM;
    const int bcol = blockIdx.x * G_BN;
    const bool a_fp32 = (Af != nullptr);

    if (wid == 0) TCGEN05_ALLOC(sb, 256);
    __syncthreads();
    uint32_t tmem;
    asm volatile("ld.shared.b32 %0, [%1];" : "=r"(tmem) : "r"(sb));
    if (wid == 0) TCGEN05_RELINQ();
    if (tid == 0) {
        MBARRIER_INIT(sb + 8,  1);   // mma_done buf0
        MBARRIER_INIT(sb + 16, 1);   // mma_done buf1
        MBARRIER_INIT(sb + 24, 1);   // tma_full buf0
        MBARRIER_INIT(sb + 32, 1);   // tma_full buf1
    }
    __syncthreads();

    const int KCH = K / G_BK;
    int par_m0 = 0, par_m1 = 0, par_t0 = 0, par_t1 = 0;
    const uint32_t tx_bytes = a_fp32 ? 65536u : 98304u;

    // A register prefetch (fp32 path only)
    const int a_row = tid >> 3;      // 0..31, rows a_row + i*32
    const int a_v   = tid & 7;       // vec16 within 128B row
    uint4 pah[4], pal[4];

    auto load_a = [&](int c) {
        const int k0 = c * G_BK;
#pragma unroll
        for (int i = 0; i < 4; ++i) {
            int gr = brow + a_row + i*32;
            float fa[8];
            if (gr < Mvalid) {
                const float4* src = (const float4*)(Af + (size_t)gr*K + k0 + a_v*8);
                float4 a0 = src[0], a1 = src[1];
                fa[0]=a0.x; fa[1]=a0.y; fa[2]=a0.z; fa[3]=a0.w;
                fa[4]=a1.x; fa[5]=a1.y; fa[6]=a1.z; fa[7]=a1.w;
            } else {
#pragma unroll
                for (int e = 0; e < 8; ++e) fa[e] = 0.f;
            }
            uint32_t hw[4], lw[4];
#pragma unroll
            for (int e = 0; e < 4; ++e) {
                ushort_t h0, l0, h1, l1;
                bf16split(fa[2*e],   h0, l0);
                bf16split(fa[2*e+1], h1, l1);
                hw[e] = ((uint32_t)h1 << 16) | h0;
                lw[e] = ((uint32_t)l1 << 16) | l0;
            }
            pah[i] = make_uint4(hw[0], hw[1], hw[2], hw[3]);
            pal[i] = make_uint4(lw[0], lw[1], lw[2], lw[3]);
        }
    };

    if (a_fp32) load_a(0);

    for (int c = 0; c < KCH; ++c) {
        int p = c & 1;
        if (c >= 2) {
            if (p == 0) { MBARRIER_WAIT_PARITY(sb + 8,  par_m0); par_m0 ^= 1; }
            else        { MBARRIER_WAIT_PARITY(sb + 16, par_m1); par_m1 ^= 1; }
        }
        char* base = abp + p * G_BUFSZ;
        const uint32_t bu = ab + p * G_BUFSZ;
        const int k0 = c * G_BK;

        // TMA loads into buffer p (single thread)
        if (wid == 0 && elect_one_pred()) {
            uint32_t mb = sb + 24 + p*8;
            MBARRIER_EXPECT_TX(mb, tx_bytes);
            if (!a_fp32) {
                TMA_LOAD_2D(bu,         &tmAhi, k0, brow, mb);
                TMA_LOAD_2D(bu + 16384, &tmAlo, k0, brow, mb);
            }
            TMA_LOAD_2D(bu + 32768, &tmBhi, k0, bcol, mb);
            TMA_LOAD_2D(bu + 65536, &tmBlo, k0, bcol, mb);
        }

        // A via LDG/convert/STS (fp32 path)
        if (a_fp32) {
#pragma unroll
            for (int i = 0; i < 4; ++i) {
                uint32_t so = SMEM_SWIZZLE_128B((uint32_t)((a_row + i*32)*128 + a_v*16));
                *(uint4*)(base + so) = pah[i];
                *(uint4*)(base + 16384 + so) = pal[i];
            }
            __syncthreads();
        }

        if (wid == 0 && elect_one_pred()) {
            if (a_fp32) FENCE_ASYNC();
            if (p == 0) { MBARRIER_WAIT_PARITY(sb + 24, par_t0); }
            else        { MBARRIER_WAIT_PARITY(sb + 32, par_t1); }
            uint64_t dah = MAKE_SMEM_DESC(bu);
            uint64_t dal = MAKE_SMEM_DESC(bu + 16384);
            uint64_t dbh = MAKE_SMEM_DESC(bu + 32768);
            uint64_t dbl = MAKE_SMEM_DESC(bu + 65536);
#pragma unroll
            for (int ks = 0; ks < 4; ++ks)
                mma_f16_ss(tmem, dah + ks*2, dbh + ks*2, G_IDESC, !(c == 0 && ks == 0));
#pragma unroll
            for (int ks = 0; ks < 4; ++ks)
                mma_f16_ss(tmem, dah + ks*2, dbl + ks*2, G_IDESC, true);
#pragma unroll
            for (int ks = 0; ks < 4; ++ks)
                mma_f16_ss(tmem, dal + ks*2, dbh + ks*2, G_IDESC, true);
            TCGEN05_COMMIT(sb + 8 + p*8);
        }
        if (p == 0) par_t0 ^= 1; else par_t1 ^= 1;

        if (a_fp32 && c + 1 < KCH) load_a(c + 1);
    }
    MBARRIER_WAIT_PARITY(sb + 8,  par_m0);
    MBARRIER_WAIT_PARITY(sb + 16, par_m1);
    TCGEN05_FENCE_AFTER();

    if (wid < 4) {
        int row = brow + wid*32 + lane;
#pragma unroll
        for (int cb = 0; cb < G_BN/32; ++cb) {
            uint32_t r[32];
            TCGEN05_LD_32X32B_X32(r, tmem + cb*32);
            TCGEN05_WAIT_LD();
            int col0 = bcol + cb*32;
            if (Chi) {
                uint32_t hp[16], lp[16];
#pragma unroll
                for (int m = 0; m < 16; ++m) {
                    ushort_t h0, l0, h1, l1;
                    bf16split(__uint_as_float(r[2*m]),   h0, l0);
                    bf16split(__uint_as_float(r[2*m+1]), h1, l1);
                    hp[m] = ((uint32_t)h1 << 16) | h0;
                    lp[m] = ((uint32_t)l1 << 16) | l0;
                }
                uint32_t* dh = (uint32_t*)(Chi + (size_t)row*N + col0);
                uint32_t* dl = (uint32_t*)(Clo + (size_t)row*N + col0);
#pragma unroll
                for (int m = 0; m < 16; ++m) { dh[m] = hp[m]; dl[m] = lp[m]; }
            } else {
                float* cp = C + (size_t)row*N + col0;
                if (bias) {
#pragma unroll
                    for (int i = 0; i < 32; ++i) cp[i] = __uint_as_float(r[i]) + bias[col0 + i];
                } else {
#pragma unroll
                    for (int i = 0; i < 32; ++i) cp[i] = __uint_as_float(r[i]);
                }
            }
        }
        TCGEN05_FENCE_BEFORE();
    }
    __syncthreads();
    if (wid == 0) TCGEN05_DEALLOC(tmem, 256);
#endif
}

// ---------------- K / V^T image bake (swizzled SMEM images) -------------------
__global__ void __launch_bounds__(128) kv_image_kernel()
{
    int bh = blockIdx.x;
    int b = bh / NHEADS, h = bh % NHEADS;
    int tid = threadIdx.x;
    char* kh = (char*)(g_kimg_hi + (size_t)bh*96*64);
    char* kl = (char*)(g_kimg_lo + (size_t)bh*96*64);
    char* vh = (char*)(g_vimg_hi + (size_t)bh*64*128);
    char* vl = (char*)(g_vimg_lo + (size_t)bh*64*128);

    for (int u = tid; u < 96*64; u += 128) {
        int j = u >> 6, d = u & 63;
        float f = (j < CTX) ? g_k[(size_t)(b*CTX + j)*INNER + h*DHEAD + d] : 0.f;
        ushort_t hh, ll; bf16split(f, hh, ll);
        uint32_t so = SMEM_SWIZZLE_128B((uint32_t)(j*128 + d*2));
        *(ushort_t*)(kh + so) = hh;
        *(ushort_t*)(kl + so) = ll;
    }
    for (int u = tid; u < 64*128; u += 128) {
        int d = u >> 7, j = u & 127;
        float f = (j < CTX) ? g_v[(size_t)(b*CTX + j)*INNER + h*DHEAD + d] : 0.f;
        ushort_t hh, ll; bf16split(f, hh, ll);
        uint32_t addr = (uint32_t)(((d >> 3) + (j >> 6)*8)*1024 + (d & 7)*128 + (j & 63)*2);
        uint32_t so = SMEM_SWIZZLE_128B(addr);
        *(ushort_t*)(vh + so) = hh;
        *(ushort_t*)(vl + so) = ll;
    }
}

// ---------------- tcgen05 fused masked attention (R7 version) -----------------
#define ATT_QT 4
#define A_QHI 0
#define A_QLO 16384
#define A_KHI 32768
#define A_KLO 45056
#define A_VHI 57344
#define A_VLO 73728
#define A_PHI 90112
#define A_PLO 122880
#define ATTN_SMEM (2048 + 155648)
#define IDESC_S 0x08180490u   // M=128, N=96
#define IDESC_O 0x08100490u   // M=128, N=64

__global__ void __launch_bounds__(128) attn_tc()
{
#if HAS_TCGEN05
    extern __shared__ char smem[];
    const uint32_t sb = smem_to_u32(smem);
    const uint32_t ab = (sb + 1024 + 1023) & ~1023u;
    char* abp = smem + (ab - sb);
    int tid = threadIdx.x, wid = tid >> 5;
    int b = blockIdx.z, h = blockIdx.y, qg = blockIdx.x;
    int bh = b*NHEADS + h;

    if (wid == 0) TCGEN05_ALLOC(sb, 256);
    __syncthreads();
    uint32_t tmem;
    asm volatile("ld.shared.b32 %0, [%1];" : "=r"(tmem) : "r"(sb));
    if (wid == 0) TCGEN05_RELINQ();
    if (tid == 0) { MBARRIER_INIT(sb + 8, 1); MBARRIER_INIT(sb + 16, 1); }
    __syncthreads();

    {
        const uint4* skh = (const uint4*)(g_kimg_hi + (size_t)bh*96*64);
        const uint4* skl = (const uint4*)(g_kimg_lo + (size_t)bh*96*64);
        for (int u = tid; u < 768; u += 128) {
            ((uint4*)(abp + A_KHI))[u] = skh[u];
            ((uint4*)(abp + A_KLO))[u] = skl[u];
        }
        const uint4* svh = (const uint4*)(g_vimg_hi + (size_t)bh*64*128);
        const uint4* svl = (const uint4*)(g_vimg_lo + (size_t)bh*64*128);
        for (int u = tid; u < 1024; u += 128) {
            ((uint4*)(abp + A_VHI))[u] = svh[u];
            ((uint4*)(abp + A_VLO))[u] = svl[u];
        }
    }

    int par0 = 0, par1 = 0;
    for (int qt = 0; qt < ATT_QT; ++qt) {
        int qbase = (qg*ATT_QT + qt)*128;
        size_t qrow = (size_t)(b*NQ + qbase + tid)*INNER + h*DHEAD;
        {
            const uint4* qh = (const uint4*)(g_qhi + qrow);
            const uint4* ql = (const uint4*)(g_qlo + qrow);
#pragma unroll
            for (int v = 0; v < 8; ++v) {
                uint32_t so = SMEM_SWIZZLE_128B((uint32_t)(tid*128 + v*16));
                *(uint4*)(abp + A_QHI + so) = qh[v];
                *(uint4*)(abp + A_QLO + so) = ql[v];
            }
        }
        __syncthreads();
        if (wid == 0 && elect_one_pred()) {
            FENCE_ASYNC();
            uint64_t dqh = MAKE_SMEM_DESC(ab + A_QHI);
            uint64_t dql = MAKE_SMEM_DESC(ab + A_QLO);
            uint64_t dkh = MAKE_SMEM_DESC(ab + A_KHI);
            uint64_t dkl = MAKE_SMEM_DESC(ab + A_KLO);
#pragma unroll
            for (int ks = 0; ks < 4; ++ks)
                mma_f16_ss(tmem, dqh + ks*2, dkh + ks*2, IDESC_S, ks > 0);
#pragma unroll
            for (int ks = 0; ks < 4; ++ks)
                mma_f16_ss(tmem, dqh + ks*2, dkl + ks*2, IDESC_S, true);
#pragma unroll
            for (int ks = 0; ks < 4; ++ks)
                mma_f16_ss(tmem, dql + ks*2, dkh + ks*2, IDESC_S, true);
            TCGEN05_COMMIT(sb + 8);
        }
        MBARRIER_WAIT_PARITY(sb + 8, par0); par0 ^= 1;
        TCGEN05_FENCE_AFTER();

        float s[96];
#pragma unroll
        for (int cb = 0; cb < 3; ++cb) {
            uint32_t rr[32];
            TCGEN05_LD_32X32B_X32(rr, tmem + cb*32);
            TCGEN05_WAIT_LD();
#pragma unroll
            for (int i = 0; i < 32; ++i) s[cb*32 + i] = __uint_as_float(rr[i]);
        }
        TCGEN05_FENCE_BEFORE();
        int fg = g_fg[b*NQ + qbase + tid];
        float mx = -FLT_MAX;
#pragma unroll
        for (int j = 0; j < CTX; ++j) {
            float a = s[j] * 0.125f;
            bool valid = (j < 77) || ((j < 81) ? (fg != 0) : (fg == 0));
            a = valid ? a : -FLT_MAX;
            s[j] = a;
            mx = fmaxf(mx, a);
        }
        float sum = 0.f;
#pragma unroll
        for (int j = 0; j < CTX; ++j) {
            float e = (s[j] > -3.0e38f) ? __expf(s[j] - mx) : 0.f;
            s[j] = e;
            sum += e;
        }
        float inv = 1.f / sum;
#pragma unroll
        for (int j = CTX; j < 96; ++j) s[j] = 0.f;

        {
            int r = tid;
#pragma unroll
            for (int g = 0; g < 16; ++g) {
                int c0 = g*8;
                uint32_t hv[4], lv[4];
#pragma unroll
                for (int pe = 0; pe < 4; ++pe) {
                    int c = c0 + 2*pe;
                    float f0 = (c < 96) ? s[c] : 0.f;
                    float f1 = (c+1 < 96) ? s[c+1] : 0.f;
                    ushort_t h0, l0, h1, l1;
                    bf16split(f0, h0, l0);
                    bf16split(f1, h1, l1);
                    hv[pe] = ((uint32_t)h1 << 16) | h0;
                    lv[pe] = ((uint32_t)l1 << 16) | l0;
                }
                uint32_t addr = (uint32_t)(((r >> 3) + (c0 >> 6)*16)*1024 + (r & 7)*128 + (c0 & 63)*2);
                uint32_t so = SMEM_SWIZZLE_128B(addr);
                *(uint4*)(abp + A_PHI + so) = make_uint4(hv[0], hv[1], hv[2], hv[3]);
                *(uint4*)(abp + A_PLO + so) = make_uint4(lv[0], lv[1], lv[2], lv[3]);
            }
        }
        __syncthreads();
        if (wid == 0 && elect_one_pred()) {
            FENCE_ASYNC();
            uint64_t dph = MAKE_SMEM_DESC(ab + A_PHI);
            uint64_t dpl = MAKE_SMEM_DESC(ab + A_PLO);
            uint64_t dvh = MAKE_SMEM_DESC(ab + A_VHI);
            uint64_t dvl = MAKE_SMEM_DESC(ab + A_VLO);
#pragma unroll
            for (int ks = 0; ks < 8; ++ks) {
                uint64_t aoff = (ks < 4) ? ks*2 : 1024 + (ks-4)*2;
                uint64_t boff = (ks < 4) ? ks*2 : 512 + (ks-4)*2;
                mma_f16_ss(tmem + 96, dph + aoff, dvh + boff, IDESC_O, ks > 0);
            }
#pragma unroll
            for (int ks = 0; ks < 8; ++ks) {
                uint64_t aoff = (ks < 4) ? ks*2 : 1024 + (ks-4)*2;
                uint64_t boff = (ks < 4) ? ks*2 : 512 + (ks-4)*2;
                mma_f16_ss(tmem + 96, dph + aoff, dvl + boff, IDESC_O, true);
            }
#pragma unroll
            for (int ks = 0; ks < 8; ++ks) {
                uint64_t aoff = (ks < 4) ? ks*2 : 1024 + (ks-4)*2;
                uint64_t boff = (ks < 4) ? ks*2 : 512 + (ks-4)*2;
                mma_f16_ss(tmem + 96, dpl + aoff, dvh + boff, IDESC_O, true);
            }
            TCGEN05_COMMIT(sb + 16);
        }
        MBARRIER_WAIT_PARITY(sb + 16, par1); par1 ^= 1;
        TCGEN05_FENCE_AFTER();

        size_t obase = (size_t)(b*NQ + qbase + tid)*INNER + h*DHEAD;
#pragma unroll
        for (int cb = 0; cb < 2; ++cb) {
            uint32_t rr[32];
            TCGEN05_LD_32X32B_X32(rr, tmem + 96 + cb*32);
            TCGEN05_WAIT_LD();
#pragma unroll
            for (int g = 0; g < 4; ++g) {
                uint32_t hv[4], lv[4];
#pragma unroll
                for (int pe = 0; pe < 4; ++pe) {
                    float f0 = __uint_as_float(rr[g*8 + 2*pe])     * inv;
                    float f1 = __uint_as_float(rr[g*8 + 2*pe + 1]) * inv;
                    ushort_t h0, l0, h1, l1;
                    bf16split(f0, h0, l0);
                    bf16split(f1, h1, l1);
                    hv[pe] = ((uint32_t)h1 << 16) | h0;
                    lv[pe] = ((uint32_t)l1 << 16) | l0;
                }
                *(uint4*)(g_ao_hi + obase + cb*32 + g*8) = make_uint4(hv[0], hv[1], hv[2], hv[3]);
                *(uint4*)(g_ao_lo + obase + cb*32 + g*8) = make_uint4(lv[0], lv[1], lv[2], lv[3]);
            }
        }
        TCGEN05_FENCE_BEFORE();
        __syncthreads();
    }
    if (wid == 0) TCGEN05_DEALLOC(tmem, 256);
#endif
}

// ---------------- host-side tensor map creation -------------------------------
typedef CUresult (*PFN_encodeTiled)(
    CUtensorMap*, CUtensorMapDataType, cuuint32_t, void*,
    const cuuint64_t*, const cuuint64_t*, const cuuint32_t*, const cuuint32_t*,
    CUtensorMapInterleave, CUtensorMapSwizzle, CUtensorMapL2promotion,
    CUtensorMapFloatOOBfill);

static PFN_encodeTiled get_encode_fn()
{
    static PFN_encodeTiled fn = nullptr;
    if (!fn) {
        void* p = nullptr;
        cudaDriverEntryPointQueryResult qr;
#if CUDART_VERSION >= 12050
        cudaGetDriverEntryPointByVersion("cuTensorMapEncodeTiled", &p, 12000,
                                         cudaEnableDefault, &qr);
#else
        cudaGetDriverEntryPoint("cuTensorMapEncodeTiled", &p, cudaEnableDefault, &qr);
#endif
        fn = (PFN_encodeTiled)p;
    }
    return fn;
}

static void make_map2d(CUtensorMap* m, void* ptr, uint64_t kdim, uint64_t ndim,
                       uint32_t box0, uint32_t box1)
{
    PFN_encodeTiled fn = get_encode_fn();
    cuuint64_t dims[2] = {kdim, ndim};
    cuuint64_t strides[1] = {kdim * 2};   // bf16 bytes
    cuuint32_t box[2] = {box0, box1};
    cuuint32_t es[2] = {1, 1};
    fn(m, CU_TENSOR_MAP_DATA_TYPE_BFLOAT16, 2, ptr, dims, strides, box, es,
       CU_TENSOR_MAP_INTERLEAVE_NONE, CU_TENSOR_MAP_SWIZZLE_128B,
       CU_TENSOR_MAP_L2_PROMOTION_L2_128B, CU_TENSOR_MAP_FLOAT_OOB_FILL_NONE);
}

// ---------------- launch ------------------------------------------------------
extern "C" void kernel_launch(void* const* d_in, const int* in_sizes, int n_in,
                              void* d_out, int out_size)
{
    (void)in_sizes; (void)n_in; (void)out_size;
    const float* x    = (const float*)d_in[0];
    const float* ctxp = (const float*)d_in[1];
    const float* Wq   = (const float*)d_in[2];
    const float* Wk   = (const float*)d_in[3];
    const float* Wv   = (const float*)d_in[4];
    const float* Wo   = (const float*)d_in[5];
    const float* bo   = (const float*)d_in[6];
    const int*   mask = (const int*)d_in[7];
    float* out = (float*)d_out;

    float *k, *v;
    __nv_bfloat16 *qhi, *qlo, *aohi, *aolo;
    __nv_bfloat16 *wqth, *wqtl, *wkth, *wktl, *wvth, *wvtl, *woth, *wotl;
    cudaGetSymbolAddress((void**)&k,    g_k);
    cudaGetSymbolAddress((void**)&v,    g_v);
    cudaGetSymbolAddress((void**)&qhi,  g_qhi);
    cudaGetSymbolAddress((void**)&qlo,  g_qlo);
    cudaGetSymbolAddress((void**)&aohi, g_ao_hi);
    cudaGetSymbolAddress((void**)&aolo, g_ao_lo);
    cudaGetSymbolAddress((void**)&wqth, g_wqt_hi);
    cudaGetSymbolAddress((void**)&wqtl, g_wqt_lo);
    cudaGetSymbolAddress((void**)&wkth, g_wkt_hi);
    cudaGetSymbolAddress((void**)&wktl, g_wkt_lo);
    cudaGetSymbolAddress((void**)&wvth, g_wvt_hi);
    cudaGetSymbolAddress((void**)&wvtl, g_wvt_lo);
    cudaGetSymbolAddress((void**)&woth, g_wot_hi);
    cudaGetSymbolAddress((void**)&wotl, g_wot_lo);

    // tensor maps (host-side, capture-safe)
    CUtensorMap tmQBh, tmQBl, tmKBh, tmKBl, tmVBh, tmVBl, tmOBh, tmOBl, tmOAh, tmOAl;
    make_map2d(&tmQBh, wqth, QD,    INNER, 64, 256);
    make_map2d(&tmQBl, wqtl, QD,    INNER, 64, 256);
    make_map2d(&tmKBh, wkth, CD,    INNER, 64, 256);
    make_map2d(&tmKBl, wktl, CD,    INNER, 64, 256);
    make_map2d(&tmVBh, wvth, CD,    INNER, 64, 256);
    make_map2d(&tmVBl, wvtl, CD,    INNER, 64, 256);
    make_map2d(&tmOBh, woth, INNER, QD,    64, 256);
    make_map2d(&tmOBl, wotl, INNER, QD,    64, 256);
    make_map2d(&tmOAh, aohi, INNER, (uint64_t)BB*NQ, 64, 128);
    make_map2d(&tmOAl, aolo, INNER, (uint64_t)BB*NQ, 64, 128);

    cudaFuncSetAttribute(gemm_bf16x3, cudaFuncAttributeMaxDynamicSharedMemorySize, G_SMEM);
    cudaFuncSetAttribute(attn_tc, cudaFuncAttributeMaxDynamicSharedMemorySize, ATTN_SMEM);

    dim3 blk(32, 8);

    // Profiler captures launch #4 -> keep the Q GEMM there.
    mask_kernel<<<(BB*NQ + 255)/256, 256>>>(mask);                              // 1
    wtrans_kernel<<<dim3(QD/32, INNER/32), blk>>>(Wq, wqth, wqtl, QD, INNER);   // 2
    wtrans_kernel<<<dim3(INNER/32, QD/32), blk>>>(Wo, woth, wotl, INNER, QD);   // 3

    // 4: Q projection (fp32 A fused split, TMA B) -> bf16 hi/lo   [PROFILED]
    gemm_bf16x3<<<dim3(INNER/G_BN, (BB*NQ)/G_BM), 256, G_SMEM>>>(
        x, tmQBh, tmQBl, tmQBh, tmQBl, nullptr, nullptr, qhi, qlo,
        BB*NQ, INNER, QD);

    // 5,6: remaining weight transposes
    wtrans_kernel<<<dim3(CD/32, INNER/32), blk>>>(Wk, wkth, wktl, CD, INNER);   // 5
    wtrans_kernel<<<dim3(CD/32, INNER/32), blk>>>(Wv, wvth, wvtl, CD, INNER);   // 6

    // 7,8: K, V projections (fp32 ctx A fused split + pad, TMA B)
    gemm_bf16x3<<<dim3(INNER/G_BN, MKV/G_BM), 256, G_SMEM>>>(
        ctxp, tmKBh, tmKBl, tmKBh, tmKBl, nullptr, k, nullptr, nullptr,
        BB*CTX, INNER, CD);
    gemm_bf16x3<<<dim3(INNER/G_BN, MKV/G_BM), 256, G_SMEM>>>(
        ctxp, tmVBh, tmVBl, tmVBh, tmVBl, nullptr, v, nullptr, nullptr,
        BB*CTX, INNER, CD);

    // 9: bake K / V^T swizzled images
    kv_image_kernel<<<NBH, 128>>>();

    // 10: tensor-core masked attention
    attn_tc<<<dim3(NQ/(ATT_QT*128), NHEADS, BB), 128, ATTN_SMEM>>>();

    // 11: output projection + bias (full TMA: A and B)
    gemm_bf16x3<<<dim3(QD/G_BN, (BB*NQ)/G_BM), 256, G_SMEM>>>(
        nullptr, tmOAh, tmOAl, tmOBh, tmOBl, bo, out, nullptr, nullptr,
        BB*NQ, QD, INNER);
}

// round 10
// speedup vs baseline: 1.4946x; 1.1154x over previous
#include <cuda_runtime.h>
#include <cuda_bf16.h>
#include <math.h>
#include <float.h>
#include <stdint.h>

#define BB 8
#define NQ 4096
#define QD 1280
#define CD 1024
#define CTX 85
#define NHEADS 20
#define DHEAD 64
#define INNER (NHEADS*DHEAD)   // 1280
#define MKV 768
#define NBH (BB*NHEADS)        // 160

typedef unsigned short ushort_t;

// ---------------- scratch (static device globals; no allocation) -------------
__device__ float g_k [(size_t)MKV*INNER];
__device__ float g_v [(size_t)MKV*INNER];
__device__ __nv_bfloat16 g_qhi[(size_t)BB*NQ*INNER];
__device__ __nv_bfloat16 g_qlo[(size_t)BB*NQ*INNER];
__device__ __nv_bfloat16 g_ao_hi[(size_t)BB*NQ*INNER];
__device__ __nv_bfloat16 g_ao_lo[(size_t)BB*NQ*INNER];
__device__ __nv_bfloat16 g_wqt_hi[(size_t)INNER*QD];
__device__ __nv_bfloat16 g_wqt_lo[(size_t)INNER*QD];
__device__ __nv_bfloat16 g_wkt_hi[(size_t)INNER*CD];
__device__ __nv_bfloat16 g_wkt_lo[(size_t)INNER*CD];
__device__ __nv_bfloat16 g_wvt_hi[(size_t)INNER*CD];
__device__ __nv_bfloat16 g_wvt_lo[(size_t)INNER*CD];
__device__ __nv_bfloat16 g_wot_hi[(size_t)QD*INNER];
__device__ __nv_bfloat16 g_wot_lo[(size_t)QD*INNER];
__device__ __nv_bfloat16 g_kimg_hi[(size_t)NBH*96*64];
__device__ __nv_bfloat16 g_kimg_lo[(size_t)NBH*96*64];
__device__ __nv_bfloat16 g_vimg_hi[(size_t)NBH*64*128];
__device__ __nv_bfloat16 g_vimg_lo[(size_t)NBH*64*128];
__device__ unsigned char g_fg[BB*NQ];

// ============================ PTX helpers ====================================
__device__ __forceinline__ uint32_t smem_to_u32(const void* p) {
    uint32_t a;
    asm("{ .reg .u64 t; cvta.to.shared.u64 t, %1; cvt.u32.u64 %0, t; }"
        : "=r"(a) : "l"(p));
    return a;
}

#if defined(__CUDA_ARCH_FEAT_SM103_ALL)
#define HAS_TCGEN05 1
#else
#define HAS_TCGEN05 0
#endif

#if HAS_TCGEN05
__device__ __forceinline__ uint32_t elect_one_pred() {
    uint32_t pred;
    asm volatile(
        "{\n\t.reg .pred p;\n\t"
        "elect.sync _|p, 0xFFFFFFFF;\n\t"
        "selp.b32 %0, 1, 0, p;\n\t}"
        : "=r"(pred));
    return pred;
}
#define TCGEN05_ALLOC(sa, n) \
    asm volatile("tcgen05.alloc.cta_group::1.sync.aligned.shared::cta.b32 [%0], %1;" \
        :: "r"((uint32_t)(sa)), "r"((uint32_t)(n)) : "memory")
#define TCGEN05_DEALLOC(t, n) \
    asm volatile("tcgen05.dealloc.cta_group::1.sync.aligned.b32 %0, %1;" :: "r"(t), "r"((uint32_t)(n)))
#define TCGEN05_RELINQ() \
    asm volatile("tcgen05.relinquish_alloc_permit.cta_group::1.sync.aligned;")
#define TCGEN05_COMMIT(mb) \
    asm volatile("tcgen05.commit.cta_group::1.mbarrier::arrive::one.shared::cluster.b64 [%0];" \
        :: "r"((uint32_t)(mb)) : "memory")
#define TCGEN05_FENCE_AFTER() asm volatile("tcgen05.fence::after_thread_sync;" ::: "memory")
#define TCGEN05_FENCE_BEFORE() asm volatile("tcgen05.fence::before_thread_sync;" ::: "memory")
#define TCGEN05_WAIT_LD() asm volatile("tcgen05.wait::ld.sync.aligned;" ::: "memory")
#define FENCE_ASYNC() asm volatile("fence.proxy.async.shared::cta;" ::: "memory")
#define MBARRIER_INIT(mb, c) \
    asm volatile("mbarrier.init.shared.b64 [%0], %1;" :: "r"((uint32_t)(mb)), "r"((uint32_t)(c)) : "memory")
#define MBARRIER_WAIT_PARITY(mb, ph) do { \
    uint32_t _m = (uint32_t)(mb), _p = (uint32_t)(ph), _d; \
    asm volatile("{\n\t.reg .pred p;\n\t" \
        "mbarrier.try_wait.parity.acquire.cta.shared::cta.b64 p, [%1], %2;\n\t" \
        "selp.b32 %0, 1, 0, p;\n\t}" : "=r"(_d) : "r"(_m), "r"(_p) : "memory"); \
    if (!_d) { \
        asm volatile("{\n\t.reg .pred P1;\n\t" \
            "WL_%=:\n\t" \
            "mbarrier.try_wait.parity.acquire.cta.shared::cta.b64 P1, [%0], %1, 0x989680;\n\t" \
            "@P1 bra.uni WD_%=;\n\t" \
            "bra.uni WL_%=;\n\t" \
            "WD_%=:\n\t}" :: "r"(_m), "r"(_p) : "memory"); \
    } \
} while (0)
#define TCGEN05_LD_32X32B_X32(r, ta) \
    asm volatile("tcgen05.ld.sync.aligned.32x32b.x32.b32 " \
        "{%0, %1, %2, %3, %4, %5, %6, %7, %8, %9, %10, %11, %12, %13, %14, %15, " \
        " %16, %17, %18, %19, %20, %21, %22, %23, %24, %25, %26, %27, %28, %29, %30, %31}, [%32];" \
        : "=r"((r)[0]),  "=r"((r)[1]),  "=r"((r)[2]),  "=r"((r)[3]), \
          "=r"((r)[4]),  "=r"((r)[5]),  "=r"((r)[6]),  "=r"((r)[7]), \
          "=r"((r)[8]),  "=r"((r)[9]),  "=r"((r)[10]), "=r"((r)[11]), \
          "=r"((r)[12]), "=r"((r)[13]), "=r"((r)[14]), "=r"((r)[15]), \
          "=r"((r)[16]), "=r"((r)[17]), "=r"((r)[18]), "=r"((r)[19]), \
          "=r"((r)[20]), "=r"((r)[21]), "=r"((r)[22]), "=r"((r)[23]), \
          "=r"((r)[24]), "=r"((r)[25]), "=r"((r)[26]), "=r"((r)[27]), \
          "=r"((r)[28]), "=r"((r)[29]), "=r"((r)[30]), "=r"((r)[31]) \
        : "r"(ta))

__device__ __forceinline__ void mma_f16_ss(uint32_t d_tmem, uint64_t a_desc,
                                           uint64_t b_desc, uint32_t idesc, bool acc)
{
    uint32_t en = acc ? 1u : 0u;
    asm volatile(
        "{\n\t.reg .pred p;\n\t"
        "setp.ne.u32 p, %5, 0;\n\t"
        "tcgen05.mma.cta_group::1.kind::f16 [%0], %1, %2, %3, {%4, %4, %4, %4}, p;\n\t}"
        :: "r"(d_tmem), "l"(a_desc), "l"(b_desc), "r"(idesc), "r"(0u), "r"(en)
        : "memory");
}
#endif // HAS_TCGEN05

static constexpr uint64_t SMEM_DESC_BASE_SW128 =
    (uint64_t(2)  << 61) | (uint64_t(1) << 46) | (uint64_t(64) << 32) | (uint64_t(1) << 16);
#define MAKE_SMEM_DESC(ba) (SMEM_DESC_BASE_SW128 | ((uint64_t)((ba) >> 4) & 0x3FFF))
#define SMEM_SWIZZLE_128B(bo) ((bo) ^ (((bo) >> 3) & 0x70))

__device__ __forceinline__ void bf16split(float f, ushort_t& h, ushort_t& l)
{
    __nv_bfloat16 hh = __float2bfloat16(f);
    __nv_bfloat16 ll = __float2bfloat16(f - __bfloat162float(hh));
    h = __bfloat16_as_ushort(hh);
    l = __bfloat16_as_ushort(ll);
}

// ---------------- mask: exact integer bicubic-threshold ----------------------
__global__ void mask_kernel(const int* __restrict__ mask)
{
    int idx = blockIdx.x * blockDim.x + threadIdx.x;
    if (idx >= BB*NQ) return;
    int b = idx / NQ, n = idx % NQ;
    int o = n >> 6, p = n & 63;
    const int iw[4] = {-3, 19, 19, -3};
    const int* mb = mask + (size_t)b * 256 * 256;
    int acc = 0;
#pragma unroll
    for (int s = 0; s < 4; s++) {
        const int* row = mb + (4*o + s) * 256 + 4*p;
        int rw = iw[s];
#pragma unroll
        for (int t = 0; t < 4; t++) acc += rw * iw[t] * row[t];
    }
    g_fg[idx] = (acc != 0) ? 1 : 0;
}

// ---------------- weight transpose + bf16 split -------------------------------
__global__ void wtrans_kernel(const float* __restrict__ W,
                              __nv_bfloat16* __restrict__ Thi,
                              __nv_bfloat16* __restrict__ Tlo, int K, int N)
{
    __shared__ float t[32][33];
    int k0 = blockIdx.x * 32, n0 = blockIdx.y * 32;
    int tx = threadIdx.x, ty = threadIdx.y;
    for (int r = ty; r < 32; r += 8)
        t[r][tx] = W[(size_t)(k0 + r)*N + n0 + tx];
    __syncthreads();
    for (int r = ty; r < 32; r += 8) {
        float v = t[tx][r];
        ushort_t h, l; bf16split(v, h, l);
        Thi[(size_t)(n0 + r)*K + k0 + tx] = __ushort_as_bfloat16(h);
        Tlo[(size_t)(n0 + r)*K + k0 + tx] = __ushort_as_bfloat16(l);
    }
}

// ================= bf16x3 tcgen05 GEMM: C = A@B^T (+bias) ====================
// R7 config: BK=64, BM=128, BN=256, double-buffered, register-prefetched loads.
#define G_BM 128
#define G_BN 256
#define G_BK 64
#define G_BUFSZ 98304
#define G_SMEM  (2048 + 2*G_BUFSZ)
#define G_IDESC 0x08400490u   // F32 acc, BF16xBF16, N=256, M=128

__global__ void __launch_bounds__(256)
gemm_bf16x3(const float* __restrict__ Af,
            const __nv_bfloat16* __restrict__ Ahi, const __nv_bfloat16* __restrict__ Alo,
            const __nv_bfloat16* __restrict__ Bhi, const __nv_bfloat16* __restrict__ Blo,
            const float* __restrict__ bias, float* __restrict__ C,
            __nv_bfloat16* __restrict__ Chi, __nv_bfloat16* __restrict__ Clo,
            int Mvalid, int N, int K)
{
#if HAS_TCGEN05
    extern __shared__ char smem[];
    const uint32_t sb = smem_to_u32(smem);
    const uint32_t ab = (sb + 1024 + 1023) & ~1023u;
    char* abp = smem + (ab - sb);
    const int tid = threadIdx.x;
    const int wid = tid >> 5, lane = tid & 31;
    const int brow = blockIdx.y * G_BM;
    const int bcol = blockIdx.x * G_BN;

    if (wid == 0) TCGEN05_ALLOC(sb, 256);
    __syncthreads();
    uint32_t tmem;
    asm volatile("ld.shared.b32 %0, [%1];" : "=r"(tmem) : "r"(sb));
    if (wid == 0) TCGEN05_RELINQ();
    if (tid == 0) { MBARRIER_INIT(sb + 8, 1); MBARRIER_INIT(sb + 16, 1); }
    __syncthreads();

    const int KCH = K / G_BK;
    int par0 = 0, par1 = 0;

    uint4 pah[4], pal[4], pbh[8], pbl[8];
    const int a_row = tid >> 3;
    const int a_v   = tid & 7;

    auto load_chunk = [&](int c) {
        const int k0 = c * G_BK;
#pragma unroll
        for (int i = 0; i < 4; ++i) {
            int row = a_row + i*32;
            int gr = brow + row;
            if (Af) {
                float fa[8];
                if (gr < Mvalid) {
                    const float4* src = (const float4*)(Af + (size_t)gr*K + k0 + a_v*8);
                    float4 a0 = src[0], a1 = src[1];
                    fa[0]=a0.x; fa[1]=a0.y; fa[2]=a0.z; fa[3]=a0.w;
                    fa[4]=a1.x; fa[5]=a1.y; fa[6]=a1.z; fa[7]=a1.w;
                } else {
#pragma unroll
                    for (int e = 0; e < 8; ++e) fa[e] = 0.f;
                }
                uint32_t hw[4], lw[4];
#pragma unroll
                for (int e = 0; e < 4; ++e) {
                    ushort_t h0, l0, h1, l1;
                    bf16split(fa[2*e],   h0, l0);
                    bf16split(fa[2*e+1], h1, l1);
                    hw[e] = ((uint32_t)h1 << 16) | h0;
                    lw[e] = ((uint32_t)l1 << 16) | l0;
                }
                pah[i] = make_uint4(hw[0], hw[1], hw[2], hw[3]);
                pal[i] = make_uint4(lw[0], lw[1], lw[2], lw[3]);
            } else {
                pah[i] = *(const uint4*)(Ahi + (size_t)gr*K + k0 + a_v*8);
                pal[i] = *(const uint4*)(Alo + (size_t)gr*K + k0 + a_v*8);
            }
        }
#pragma unroll
        for (int i = 0; i < 8; ++i) {
            int row = a_row + i*32;
            pbh[i] = *(const uint4*)(Bhi + (size_t)(bcol + row)*K + k0 + a_v*8);
            pbl[i] = *(const uint4*)(Blo + (size_t)(bcol + row)*K + k0 + a_v*8);
        }
    };

    load_chunk(0);

    for (int c = 0; c < KCH; ++c) {
        int p = c & 1;
        if (c >= 2) {
            if (p == 0) { MBARRIER_WAIT_PARITY(sb + 8, par0); par0 ^= 1; }
            else        { MBARRIER_WAIT_PARITY(sb + 16, par1); par1 ^= 1; }
        }
        char* base = abp + p * G_BUFSZ;

#pragma unroll
        for (int i = 0; i < 4; ++i) {
            uint32_t so = SMEM_SWIZZLE_128B((uint32_t)((a_row + i*32)*128 + a_v*16));
            *(uint4*)(base + so) = pah[i];
            *(uint4*)(base + 16384 + so) = pal[i];
        }
#pragma unroll
        for (int i = 0; i < 8; ++i) {
            uint32_t so = SMEM_SWIZZLE_128B((uint32_t)((a_row + i*32)*128 + a_v*16));
            *(uint4*)(base + 32768 + so) = pbh[i];
            *(uint4*)(base + 65536 + so) = pbl[i];
        }
        __syncthreads();

        if (wid == 0 && elect_one_pred()) {
            FENCE_ASYNC();
            uint32_t bu = ab + p * G_BUFSZ;
            uint64_t dah = MAKE_SMEM_DESC(bu);
            uint64_t dal = MAKE_SMEM_DESC(bu + 16384);
            uint64_t dbh = MAKE_SMEM_DESC(bu + 32768);
            uint64_t dbl = MAKE_SMEM_DESC(bu + 65536);
#pragma unroll
            for (int ks = 0; ks < 4; ++ks)
                mma_f16_ss(tmem, dah + ks*2, dbh + ks*2, G_IDESC, !(c == 0 && ks == 0));
#pragma unroll
            for (int ks = 0; ks < 4; ++ks)
                mma_f16_ss(tmem, dah + ks*2, dbl + ks*2, G_IDESC, true);
#pragma unroll
            for (int ks = 0; ks < 4; ++ks)
                mma_f16_ss(tmem, dal + ks*2, dbh + ks*2, G_IDESC, true);
            TCGEN05_COMMIT(sb + 8 + p*8);
        }

        if (c + 1 < KCH) load_chunk(c + 1);
    }
    MBARRIER_WAIT_PARITY(sb + 8, par0);
    MBARRIER_WAIT_PARITY(sb + 16, par1);
    TCGEN05_FENCE_AFTER();

    if (wid < 4) {
        int row = brow + wid*32 + lane;
#pragma unroll
        for (int cb = 0; cb < G_BN/32; ++cb) {
            uint32_t r[32];
            TCGEN05_LD_32X32B_X32(r, tmem + cb*32);
            TCGEN05_WAIT_LD();
            int col0 = bcol + cb*32;
            if (Chi) {
                uint32_t hp[16], lp[16];
#pragma unroll
                for (int m = 0; m < 16; ++m) {
                    ushort_t h0, l0, h1, l1;
                    bf16split(__uint_as_float(r[2*m]),   h0, l0);
                    bf16split(__uint_as_float(r[2*m+1]), h1, l1);
                    hp[m] = ((uint32_t)h1 << 16) | h0;
                    lp[m] = ((uint32_t)l1 << 16) | l0;
                }
                uint32_t* dh = (uint32_t*)(Chi + (size_t)row*N + col0);
                uint32_t* dl = (uint32_t*)(Clo + (size_t)row*N + col0);
#pragma unroll
                for (int m = 0; m < 16; ++m) { dh[m] = hp[m]; dl[m] = lp[m]; }
            } else {
                float* cp = C + (size_t)row*N + col0;
                if (bias) {
#pragma unroll
                    for (int i = 0; i < 32; ++i) cp[i] = __uint_as_float(r[i]) + bias[col0 + i];
                } else {
#pragma unroll
                    for (int i = 0; i < 32; ++i) cp[i] = __uint_as_float(r[i]);
                }
            }
        }
        TCGEN05_FENCE_BEFORE();
    }
    __syncthreads();
    if (wid == 0) TCGEN05_DEALLOC(tmem, 256);
#endif
}

// ---------------- K / V^T image bake (swizzled SMEM images) -------------------
__global__ void __launch_bounds__(128) kv_image_kernel()
{
    int bh = blockIdx.x;
    int b = bh / NHEADS, h = bh % NHEADS;
    int tid = threadIdx.x;
    char* kh = (char*)(g_kimg_hi + (size_t)bh*96*64);
    char* kl = (char*)(g_kimg_lo + (size_t)bh*96*64);
    char* vh = (char*)(g_vimg_hi + (size_t)bh*64*128);
    char* vl = (char*)(g_vimg_lo + (size_t)bh*64*128);

    for (int u = tid; u < 96*64; u += 128) {
        int j = u >> 6, d = u & 63;
        float f = (j < CTX) ? g_k[(size_t)(b*CTX + j)*INNER + h*DHEAD + d] : 0.f;
        ushort_t hh, ll; bf16split(f, hh, ll);
        uint32_t so = SMEM_SWIZZLE_128B((uint32_t)(j*128 + d*2));
        *(ushort_t*)(kh + so) = hh;
        *(ushort_t*)(kl + so) = ll;
    }
    for (int u = tid; u < 64*128; u += 128) {
        int d = u >> 7, j = u & 127;
        float f = (j < CTX) ? g_v[(size_t)(b*CTX + j)*INNER + h*DHEAD + d] : 0.f;
        ushort_t hh, ll; bf16split(f, hh, ll);
        uint32_t addr = (uint32_t)(((d >> 3) + (j >> 6)*8)*1024 + (d & 7)*128 + (j & 63)*2);
        uint32_t so = SMEM_SWIZZLE_128B(addr);
        *(ushort_t*)(vh + so) = hh;
        *(ushort_t*)(vl + so) = ll;
    }
}

// ---------------- tcgen05 fused masked attention ------------------------------
// ATT_QT=8: 640 CTAs (4.32 waves), KV-image prologue amortized over 8 q-tiles.
#define ATT_QT 8
#define A_QHI 0
#define A_QLO 16384
#define A_KHI 32768
#define A_KLO 45056
#define A_VHI 57344
#define A_VLO 73728
#define A_PHI 90112
#define A_PLO 122880
#define ATTN_SMEM (2048 + 155648)
#define IDESC_S 0x08180490u   // M=128, N=96
#define IDESC_O 0x08100490u   // M=128, N=64

__global__ void __launch_bounds__(128) attn_tc()
{
#if HAS_TCGEN05
    extern __shared__ char smem[];
    const uint32_t sb = smem_to_u32(smem);
    const uint32_t ab = (sb + 1024 + 1023) & ~1023u;
    char* abp = smem + (ab - sb);
    int tid = threadIdx.x, wid = tid >> 5;
    int b = blockIdx.z, h = blockIdx.y, qg = blockIdx.x;
    int bh = b*NHEADS + h;

    if (wid == 0) TCGEN05_ALLOC(sb, 256);
    __syncthreads();
    uint32_t tmem;
    asm volatile("ld.shared.b32 %0, [%1];" : "=r"(tmem) : "r"(sb));
    if (wid == 0) TCGEN05_RELINQ();
    if (tid == 0) { MBARRIER_INIT(sb + 8, 1); MBARRIER_INIT(sb + 16, 1); }
    __syncthreads();

    {
        const uint4* skh = (const uint4*)(g_kimg_hi + (size_t)bh*96*64);
        const uint4* skl = (const uint4*)(g_kimg_lo + (size_t)bh*96*64);
        for (int u = tid; u < 768; u += 128) {
            ((uint4*)(abp + A_KHI))[u] = skh[u];
            ((uint4*)(abp + A_KLO))[u] = skl[u];
        }
        const uint4* svh = (const uint4*)(g_vimg_hi + (size_t)bh*64*128);
        const uint4* svl = (const uint4*)(g_vimg_lo + (size_t)bh*64*128);
        for (int u = tid; u < 1024; u += 128) {
            ((uint4*)(abp + A_VHI))[u] = svh[u];
            ((uint4*)(abp + A_VLO))[u] = svl[u];
        }
    }

    int par0 = 0, par1 = 0;
    for (int qt = 0; qt < ATT_QT; ++qt) {
        int qbase = (qg*ATT_QT + qt)*128;
        size_t qrow = (size_t)(b*NQ + qbase + tid)*INNER + h*DHEAD;
        {
            const uint4* qh = (const uint4*)(g_qhi + qrow);
            const uint4* ql = (const uint4*)(g_qlo + qrow);
#pragma unroll
            for (int v = 0; v < 8; ++v) {
                uint32_t so = SMEM_SWIZZLE_128B((uint32_t)(tid*128 + v*16));
                *(uint4*)(abp + A_QHI + so) = qh[v];
                *(uint4*)(abp + A_QLO + so) = ql[v];
            }
        }
        __syncthreads();
        if (wid == 0 && elect_one_pred()) {
            FENCE_ASYNC();
            uint64_t dqh = MAKE_SMEM_DESC(ab + A_QHI);
            uint64_t dql = MAKE_SMEM_DESC(ab + A_QLO);
            uint64_t dkh = MAKE_SMEM_DESC(ab + A_KHI);
            uint64_t dkl = MAKE_SMEM_DESC(ab + A_KLO);
#pragma unroll
            for (int ks = 0; ks < 4; ++ks)
                mma_f16_ss(tmem, dqh + ks*2, dkh + ks*2, IDESC_S, ks > 0);
#pragma unroll
            for (int ks = 0; ks < 4; ++ks)
                mma_f16_ss(tmem, dqh + ks*2, dkl + ks*2, IDESC_S, true);
#pragma unroll
            for (int ks = 0; ks < 4; ++ks)
                mma_f16_ss(tmem, dql + ks*2, dkh + ks*2, IDESC_S, true);
            TCGEN05_COMMIT(sb + 8);
        }
        MBARRIER_WAIT_PARITY(sb + 8, par0); par0 ^= 1;
        TCGEN05_FENCE_AFTER();

        float s[96];
#pragma unroll
        for (int cb = 0; cb < 3; ++cb) {
            uint32_t rr[32];
            TCGEN05_LD_32X32B_X32(rr, tmem + cb*32);
            TCGEN05_WAIT_LD();
#pragma unroll
            for (int i = 0; i < 32; ++i) s[cb*32 + i] = __uint_as_float(rr[i]);
        }
        TCGEN05_FENCE_BEFORE();
        int fg = g_fg[b*NQ + qbase + tid];
        float mx = -FLT_MAX;
#pragma unroll
        for (int j = 0; j < CTX; ++j) {
            float a = s[j] * 0.125f;
            bool valid = (j < 77) || ((j < 81) ? (fg != 0) : (fg == 0));
            a = valid ? a : -FLT_MAX;
            s[j] = a;
            mx = fmaxf(mx, a);
        }
        float sum = 0.f;
#pragma unroll
        for (int j = 0; j < CTX; ++j) {
            float e = (s[j] > -3.0e38f) ? __expf(s[j] - mx) : 0.f;
            s[j] = e;
            sum += e;
        }
        float inv = 1.f / sum;
#pragma unroll
        for (int j = CTX; j < 96; ++j) s[j] = 0.f;

        {
            int r = tid;
#pragma unroll
            for (int g = 0; g < 16; ++g) {
                int c0 = g*8;
                uint32_t hv[4], lv[4];
#pragma unroll
                for (int pe = 0; pe < 4; ++pe) {
                    int c = c0 + 2*pe;
                    float f0 = (c < 96) ? s[c] : 0.f;
                    float f1 = (c+1 < 96) ? s[c+1] : 0.f;
                    ushort_t h0, l0, h1, l1;
                    bf16split(f0, h0, l0);
                    bf16split(f1, h1, l1);
                    hv[pe] = ((uint32_t)h1 << 16) | h0;
                    lv[pe] = ((uint32_t)l1 << 16) | l0;
                }
                uint32_t addr = (uint32_t)(((r >> 3) + (c0 >> 6)*16)*1024 + (r & 7)*128 + (c0 & 63)*2);
                uint32_t so = SMEM_SWIZZLE_128B(addr);
                *(uint4*)(abp + A_PHI + so) = make_uint4(hv[0], hv[1], hv[2], hv[3]);
                *(uint4*)(abp + A_PLO + so) = make_uint4(lv[0], lv[1], lv[2], lv[3]);
            }
        }
        __syncthreads();
        if (wid == 0 && elect_one_pred()) {
            FENCE_ASYNC();
            uint64_t dph = MAKE_SMEM_DESC(ab + A_PHI);
            uint64_t dpl = MAKE_SMEM_DESC(ab + A_PLO);
            uint64_t dvh = MAKE_SMEM_DESC(ab + A_VHI);
            uint64_t dvl = MAKE_SMEM_DESC(ab + A_VLO);
#pragma unroll
            for (int ks = 0; ks < 8; ++ks) {
                uint64_t aoff = (ks < 4) ? ks*2 : 1024 + (ks-4)*2;
                uint64_t boff = (ks < 4) ? ks*2 : 512 + (ks-4)*2;
                mma_f16_ss(tmem + 96, dph + aoff, dvh + boff, IDESC_O, ks > 0);
            }
#pragma unroll
            for (int ks = 0; ks < 8; ++ks) {
                uint64_t aoff = (ks < 4) ? ks*2 : 1024 + (ks-4)*2;
                uint64_t boff = (ks < 4) ? ks*2 : 512 + (ks-4)*2;
                mma_f16_ss(tmem + 96, dph + aoff, dvl + boff, IDESC_O, true);
            }
#pragma unroll
            for (int ks = 0; ks < 8; ++ks) {
                uint64_t aoff = (ks < 4) ? ks*2 : 1024 + (ks-4)*2;
                uint64_t boff = (ks < 4) ? ks*2 : 512 + (ks-4)*2;
                mma_f16_ss(tmem + 96, dpl + aoff, dvh + boff, IDESC_O, true);
            }
            TCGEN05_COMMIT(sb + 16);
        }
        MBARRIER_WAIT_PARITY(sb + 16, par1); par1 ^= 1;
        TCGEN05_FENCE_AFTER();

        size_t obase = (size_t)(b*NQ + qbase + tid)*INNER + h*DHEAD;
#pragma unroll
        for (int cb = 0; cb < 2; ++cb) {
            uint32_t rr[32];
            TCGEN05_LD_32X32B_X32(rr, tmem + 96 + cb*32);
            TCGEN05_WAIT_LD();
#pragma unroll
            for (int g = 0; g < 4; ++g) {
                uint32_t hv[4], lv[4];
#pragma unroll
                for (int pe = 0; pe < 4; ++pe) {
                    float f0 = __uint_as_float(rr[g*8 + 2*pe])     * inv;
                    float f1 = __uint_as_float(rr[g*8 + 2*pe + 1]) * inv;
                    ushort_t h0, l0, h1, l1;
                    bf16split(f0, h0, l0);
                    bf16split(f1, h1, l1);
                    hv[pe] = ((uint32_t)h1 << 16) | h0;
                    lv[pe] = ((uint32_t)l1 << 16) | l0;
                }
                *(uint4*)(g_ao_hi + obase + cb*32 + g*8) = make_uint4(hv[0], hv[1], hv[2], hv[3]);
                *(uint4*)(g_ao_lo + obase + cb*32 + g*8) = make_uint4(lv[0], lv[1], lv[2], lv[3]);
            }
        }
        TCGEN05_FENCE_BEFORE();
        __syncthreads();
    }
    if (wid == 0) TCGEN05_DEALLOC(tmem, 256);
#endif
}

// ---------------- launch ------------------------------------------------------
extern "C" void kernel_launch(void* const* d_in, const int* in_sizes, int n_in,
                              void* d_out, int out_size)
{
    (void)in_sizes; (void)n_in; (void)out_size;
    const float* x    = (const float*)d_in[0];
    const float* ctxp = (const float*)d_in[1];
    const float* Wq   = (const float*)d_in[2];
    const float* Wk   = (const float*)d_in[3];
    const float* Wv   = (const float*)d_in[4];
    const float* Wo   = (const float*)d_in[5];
    const float* bo   = (const float*)d_in[6];
    const int*   mask = (const int*)d_in[7];
    float* out = (float*)d_out;

    float *k, *v;
    __nv_bfloat16 *qhi, *qlo, *aohi, *aolo;
    __nv_bfloat16 *wqth, *wqtl, *wkth, *wktl, *wvth, *wvtl, *woth, *wotl;
    cudaGetSymbolAddress((void**)&k,    g_k);
    cudaGetSymbolAddress((void**)&v,    g_v);
    cudaGetSymbolAddress((void**)&qhi,  g_qhi);
    cudaGetSymbolAddress((void**)&qlo,  g_qlo);
    cudaGetSymbolAddress((void**)&aohi, g_ao_hi);
    cudaGetSymbolAddress((void**)&aolo, g_ao_lo);
    cudaGetSymbolAddress((void**)&wqth, g_wqt_hi);
    cudaGetSymbolAddress((void**)&wqtl, g_wqt_lo);
    cudaGetSymbolAddress((void**)&wkth, g_wkt_hi);
    cudaGetSymbolAddress((void**)&wktl, g_wkt_lo);
    cudaGetSymbolAddress((void**)&wvth, g_wvt_hi);
    cudaGetSymbolAddress((void**)&wvtl, g_wvt_lo);
    cudaGetSymbolAddress((void**)&woth, g_wot_hi);
    cudaGetSymbolAddress((void**)&wotl, g_wot_lo);

    cudaFuncSetAttribute(gemm_bf16x3, cudaFuncAttributeMaxDynamicSharedMemorySize, G_SMEM);
    cudaFuncSetAttribute(attn_tc, cudaFuncAttributeMaxDynamicSharedMemorySize, ATTN_SMEM);

    dim3 blk(32, 8);

    // Profiler captures launch #4 -> keep the Q GEMM there.
    mask_kernel<<<(BB*NQ + 255)/256, 256>>>(mask);                              // 1
    wtrans_kernel<<<dim3(QD/32, INNER/32), blk>>>(Wq, wqth, wqtl, QD, INNER);   // 2
    wtrans_kernel<<<dim3(INNER/32, QD/32), blk>>>(Wo, woth, wotl, INNER, QD);   // 3

    // 4: Q projection (fp32 A, fused split) -> bf16 hi/lo   [PROFILED]
    gemm_bf16x3<<<dim3(INNER/G_BN, (BB*NQ)/G_BM), 256, G_SMEM>>>(
        x, nullptr, nullptr, wqth, wqtl, nullptr, nullptr, qhi, qlo,
        BB*NQ, INNER, QD);

    // 5,6: remaining weight transposes
    wtrans_kernel<<<dim3(CD/32, INNER/32), blk>>>(Wk, wkth, wktl, CD, INNER);   // 5
    wtrans_kernel<<<dim3(CD/32, INNER/32), blk>>>(Wv, wvth, wvtl, CD, INNER);   // 6

    // 7,8: K, V projections (fp32 ctx A, fused split + pad)
    gemm_bf16x3<<<dim3(INNER/G_BN, MKV/G_BM), 256, G_SMEM>>>(
        ctxp, nullptr, nullptr, wkth, wktl, nullptr, k, nullptr, nullptr,
        BB*CTX, INNER, CD);
    gemm_bf16x3<<<dim3(INNER/G_BN, MKV/G_BM), 256, G_SMEM>>>(
        ctxp, nullptr, nullptr, wvth, wvtl, nullptr, v, nullptr, nullptr,
        BB*CTX, INNER, CD);

    // 9: bake K / V^T swizzled images
    kv_image_kernel<<<NBH, 128>>>();

    // 10: tensor-core masked attention (8 q-tiles per CTA)
    attn_tc<<<dim3(NQ/(ATT_QT*128), NHEADS, BB), 128, ATTN_SMEM>>>();

    // 11: output projection + bias
    gemm_bf16x3<<<dim3(QD/G_BN, (BB*NQ)/G_BM), 256, G_SMEM>>>(
        nullptr, aohi, aolo, woth, wotl, bo, out, nullptr, nullptr,
        BB*NQ, QD, INNER);
}

// round 11
// speedup vs baseline: 1.5068x; 1.0082x over previous
#include <cuda_runtime.h>
#include <cuda_bf16.h>
#include <math.h>
#include <float.h>
#include <stdint.h>

#define BB 8
#define NQ 4096
#define QD 1280
#define CD 1024
#define CTX 85
#define NHEADS 20
#define DHEAD 64
#define INNER (NHEADS*DHEAD)   // 1280
#define MKV 768
#define NBH (BB*NHEADS)        // 160

typedef unsigned short ushort_t;

// ---------------- scratch (static device globals; no allocation) -------------
__device__ float g_k [(size_t)MKV*INNER];
__device__ float g_v [(size_t)MKV*INNER];
__device__ __nv_bfloat16 g_qhi[(size_t)BB*NQ*INNER];
__device__ __nv_bfloat16 g_qlo[(size_t)BB*NQ*INNER];
__device__ __nv_bfloat16 g_ao_hi[(size_t)BB*NQ*INNER];
__device__ __nv_bfloat16 g_ao_lo[(size_t)BB*NQ*INNER];
__device__ __nv_bfloat16 g_wqt_hi[(size_t)INNER*QD];
__device__ __nv_bfloat16 g_wqt_lo[(size_t)INNER*QD];
__device__ __nv_bfloat16 g_wkt_hi[(size_t)INNER*CD];
__device__ __nv_bfloat16 g_wkt_lo[(size_t)INNER*CD];
__device__ __nv_bfloat16 g_wvt_hi[(size_t)INNER*CD];
__device__ __nv_bfloat16 g_wvt_lo[(size_t)INNER*CD];
__device__ __nv_bfloat16 g_wot_hi[(size_t)QD*INNER];
__device__ __nv_bfloat16 g_wot_lo[(size_t)QD*INNER];
__device__ __nv_bfloat16 g_kimg_hi[(size_t)NBH*96*64];
__device__ __nv_bfloat16 g_kimg_lo[(size_t)NBH*96*64];
__device__ __nv_bfloat16 g_vimg_hi[(size_t)NBH*64*128];
__device__ __nv_bfloat16 g_vimg_lo[(size_t)NBH*64*128];
__device__ unsigned char g_fg[BB*NQ];

// ============================ PTX helpers ====================================
__device__ __forceinline__ uint32_t smem_to_u32(const void* p) {
    uint32_t a;
    asm("{ .reg .u64 t; cvta.to.shared.u64 t, %1; cvt.u32.u64 %0, t; }"
        : "=r"(a) : "l"(p));
    return a;
}

#if defined(__CUDA_ARCH_FEAT_SM103_ALL)
#define HAS_TCGEN05 1
#else
#define HAS_TCGEN05 0
#endif

#if HAS_TCGEN05
__device__ __forceinline__ uint32_t elect_one_pred() {
    uint32_t pred;
    asm volatile(
        "{\n\t.reg .pred p;\n\t"
        "elect.sync _|p, 0xFFFFFFFF;\n\t"
        "selp.b32 %0, 1, 0, p;\n\t}"
        : "=r"(pred));
    return pred;
}
#define TCGEN05_ALLOC(sa, n) \
    asm volatile("tcgen05.alloc.cta_group::1.sync.aligned.shared::cta.b32 [%0], %1;" \
        :: "r"((uint32_t)(sa)), "r"((uint32_t)(n)) : "memory")
#define TCGEN05_DEALLOC(t, n) \
    asm volatile("tcgen05.dealloc.cta_group::1.sync.aligned.b32 %0, %1;" :: "r"(t), "r"((uint32_t)(n)))
#define TCGEN05_RELINQ() \
    asm volatile("tcgen05.relinquish_alloc_permit.cta_group::1.sync.aligned;")
#define TCGEN05_COMMIT(mb) \
    asm volatile("tcgen05.commit.cta_group::1.mbarrier::arrive::one.shared::cluster.b64 [%0];" \
        :: "r"((uint32_t)(mb)) : "memory")
#define TCGEN05_FENCE_AFTER() asm volatile("tcgen05.fence::after_thread_sync;" ::: "memory")
#define TCGEN05_FENCE_BEFORE() asm volatile("tcgen05.fence::before_thread_sync;" ::: "memory")
#define TCGEN05_WAIT_LD() asm volatile("tcgen05.wait::ld.sync.aligned;" ::: "memory")
#define FENCE_ASYNC() asm volatile("fence.proxy.async.shared::cta;" ::: "memory")
#define MBARRIER_INIT(mb, c) \
    asm volatile("mbarrier.init.shared.b64 [%0], %1;" :: "r"((uint32_t)(mb)), "r"((uint32_t)(c)) : "memory")
#define MBARRIER_WAIT_PARITY(mb, ph) do { \
    uint32_t _m = (uint32_t)(mb), _p = (uint32_t)(ph), _d; \
    asm volatile("{\n\t.reg .pred p;\n\t" \
        "mbarrier.try_wait.parity.acquire.cta.shared::cta.b64 p, [%1], %2;\n\t" \
        "selp.b32 %0, 1, 0, p;\n\t}" : "=r"(_d) : "r"(_m), "r"(_p) : "memory"); \
    if (!_d) { \
        asm volatile("{\n\t.reg .pred P1;\n\t" \
            "WL_%=:\n\t" \
            "mbarrier.try_wait.parity.acquire.cta.shared::cta.b64 P1, [%0], %1, 0x989680;\n\t" \
            "@P1 bra.uni WD_%=;\n\t" \
            "bra.uni WL_%=;\n\t" \
            "WD_%=:\n\t}" :: "r"(_m), "r"(_p) : "memory"); \
    } \
} while (0)
#define TCGEN05_LD_32X32B_X32(r, ta) \
    asm volatile("tcgen05.ld.sync.aligned.32x32b.x32.b32 " \
        "{%0, %1, %2, %3, %4, %5, %6, %7, %8, %9, %10, %11, %12, %13, %14, %15, " \
        " %16, %17, %18, %19, %20, %21, %22, %23, %24, %25, %26, %27, %28, %29, %30, %31}, [%32];" \
        : "=r"((r)[0]),  "=r"((r)[1]),  "=r"((r)[2]),  "=r"((r)[3]), \
          "=r"((r)[4]),  "=r"((r)[5]),  "=r"((r)[6]),  "=r"((r)[7]), \
          "=r"((r)[8]),  "=r"((r)[9]),  "=r"((r)[10]), "=r"((r)[11]), \
          "=r"((r)[12]), "=r"((r)[13]), "=r"((r)[14]), "=r"((r)[15]), \
          "=r"((r)[16]), "=r"((r)[17]), "=r"((r)[18]), "=r"((r)[19]), \
          "=r"((r)[20]), "=r"((r)[21]), "=r"((r)[22]), "=r"((r)[23]), \
          "=r"((r)[24]), "=r"((r)[25]), "=r"((r)[26]), "=r"((r)[27]), \
          "=r"((r)[28]), "=r"((r)[29]), "=r"((r)[30]), "=r"((r)[31]) \
        : "r"(ta))

__device__ __forceinline__ void mma_f16_ss(uint32_t d_tmem, uint64_t a_desc,
                                           uint64_t b_desc, uint32_t idesc, bool acc)
{
    uint32_t en = acc ? 1u : 0u;
    asm volatile(
        "{\n\t.reg .pred p;\n\t"
        "setp.ne.u32 p, %5, 0;\n\t"
        "tcgen05.mma.cta_group::1.kind::f16 [%0], %1, %2, %3, {%4, %4, %4, %4}, p;\n\t}"
        :: "r"(d_tmem), "l"(a_desc), "l"(b_desc), "r"(idesc), "r"(0u), "r"(en)
        : "memory");
}
#endif // HAS_TCGEN05

static constexpr uint64_t SMEM_DESC_BASE_SW128 =
    (uint64_t(2)  << 61) | (uint64_t(1) << 46) | (uint64_t(64) << 32) | (uint64_t(1) << 16);
#define MAKE_SMEM_DESC(ba) (SMEM_DESC_BASE_SW128 | ((uint64_t)((ba) >> 4) & 0x3FFF))
#define SMEM_SWIZZLE_128B(bo) ((bo) ^ (((bo) >> 3) & 0x70))

__device__ __forceinline__ void bf16split(float f, ushort_t& h, ushort_t& l)
{
    __nv_bfloat16 hh = __float2bfloat16(f);
    __nv_bfloat16 ll = __float2bfloat16(f - __bfloat162float(hh));
    h = __bfloat16_as_ushort(hh);
    l = __bfloat16_as_ushort(ll);
}

// ---------------- mask: exact integer bicubic-threshold ----------------------
__global__ void mask_kernel(const int* __restrict__ mask)
{
    int idx = blockIdx.x * blockDim.x + threadIdx.x;
    if (idx >= BB*NQ) return;
    int b = idx / NQ, n = idx % NQ;
    int o = n >> 6, p = n & 63;
    const int iw[4] = {-3, 19, 19, -3};
    const int* mb = mask + (size_t)b * 256 * 256;
    int acc = 0;
#pragma unroll
    for (int s = 0; s < 4; s++) {
        const int* row = mb + (4*o + s) * 256 + 4*p;
        int rw = iw[s];
#pragma unroll
        for (int t = 0; t < 4; t++) acc += rw * iw[t] * row[t];
    }
    g_fg[idx] = (acc != 0) ? 1 : 0;
}

// ---------------- weight transpose + bf16 split -------------------------------
__global__ void wtrans_kernel(const float* __restrict__ W,
                              __nv_bfloat16* __restrict__ Thi,
                              __nv_bfloat16* __restrict__ Tlo, int K, int N)
{
    __shared__ float t[32][33];
    int k0 = blockIdx.x * 32, n0 = blockIdx.y * 32;
    int tx = threadIdx.x, ty = threadIdx.y;
    for (int r = ty; r < 32; r += 8)
        t[r][tx] = W[(size_t)(k0 + r)*N + n0 + tx];
    __syncthreads();
    for (int r = ty; r < 32; r += 8) {
        float v = t[tx][r];
        ushort_t h, l; bf16split(v, h, l);
        Thi[(size_t)(n0 + r)*K + k0 + tx] = __ushort_as_bfloat16(h);
        Tlo[(size_t)(n0 + r)*K + k0 + tx] = __ushort_as_bfloat16(l);
    }
}

// ================= bf16x3 tcgen05 GEMM: C = A@B^T (+bias) ====================
// R7 config: BK=64, BM=128, BN=256, double-buffered, register-prefetched loads.
#define G_BM 128
#define G_BN 256
#define G_BK 64
#define G_BUFSZ 98304
#define G_SMEM  (2048 + 2*G_BUFSZ)
#define G_IDESC 0x08400490u   // F32 acc, BF16xBF16, N=256, M=128

__global__ void __launch_bounds__(256)
gemm_bf16x3(const float* __restrict__ Af,
            const __nv_bfloat16* __restrict__ Ahi, const __nv_bfloat16* __restrict__ Alo,
            const __nv_bfloat16* __restrict__ Bhi, const __nv_bfloat16* __restrict__ Blo,
            const float* __restrict__ bias, float* __restrict__ C,
            __nv_bfloat16* __restrict__ Chi, __nv_bfloat16* __restrict__ Clo,
            int Mvalid, int N, int K)
{
#if HAS_TCGEN05
    extern __shared__ char smem[];
    const uint32_t sb = smem_to_u32(smem);
    const uint32_t ab = (sb + 1024 + 1023) & ~1023u;
    char* abp = smem + (ab - sb);
    const int tid = threadIdx.x;
    const int wid = tid >> 5, lane = tid & 31;
    const int brow = blockIdx.y * G_BM;
    const int bcol = blockIdx.x * G_BN;

    if (wid == 0) TCGEN05_ALLOC(sb, 256);
    __syncthreads();
    uint32_t tmem;
    asm volatile("ld.shared.b32 %0, [%1];" : "=r"(tmem) : "r"(sb));
    if (wid == 0) TCGEN05_RELINQ();
    if (tid == 0) { MBARRIER_INIT(sb + 8, 1); MBARRIER_INIT(sb + 16, 1); }
    __syncthreads();

    const int KCH = K / G_BK;
    int par0 = 0, par1 = 0;

    uint4 pah[4], pal[4], pbh[8], pbl[8];
    const int a_row = tid >> 3;
    const int a_v   = tid & 7;

    auto load_chunk = [&](int c) {
        const int k0 = c * G_BK;
#pragma unroll
        for (int i = 0; i < 4; ++i) {
            int row = a_row + i*32;
            int gr = brow + row;
            if (Af) {
                float fa[8];
                if (gr < Mvalid) {
                    const float4* src = (const float4*)(Af + (size_t)gr*K + k0 + a_v*8);
                    float4 a0 = src[0], a1 = src[1];
                    fa[0]=a0.x; fa[1]=a0.y; fa[2]=a0.z; fa[3]=a0.w;
                    fa[4]=a1.x; fa[5]=a1.y; fa[6]=a1.z; fa[7]=a1.w;
                } else {
#pragma unroll
                    for (int e = 0; e < 8; ++e) fa[e] = 0.f;
                }
                uint32_t hw[4], lw[4];
#pragma unroll
                for (int e = 0; e < 4; ++e) {
                    ushort_t h0, l0, h1, l1;
                    bf16split(fa[2*e],   h0, l0);
                    bf16split(fa[2*e+1], h1, l1);
                    hw[e] = ((uint32_t)h1 << 16) | h0;
                    lw[e] = ((uint32_t)l1 << 16) | l0;
                }
                pah[i] = make_uint4(hw[0], hw[1], hw[2], hw[3]);
                pal[i] = make_uint4(lw[0], lw[1], lw[2], lw[3]);
            } else {
                pah[i] = *(const uint4*)(Ahi + (size_t)gr*K + k0 + a_v*8);
                pal[i] = *(const uint4*)(Alo + (size_t)gr*K + k0 + a_v*8);
            }
        }
#pragma unroll
        for (int i = 0; i < 8; ++i) {
            int row = a_row + i*32;
            pbh[i] = *(const uint4*)(Bhi + (size_t)(bcol + row)*K + k0 + a_v*8);
            pbl[i] = *(const uint4*)(Blo + (size_t)(bcol + row)*K + k0 + a_v*8);
        }
    };

    load_chunk(0);

    for (int c = 0; c < KCH; ++c) {
        int p = c & 1;
        if (c >= 2) {
            if (p == 0) { MBARRIER_WAIT_PARITY(sb + 8, par0); par0 ^= 1; }
            else        { MBARRIER_WAIT_PARITY(sb + 16, par1); par1 ^= 1; }
        }
        char* base = abp + p * G_BUFSZ;

#pragma unroll
        for (int i = 0; i < 4; ++i) {
            uint32_t so = SMEM_SWIZZLE_128B((uint32_t)((a_row + i*32)*128 + a_v*16));
            *(uint4*)(base + so) = pah[i];
            *(uint4*)(base + 16384 + so) = pal[i];
        }
#pragma unroll
        for (int i = 0; i < 8; ++i) {
            uint32_t so = SMEM_SWIZZLE_128B((uint32_t)((a_row + i*32)*128 + a_v*16));
            *(uint4*)(base + 32768 + so) = pbh[i];
            *(uint4*)(base + 65536 + so) = pbl[i];
        }
        __syncthreads();

        if (wid == 0 && elect_one_pred()) {
            FENCE_ASYNC();
            uint32_t bu = ab + p * G_BUFSZ;
            uint64_t dah = MAKE_SMEM_DESC(bu);
            uint64_t dal = MAKE_SMEM_DESC(bu + 16384);
            uint64_t dbh = MAKE_SMEM_DESC(bu + 32768);
            uint64_t dbl = MAKE_SMEM_DESC(bu + 65536);
#pragma unroll
            for (int ks = 0; ks < 4; ++ks)
                mma_f16_ss(tmem, dah + ks*2, dbh + ks*2, G_IDESC, !(c == 0 && ks == 0));
#pragma unroll
            for (int ks = 0; ks < 4; ++ks)
                mma_f16_ss(tmem, dah + ks*2, dbl + ks*2, G_IDESC, true);
#pragma unroll
            for (int ks = 0; ks < 4; ++ks)
                mma_f16_ss(tmem, dal + ks*2, dbh + ks*2, G_IDESC, true);
            TCGEN05_COMMIT(sb + 8 + p*8);
        }

        if (c + 1 < KCH) load_chunk(c + 1);
    }
    MBARRIER_WAIT_PARITY(sb + 8, par0);
    MBARRIER_WAIT_PARITY(sb + 16, par1);
    TCGEN05_FENCE_AFTER();

    if (wid < 4) {
        int row = brow + wid*32 + lane;
#pragma unroll
        for (int cb = 0; cb < G_BN/32; ++cb) {
            uint32_t r[32];
            TCGEN05_LD_32X32B_X32(r, tmem + cb*32);
            TCGEN05_WAIT_LD();
            int col0 = bcol + cb*32;
            if (Chi) {
                uint32_t hp[16], lp[16];
#pragma unroll
                for (int m = 0; m < 16; ++m) {
                    ushort_t h0, l0, h1, l1;
                    bf16split(__uint_as_float(r[2*m]),   h0, l0);
                    bf16split(__uint_as_float(r[2*m+1]), h1, l1);
                    hp[m] = ((uint32_t)h1 << 16) | h0;
                    lp[m] = ((uint32_t)l1 << 16) | l0;
                }
                uint32_t* dh = (uint32_t*)(Chi + (size_t)row*N + col0);
                uint32_t* dl = (uint32_t*)(Clo + (size_t)row*N + col0);
#pragma unroll
                for (int m = 0; m < 16; ++m) { dh[m] = hp[m]; dl[m] = lp[m]; }
            } else {
                float* cp = C + (size_t)row*N + col0;
                if (bias) {
#pragma unroll
                    for (int i = 0; i < 32; ++i) cp[i] = __uint_as_float(r[i]) + bias[col0 + i];
                } else {
#pragma unroll
                    for (int i = 0; i < 32; ++i) cp[i] = __uint_as_float(r[i]);
                }
            }
        }
        TCGEN05_FENCE_BEFORE();
    }
    __syncthreads();
    if (wid == 0) TCGEN05_DEALLOC(tmem, 256);
#endif
}

// ---------------- K / V^T image bake (swizzled SMEM images) -------------------
__global__ void __launch_bounds__(128) kv_image_kernel()
{
    int bh = blockIdx.x;
    int b = bh / NHEADS, h = bh % NHEADS;
    int tid = threadIdx.x;
    char* kh = (char*)(g_kimg_hi + (size_t)bh*96*64);
    char* kl = (char*)(g_kimg_lo + (size_t)bh*96*64);
    char* vh = (char*)(g_vimg_hi + (size_t)bh*64*128);
    char* vl = (char*)(g_vimg_lo + (size_t)bh*64*128);

    for (int u = tid; u < 96*64; u += 128) {
        int j = u >> 6, d = u & 63;
        float f = (j < CTX) ? g_k[(size_t)(b*CTX + j)*INNER + h*DHEAD + d] : 0.f;
        ushort_t hh, ll; bf16split(f, hh, ll);
        uint32_t so = SMEM_SWIZZLE_128B((uint32_t)(j*128 + d*2));
        *(ushort_t*)(kh + so) = hh;
        *(ushort_t*)(kl + so) = ll;
    }
    for (int u = tid; u < 64*128; u += 128) {
        int d = u >> 7, j = u & 127;
        float f = (j < CTX) ? g_v[(size_t)(b*CTX + j)*INNER + h*DHEAD + d] : 0.f;
        ushort_t hh, ll; bf16split(f, hh, ll);
        uint32_t addr = (uint32_t)(((d >> 3) + (j >> 6)*8)*1024 + (d & 7)*128 + (j & 63)*2);
        uint32_t so = SMEM_SWIZZLE_128B(addr);
        *(ushort_t*)(vh + so) = hh;
        *(ushort_t*)(vl + so) = ll;
    }
}

// ---------------- tcgen05 fused masked attention ------------------------------
// ATT_QT=8: 640 CTAs (4.32 waves), KV-image prologue amortized over 8 q-tiles.
#define ATT_QT 8
#define A_QHI 0
#define A_QLO 16384
#define A_KHI 32768
#define A_KLO 45056
#define A_VHI 57344
#define A_VLO 73728
#define A_PHI 90112
#define A_PLO 122880
#define ATTN_SMEM (2048 + 155648)
#define IDESC_S 0x08180490u   // M=128, N=96
#define IDESC_O 0x08100490u   // M=128, N=64

__global__ void __launch_bounds__(128) attn_tc()
{
#if HAS_TCGEN05
    extern __shared__ char smem[];
    const uint32_t sb = smem_to_u32(smem);
    const uint32_t ab = (sb + 1024 + 1023) & ~1023u;
    char* abp = smem + (ab - sb);
    int tid = threadIdx.x, wid = tid >> 5;
    int b = blockIdx.z, h = blockIdx.y, qg = blockIdx.x;
    int bh = b*NHEADS + h;

    if (wid == 0) TCGEN05_ALLOC(sb, 256);
    __syncthreads();
    uint32_t tmem;
    asm volatile("ld.shared.b32 %0, [%1];" : "=r"(tmem) : "r"(sb));
    if (wid == 0) TCGEN05_RELINQ();
    if (tid == 0) { MBARRIER_INIT(sb + 8, 1); MBARRIER_INIT(sb + 16, 1); }
    __syncthreads();

    {
        const uint4* skh = (const uint4*)(g_kimg_hi + (size_t)bh*96*64);
        const uint4* skl = (const uint4*)(g_kimg_lo + (size_t)bh*96*64);
        for (int u = tid; u < 768; u += 128) {
            ((uint4*)(abp + A_KHI))[u] = skh[u];
            ((uint4*)(abp + A_KLO))[u] = skl[u];
        }
        const uint4* svh = (const uint4*)(g_vimg_hi + (size_t)bh*64*128);
        const uint4* svl = (const uint4*)(g_vimg_lo + (size_t)bh*64*128);
        for (int u = tid; u < 1024; u += 128) {
            ((uint4*)(abp + A_VHI))[u] = svh[u];
            ((uint4*)(abp + A_VLO))[u] = svl[u];
        }
    }

    int par0 = 0, par1 = 0;
    for (int qt = 0; qt < ATT_QT; ++qt) {
        int qbase = (qg*ATT_QT + qt)*128;
        size_t qrow = (size_t)(b*NQ + qbase + tid)*INNER + h*DHEAD;
        {
            const uint4* qh = (const uint4*)(g_qhi + qrow);
            const uint4* ql = (const uint4*)(g_qlo + qrow);
#pragma unroll
            for (int v = 0; v < 8; ++v) {
                uint32_t so = SMEM_SWIZZLE_128B((uint32_t)(tid*128 + v*16));
                *(uint4*)(abp + A_QHI + so) = qh[v];
                *(uint4*)(abp + A_QLO + so) = ql[v];
            }
        }
        __syncthreads();
        if (wid == 0 && elect_one_pred()) {
            FENCE_ASYNC();
            uint64_t dqh = MAKE_SMEM_DESC(ab + A_QHI);
            uint64_t dql = MAKE_SMEM_DESC(ab + A_QLO);
            uint64_t dkh = MAKE_SMEM_DESC(ab + A_KHI);
            uint64_t dkl = MAKE_SMEM_DESC(ab + A_KLO);
#pragma unroll
            for (int ks = 0; ks < 4; ++ks)
                mma_f16_ss(tmem, dqh + ks*2, dkh + ks*2, IDESC_S, ks > 0);
#pragma unroll
            for (int ks = 0; ks < 4; ++ks)
                mma_f16_ss(tmem, dqh + ks*2, dkl + ks*2, IDESC_S, true);
#pragma unroll
            for (int ks = 0; ks < 4; ++ks)
                mma_f16_ss(tmem, dql + ks*2, dkh + ks*2, IDESC_S, true);
            TCGEN05_COMMIT(sb + 8);
        }
        MBARRIER_WAIT_PARITY(sb + 8, par0); par0 ^= 1;
        TCGEN05_FENCE_AFTER();

        float s[96];
#pragma unroll
        for (int cb = 0; cb < 3; ++cb) {
            uint32_t rr[32];
            TCGEN05_LD_32X32B_X32(rr, tmem + cb*32);
            TCGEN05_WAIT_LD();
#pragma unroll
            for (int i = 0; i < 32; ++i) s[cb*32 + i] = __uint_as_float(rr[i]);
        }
        TCGEN05_FENCE_BEFORE();
        int fg = g_fg[b*NQ + qbase + tid];
        float mx = -FLT_MAX;
#pragma unroll
        for (int j = 0; j < CTX; ++j) {
            float a = s[j] * 0.125f;
            bool valid = (j < 77) || ((j < 81) ? (fg != 0) : (fg == 0));
            a = valid ? a : -FLT_MAX;
            s[j] = a;
            mx = fmaxf(mx, a);
        }
        float sum = 0.f;
#pragma unroll
        for (int j = 0; j < CTX; ++j) {
            float e = (s[j] > -3.0e38f) ? __expf(s[j] - mx) : 0.f;
            s[j] = e;
            sum += e;
        }
        float inv = 1.f / sum;
#pragma unroll
        for (int j = CTX; j < 96; ++j) s[j] = 0.f;

        {
            int r = tid;
#pragma unroll
            for (int g = 0; g < 16; ++g) {
                int c0 = g*8;
                uint32_t hv[4], lv[4];
#pragma unroll
                for (int pe = 0; pe < 4; ++pe) {
                    int c = c0 + 2*pe;
                    float f0 = (c < 96) ? s[c] : 0.f;
                    float f1 = (c+1 < 96) ? s[c+1] : 0.f;
                    ushort_t h0, l0, h1, l1;
                    bf16split(f0, h0, l0);
                    bf16split(f1, h1, l1);
                    hv[pe] = ((uint32_t)h1 << 16) | h0;
                    lv[pe] = ((uint32_t)l1 << 16) | l0;
                }
                uint32_t addr = (uint32_t)(((r >> 3) + (c0 >> 6)*16)*1024 + (r & 7)*128 + (c0 & 63)*2);
                uint32_t so = SMEM_SWIZZLE_128B(addr);
                *(uint4*)(abp + A_PHI + so) = make_uint4(hv[0], hv[1], hv[2], hv[3]);
                *(uint4*)(abp + A_PLO + so) = make_uint4(lv[0], lv[1], lv[2], lv[3]);
            }
        }
        __syncthreads();
        if (wid == 0 && elect_one_pred()) {
            FENCE_ASYNC();
            uint64_t dph = MAKE_SMEM_DESC(ab + A_PHI);
            uint64_t dpl = MAKE_SMEM_DESC(ab + A_PLO);
            uint64_t dvh = MAKE_SMEM_DESC(ab + A_VHI);
            uint64_t dvl = MAKE_SMEM_DESC(ab + A_VLO);
#pragma unroll
            for (int ks = 0; ks < 8; ++ks) {
                uint64_t aoff = (ks < 4) ? ks*2 : 1024 + (ks-4)*2;
                uint64_t boff = (ks < 4) ? ks*2 : 512 + (ks-4)*2;
                mma_f16_ss(tmem + 96, dph + aoff, dvh + boff, IDESC_O, ks > 0);
            }
#pragma unroll
            for (int ks = 0; ks < 8; ++ks) {
                uint64_t aoff = (ks < 4) ? ks*2 : 1024 + (ks-4)*2;
                uint64_t boff = (ks < 4) ? ks*2 : 512 + (ks-4)*2;
                mma_f16_ss(tmem + 96, dph + aoff, dvl + boff, IDESC_O, true);
            }
#pragma unroll
            for (int ks = 0; ks < 8; ++ks) {
                uint64_t aoff = (ks < 4) ? ks*2 : 1024 + (ks-4)*2;
                uint64_t boff = (ks < 4) ? ks*2 : 512 + (ks-4)*2;
                mma_f16_ss(tmem + 96, dpl + aoff, dvh + boff, IDESC_O, true);
            }
            TCGEN05_COMMIT(sb + 16);
        }
        MBARRIER_WAIT_PARITY(sb + 16, par1); par1 ^= 1;
        TCGEN05_FENCE_AFTER();

        size_t obase = (size_t)(b*NQ + qbase + tid)*INNER + h*DHEAD;
#pragma unroll
        for (int cb = 0; cb < 2; ++cb) {
            uint32_t rr[32];
            TCGEN05_LD_32X32B_X32(rr, tmem + 96 + cb*32);
            TCGEN05_WAIT_LD();
#pragma unroll
            for (int g = 0; g < 4; ++g) {
                uint32_t hv[4], lv[4];
#pragma unroll
                for (int pe = 0; pe < 4; ++pe) {
                    float f0 = __uint_as_float(rr[g*8 + 2*pe])     * inv;
                    float f1 = __uint_as_float(rr[g*8 + 2*pe + 1]) * inv;
                    ushort_t h0, l0, h1, l1;
                    bf16split(f0, h0, l0);
                    bf16split(f1, h1, l1);
                    hv[pe] = ((uint32_t)h1 << 16) | h0;
                    lv[pe] = ((uint32_t)l1 << 16) | l0;
                }
                *(uint4*)(g_ao_hi + obase + cb*32 + g*8) = make_uint4(hv[0], hv[1], hv[2], hv[3]);
                *(uint4*)(g_ao_lo + obase + cb*32 + g*8) = make_uint4(lv[0], lv[1], lv[2], lv[3]);
            }
        }
        TCGEN05_FENCE_BEFORE();
        __syncthreads();
    }
    if (wid == 0) TCGEN05_DEALLOC(tmem, 256);
#endif
}

// ---------------- launch ------------------------------------------------------
extern "C" void kernel_launch(void* const* d_in, const int* in_sizes, int n_in,
                              void* d_out, int out_size)
{
    (void)in_sizes; (void)n_in; (void)out_size;
    const float* x    = (const float*)d_in[0];
    const float* ctxp = (const float*)d_in[1];
    const float* Wq   = (const float*)d_in[2];
    const float* Wk   = (const float*)d_in[3];
    const float* Wv   = (const float*)d_in[4];
    const float* Wo   = (const float*)d_in[5];
    const float* bo   = (const float*)d_in[6];
    const int*   mask = (const int*)d_in[7];
    float* out = (float*)d_out;

    float *k, *v;
    __nv_bfloat16 *qhi, *qlo, *aohi, *aolo;
    __nv_bfloat16 *wqth, *wqtl, *wkth, *wktl, *wvth, *wvtl, *woth, *wotl;
    cudaGetSymbolAddress((void**)&k,    g_k);
    cudaGetSymbolAddress((void**)&v,    g_v);
    cudaGetSymbolAddress((void**)&qhi,  g_qhi);
    cudaGetSymbolAddress((void**)&qlo,  g_qlo);
    cudaGetSymbolAddress((void**)&aohi, g_ao_hi);
    cudaGetSymbolAddress((void**)&aolo, g_ao_lo);
    cudaGetSymbolAddress((void**)&wqth, g_wqt_hi);
    cudaGetSymbolAddress((void**)&wqtl, g_wqt_lo);
    cudaGetSymbolAddress((void**)&wkth, g_wkt_hi);
    cudaGetSymbolAddress((void**)&wktl, g_wkt_lo);
    cudaGetSymbolAddress((void**)&wvth, g_wvt_hi);
    cudaGetSymbolAddress((void**)&wvtl, g_wvt_lo);
    cudaGetSymbolAddress((void**)&woth, g_wot_hi);
    cudaGetSymbolAddress((void**)&wotl, g_wot_lo);

    cudaFuncSetAttribute(gemm_bf16x3, cudaFuncAttributeMaxDynamicSharedMemorySize, G_SMEM);
    cudaFuncSetAttribute(attn_tc, cudaFuncAttributeMaxDynamicSharedMemorySize, ATTN_SMEM);

    dim3 blk(32, 8);

    // Profiler captures launch #4 -> keep the Q GEMM there.
    mask_kernel<<<(BB*NQ + 255)/256, 256>>>(mask);                              // 1
    wtrans_kernel<<<dim3(QD/32, INNER/32), blk>>>(Wq, wqth, wqtl, QD, INNER);   // 2
    wtrans_kernel<<<dim3(INNER/32, QD/32), blk>>>(Wo, woth, wotl, INNER, QD);   // 3

    // 4: Q projection (fp32 A, fused split) -> bf16 hi/lo   [PROFILED]
    gemm_bf16x3<<<dim3(INNER/G_BN, (BB*NQ)/G_BM), 256, G_SMEM>>>(
        x, nullptr, nullptr, wqth, wqtl, nullptr, nullptr, qhi, qlo,
        BB*NQ, INNER, QD);

    // 5,6: remaining weight transposes
    wtrans_kernel<<<dim3(CD/32, INNER/32), blk>>>(Wk, wkth, wktl, CD, INNER);   // 5
    wtrans_kernel<<<dim3(CD/32, INNER/32), blk>>>(Wv, wvth, wvtl, CD, INNER);   // 6

    // 7,8: K, V projections (fp32 ctx A, fused split + pad)
    gemm_bf16x3<<<dim3(INNER/G_BN, MKV/G_BM), 256, G_SMEM>>>(
        ctxp, nullptr, nullptr, wkth, wktl, nullptr, k, nullptr, nullptr,
        BB*CTX, INNER, CD);
    gemm_bf16x3<<<dim3(INNER/G_BN, MKV/G_BM), 256, G_SMEM>>>(
        ctxp, nullptr, nullptr, wvth, wvtl, nullptr, v, nullptr, nullptr,
        BB*CTX, INNER, CD);

    // 9: bake K / V^T swizzled images
    kv_image_kernel<<<NBH, 128>>>();

    // 10: tensor-core masked attention (8 q-tiles per CTA)
    attn_tc<<<dim3(NQ/(ATT_QT*128), NHEADS, BB), 128, ATTN_SMEM>>>();

    // 11: output projection + bias
    gemm_bf16x3<<<dim3(QD/G_BN, (BB*NQ)/G_BM), 256, G_SMEM>>>(
        nullptr, aohi, aolo, woth, wotl, bo, out, nullptr, nullptr,
        BB*NQ, QD, INNER);
}

// round 12
// speedup vs baseline: 1.5376x; 1.0204x over previous
#include <cuda_runtime.h>
#include <cuda_bf16.h>
#include <math.h>
#include <float.h>
#include <stdint.h>

#define BB 8
#define NQ 4096
#define QD 1280
#define CD 1024
#define CTX 85
#define NHEADS 20
#define DHEAD 64
#define INNER (NHEADS*DHEAD)   // 1280
#define MKV 768
#define NBH (BB*NHEADS)        // 160

typedef unsigned short ushort_t;

// ---------------- scratch (static device globals; no allocation) -------------
__device__ float g_k [(size_t)MKV*INNER];
__device__ float g_v [(size_t)MKV*INNER];
__device__ __nv_bfloat16 g_qhi[(size_t)BB*NQ*INNER];
__device__ __nv_bfloat16 g_qlo[(size_t)BB*NQ*INNER];
__device__ __nv_bfloat16 g_ao_hi[(size_t)BB*NQ*INNER];
__device__ __nv_bfloat16 g_ao_lo[(size_t)BB*NQ*INNER];
__device__ __nv_bfloat16 g_wqt_hi[(size_t)INNER*QD];
__device__ __nv_bfloat16 g_wqt_lo[(size_t)INNER*QD];
__device__ __nv_bfloat16 g_wkt_hi[(size_t)INNER*CD];
__device__ __nv_bfloat16 g_wkt_lo[(size_t)INNER*CD];
__device__ __nv_bfloat16 g_wvt_hi[(size_t)INNER*CD];
__device__ __nv_bfloat16 g_wvt_lo[(size_t)INNER*CD];
__device__ __nv_bfloat16 g_wot_hi[(size_t)QD*INNER];
__device__ __nv_bfloat16 g_wot_lo[(size_t)QD*INNER];
__device__ __nv_bfloat16 g_kimg_hi[(size_t)NBH*96*64];
__device__ __nv_bfloat16 g_kimg_lo[(size_t)NBH*96*64];
__device__ __nv_bfloat16 g_vimg_hi[(size_t)NBH*64*128];
__device__ __nv_bfloat16 g_vimg_lo[(size_t)NBH*64*128];
__device__ unsigned char g_fg[BB*NQ];

// ============================ PTX helpers ====================================
__device__ __forceinline__ uint32_t smem_to_u32(const void* p) {
    uint32_t a;
    asm("{ .reg .u64 t; cvta.to.shared.u64 t, %1; cvt.u32.u64 %0, t; }"
        : "=r"(a) : "l"(p));
    return a;
}

#if defined(__CUDA_ARCH_FEAT_SM103_ALL)
#define HAS_TCGEN05 1
#else
#define HAS_TCGEN05 0
#endif

#if HAS_TCGEN05
__device__ __forceinline__ uint32_t elect_one_pred() {
    uint32_t pred;
    asm volatile(
        "{\n\t.reg .pred p;\n\t"
        "elect.sync _|p, 0xFFFFFFFF;\n\t"
        "selp.b32 %0, 1, 0, p;\n\t}"
        : "=r"(pred));
    return pred;
}
#define TCGEN05_ALLOC(sa, n) \
    asm volatile("tcgen05.alloc.cta_group::1.sync.aligned.shared::cta.b32 [%0], %1;" \
        :: "r"((uint32_t)(sa)), "r"((uint32_t)(n)) : "memory")
#define TCGEN05_DEALLOC(t, n) \
    asm volatile("tcgen05.dealloc.cta_group::1.sync.aligned.b32 %0, %1;" :: "r"(t), "r"((uint32_t)(n)))
#define TCGEN05_RELINQ() \
    asm volatile("tcgen05.relinquish_alloc_permit.cta_group::1.sync.aligned;")
#define TCGEN05_COMMIT(mb) \
    asm volatile("tcgen05.commit.cta_group::1.mbarrier::arrive::one.shared::cluster.b64 [%0];" \
        :: "r"((uint32_t)(mb)) : "memory")
#define TCGEN05_FENCE_AFTER() asm volatile("tcgen05.fence::after_thread_sync;" ::: "memory")
#define TCGEN05_FENCE_BEFORE() asm volatile("tcgen05.fence::before_thread_sync;" ::: "memory")
#define TCGEN05_WAIT_LD() asm volatile("tcgen05.wait::ld.sync.aligned;" ::: "memory")
#define FENCE_ASYNC() asm volatile("fence.proxy.async.shared::cta;" ::: "memory")
#define MBARRIER_INIT(mb, c) \
    asm volatile("mbarrier.init.shared.b64 [%0], %1;" :: "r"((uint32_t)(mb)), "r"((uint32_t)(c)) : "memory")
#define MBARRIER_WAIT_PARITY(mb, ph) do { \
    uint32_t _m = (uint32_t)(mb), _p = (uint32_t)(ph), _d; \
    asm volatile("{\n\t.reg .pred p;\n\t" \
        "mbarrier.try_wait.parity.acquire.cta.shared::cta.b64 p, [%1], %2;\n\t" \
        "selp.b32 %0, 1, 0, p;\n\t}" : "=r"(_d) : "r"(_m), "r"(_p) : "memory"); \
    if (!_d) { \
        asm volatile("{\n\t.reg .pred P1;\n\t" \
            "WL_%=:\n\t" \
            "mbarrier.try_wait.parity.acquire.cta.shared::cta.b64 P1, [%0], %1, 0x989680;\n\t" \
            "@P1 bra.uni WD_%=;\n\t" \
            "bra.uni WL_%=;\n\t" \
            "WD_%=:\n\t}" :: "r"(_m), "r"(_p) : "memory"); \
    } \
} while (0)
#define TCGEN05_LD_32X32B_X32(r, ta) \
    asm volatile("tcgen05.ld.sync.aligned.32x32b.x32.b32 " \
        "{%0, %1, %2, %3, %4, %5, %6, %7, %8, %9, %10, %11, %12, %13, %14, %15, " \
        " %16, %17, %18, %19, %20, %21, %22, %23, %24, %25, %26, %27, %28, %29, %30, %31}, [%32];" \
        : "=r"((r)[0]),  "=r"((r)[1]),  "=r"((r)[2]),  "=r"((r)[3]), \
          "=r"((r)[4]),  "=r"((r)[5]),  "=r"((r)[6]),  "=r"((r)[7]), \
          "=r"((r)[8]),  "=r"((r)[9]),  "=r"((r)[10]), "=r"((r)[11]), \
          "=r"((r)[12]), "=r"((r)[13]), "=r"((r)[14]), "=r"((r)[15]), \
          "=r"((r)[16]), "=r"((r)[17]), "=r"((r)[18]), "=r"((r)[19]), \
          "=r"((r)[20]), "=r"((r)[21]), "=r"((r)[22]), "=r"((r)[23]), \
          "=r"((r)[24]), "=r"((r)[25]), "=r"((r)[26]), "=r"((r)[27]), \
          "=r"((r)[28]), "=r"((r)[29]), "=r"((r)[30]), "=r"((r)[31]) \
        : "r"(ta))

__device__ __forceinline__ void mma_f16_ss(uint32_t d_tmem, uint64_t a_desc,
                                           uint64_t b_desc, uint32_t idesc, bool acc)
{
    uint32_t en = acc ? 1u : 0u;
    asm volatile(
        "{\n\t.reg .pred p;\n\t"
        "setp.ne.u32 p, %5, 0;\n\t"
        "tcgen05.mma.cta_group::1.kind::f16 [%0], %1, %2, %3, {%4, %4, %4, %4}, p;\n\t}"
        :: "r"(d_tmem), "l"(a_desc), "l"(b_desc), "r"(idesc), "r"(0u), "r"(en)
        : "memory");
}
#endif // HAS_TCGEN05

static constexpr uint64_t SMEM_DESC_BASE_SW128 =
    (uint64_t(2)  << 61) | (uint64_t(1) << 46) | (uint64_t(64) << 32) | (uint64_t(1) << 16);
#define MAKE_SMEM_DESC(ba) (SMEM_DESC_BASE_SW128 | ((uint64_t)((ba) >> 4) & 0x3FFF))
#define SMEM_SWIZZLE_128B(bo) ((bo) ^ (((bo) >> 3) & 0x70))

__device__ __forceinline__ void bf16split(float f, ushort_t& h, ushort_t& l)
{
    __nv_bfloat16 hh = __float2bfloat16(f);
    __nv_bfloat16 ll = __float2bfloat16(f - __bfloat162float(hh));
    h = __bfloat16_as_ushort(hh);
    l = __bfloat16_as_ushort(ll);
}

// ---------------- mask: exact integer bicubic-threshold ----------------------
__global__ void mask_kernel(const int* __restrict__ mask)
{
    int idx = blockIdx.x * blockDim.x + threadIdx.x;
    if (idx >= BB*NQ) return;
    int b = idx / NQ, n = idx % NQ;
    int o = n >> 6, p = n & 63;
    const int iw[4] = {-3, 19, 19, -3};
    const int* mb = mask + (size_t)b * 256 * 256;
    int acc = 0;
#pragma unroll
    for (int s = 0; s < 4; s++) {
        const int* row = mb + (4*o + s) * 256 + 4*p;
        int rw = iw[s];
#pragma unroll
        for (int t = 0; t < 4; t++) acc += rw * iw[t] * row[t];
    }
    g_fg[idx] = (acc != 0) ? 1 : 0;
}

// ---------------- weight transpose + bf16 split -------------------------------
__global__ void wtrans_kernel(const float* __restrict__ W,
                              __nv_bfloat16* __restrict__ Thi,
                              __nv_bfloat16* __restrict__ Tlo, int K, int N)
{
    __shared__ float t[32][33];
    int k0 = blockIdx.x * 32, n0 = blockIdx.y * 32;
    int tx = threadIdx.x, ty = threadIdx.y;
    for (int r = ty; r < 32; r += 8)
        t[r][tx] = W[(size_t)(k0 + r)*N + n0 + tx];
    __syncthreads();
    for (int r = ty; r < 32; r += 8) {
        float v = t[tx][r];
        ushort_t h, l; bf16split(v, h, l);
        Thi[(size_t)(n0 + r)*K + k0 + tx] = __ushort_as_bfloat16(h);
        Tlo[(size_t)(n0 + r)*K + k0 + tx] = __ushort_as_bfloat16(l);
    }
}

// ================= bf16x3 tcgen05 GEMM: C = A@B^T (+bias) ====================
// BK=64, BM=128, BN=256, double-buffered, register-prefetched with DEFERRED
// conversion: load_chunk issues all 24 LDG.128 back-to-back (MLP=24, no
// dependent consumers); the fp32->bf16 split happens at STS time.
#define G_BM 128
#define G_BN 256
#define G_BK 64
#define G_BUFSZ 98304
#define G_SMEM  (2048 + 2*G_BUFSZ)
#define G_IDESC 0x08400490u   // F32 acc, BF16xBF16, N=256, M=128

__global__ void __launch_bounds__(256)
gemm_bf16x3(const float* __restrict__ Af,
            const __nv_bfloat16* __restrict__ Ahi, const __nv_bfloat16* __restrict__ Alo,
            const __nv_bfloat16* __restrict__ Bhi, const __nv_bfloat16* __restrict__ Blo,
            const float* __restrict__ bias, float* __restrict__ C,
            __nv_bfloat16* __restrict__ Chi, __nv_bfloat16* __restrict__ Clo,
            int Mvalid, int N, int K)
{
#if HAS_TCGEN05
    extern __shared__ char smem[];
    const uint32_t sb = smem_to_u32(smem);
    const uint32_t ab = (sb + 1024 + 1023) & ~1023u;
    char* abp = smem + (ab - sb);
    const int tid = threadIdx.x;
    const int wid = tid >> 5, lane = tid & 31;
    const int brow = blockIdx.y * G_BM;
    const int bcol = blockIdx.x * G_BN;

    if (wid == 0) TCGEN05_ALLOC(sb, 256);
    __syncthreads();
    uint32_t tmem;
    asm volatile("ld.shared.b32 %0, [%1];" : "=r"(tmem) : "r"(sb));
    if (wid == 0) TCGEN05_RELINQ();
    if (tid == 0) { MBARRIER_INIT(sb + 8, 1); MBARRIER_INIT(sb + 16, 1); }
    __syncthreads();

    const int KCH = K / G_BK;
    int par0 = 0, par1 = 0;

    // raw prefetch registers:
    //  fp32 path:  pa0/pa1 = two float4 per row-group (8 floats)
    //  split path: pa0 = Ahi uint4 (8 bf16), pa1 = Alo uint4
    uint4 pa0[4], pa1[4], pbh[8], pbl[8];
    const int a_row = tid >> 3;
    const int a_v   = tid & 7;

    auto load_chunk = [&](int c) {
        const int k0 = c * G_BK;
        if (Af) {
#pragma unroll
            for (int i = 0; i < 4; ++i) {
                int gr = brow + a_row + i*32;
                if (gr < Mvalid) {
                    const uint4* src = (const uint4*)(Af + (size_t)gr*K + k0 + a_v*8);
                    pa0[i] = src[0];
                    pa1[i] = src[1];
                } else {
                    pa0[i] = make_uint4(0u,0u,0u,0u);
                    pa1[i] = make_uint4(0u,0u,0u,0u);
                }
            }
        } else {
#pragma unroll
            for (int i = 0; i < 4; ++i) {
                int gr = brow + a_row + i*32;
                pa0[i] = *(const uint4*)(Ahi + (size_t)gr*K + k0 + a_v*8);
                pa1[i] = *(const uint4*)(Alo + (size_t)gr*K + k0 + a_v*8);
            }
        }
#pragma unroll
        for (int i = 0; i < 8; ++i) {
            int row = a_row + i*32;
            pbh[i] = *(const uint4*)(Bhi + (size_t)(bcol + row)*K + k0 + a_v*8);
            pbl[i] = *(const uint4*)(Blo + (size_t)(bcol + row)*K + k0 + a_v*8);
        }
    };

    load_chunk(0);

    for (int c = 0; c < KCH; ++c) {
        int p = c & 1;
        if (c >= 2) {
            if (p == 0) { MBARRIER_WAIT_PARITY(sb + 8, par0); par0 ^= 1; }
            else        { MBARRIER_WAIT_PARITY(sb + 16, par1); par1 ^= 1; }
        }
        char* base = abp + p * G_BUFSZ;

        // A: convert (fp32 path) or pass through (split path), then STS
#pragma unroll
        for (int i = 0; i < 4; ++i) {
            uint32_t so = SMEM_SWIZZLE_128B((uint32_t)((a_row + i*32)*128 + a_v*16));
            uint4 vh, vl;
            if (Af) {
                const float* f0 = (const float*)&pa0[i];
                const float* f1 = (const float*)&pa1[i];
                float fa[8] = {f0[0], f0[1], f0[2], f0[3], f1[0], f1[1], f1[2], f1[3]};
                uint32_t hw[4], lw[4];
#pragma unroll
                for (int e = 0; e < 4; ++e) {
                    ushort_t h0, l0, h1, l1;
                    bf16split(fa[2*e],   h0, l0);
                    bf16split(fa[2*e+1], h1, l1);
                    hw[e] = ((uint32_t)h1 << 16) | h0;
                    lw[e] = ((uint32_t)l1 << 16) | l0;
                }
                vh = make_uint4(hw[0], hw[1], hw[2], hw[3]);
                vl = make_uint4(lw[0], lw[1], lw[2], lw[3]);
            } else {
                vh = pa0[i];
                vl = pa1[i];
            }
            *(uint4*)(base + so) = vh;
            *(uint4*)(base + 16384 + so) = vl;
        }
#pragma unroll
        for (int i = 0; i < 8; ++i) {
            uint32_t so = SMEM_SWIZZLE_128B((uint32_t)((a_row + i*32)*128 + a_v*16));
            *(uint4*)(base + 32768 + so) = pbh[i];
            *(uint4*)(base + 65536 + so) = pbl[i];
        }
        __syncthreads();

        if (wid == 0 && elect_one_pred()) {
            FENCE_ASYNC();
            uint32_t bu = ab + p * G_BUFSZ;
            uint64_t dah = MAKE_SMEM_DESC(bu);
            uint64_t dal = MAKE_SMEM_DESC(bu + 16384);
            uint64_t dbh = MAKE_SMEM_DESC(bu + 32768);
            uint64_t dbl = MAKE_SMEM_DESC(bu + 65536);
#pragma unroll
            for (int ks = 0; ks < 4; ++ks)
                mma_f16_ss(tmem, dah + ks*2, dbh + ks*2, G_IDESC, !(c == 0 && ks == 0));
#pragma unroll
            for (int ks = 0; ks < 4; ++ks)
                mma_f16_ss(tmem, dah + ks*2, dbl + ks*2, G_IDESC, true);
#pragma unroll
            for (int ks = 0; ks < 4; ++ks)
                mma_f16_ss(tmem, dal + ks*2, dbh + ks*2, G_IDESC, true);
            TCGEN05_COMMIT(sb + 8 + p*8);
        }

        if (c + 1 < KCH) load_chunk(c + 1);
    }
    MBARRIER_WAIT_PARITY(sb + 8, par0);
    MBARRIER_WAIT_PARITY(sb + 16, par1);
    TCGEN05_FENCE_AFTER();

    if (wid < 4) {
        int row = brow + wid*32 + lane;
#pragma unroll
        for (int cb = 0; cb < G_BN/32; ++cb) {
            uint32_t r[32];
            TCGEN05_LD_32X32B_X32(r, tmem + cb*32);
            TCGEN05_WAIT_LD();
            int col0 = bcol + cb*32;
            if (Chi) {
                uint32_t hp[16], lp[16];
#pragma unroll
                for (int m = 0; m < 16; ++m) {
                    ushort_t h0, l0, h1, l1;
                    bf16split(__uint_as_float(r[2*m]),   h0, l0);
                    bf16split(__uint_as_float(r[2*m+1]), h1, l1);
                    hp[m] = ((uint32_t)h1 << 16) | h0;
                    lp[m] = ((uint32_t)l1 << 16) | l0;
                }
                uint32_t* dh = (uint32_t*)(Chi + (size_t)row*N + col0);
                uint32_t* dl = (uint32_t*)(Clo + (size_t)row*N + col0);
#pragma unroll
                for (int m = 0; m < 16; ++m) { dh[m] = hp[m]; dl[m] = lp[m]; }
            } else {
                float* cp = C + (size_t)row*N + col0;
                if (bias) {
#pragma unroll
                    for (int i = 0; i < 32; ++i) cp[i] = __uint_as_float(r[i]) + bias[col0 + i];
                } else {
#pragma unroll
                    for (int i = 0; i < 32; ++i) cp[i] = __uint_as_float(r[i]);
                }
            }
        }
        TCGEN05_FENCE_BEFORE();
    }
    __syncthreads();
    if (wid == 0) TCGEN05_DEALLOC(tmem, 256);
#endif
}

// ---------------- K / V^T image bake (swizzled SMEM images) -------------------
__global__ void __launch_bounds__(128) kv_image_kernel()
{
    int bh = blockIdx.x;
    int b = bh / NHEADS, h = bh % NHEADS;
    int tid = threadIdx.x;
    char* kh = (char*)(g_kimg_hi + (size_t)bh*96*64);
    char* kl = (char*)(g_kimg_lo + (size_t)bh*96*64);
    char* vh = (char*)(g_vimg_hi + (size_t)bh*64*128);
    char* vl = (char*)(g_vimg_lo + (size_t)bh*64*128);

    for (int u = tid; u < 96*64; u += 128) {
        int j = u >> 6, d = u & 63;
        float f = (j < CTX) ? g_k[(size_t)(b*CTX + j)*INNER + h*DHEAD + d] : 0.f;
        ushort_t hh, ll; bf16split(f, hh, ll);
        uint32_t so = SMEM_SWIZZLE_128B((uint32_t)(j*128 + d*2));
        *(ushort_t*)(kh + so) = hh;
        *(ushort_t*)(kl + so) = ll;
    }
    for (int u = tid; u < 64*128; u += 128) {
        int d = u >> 7, j = u & 127;
        float f = (j < CTX) ? g_v[(size_t)(b*CTX + j)*INNER + h*DHEAD + d] : 0.f;
        ushort_t hh, ll; bf16split(f, hh, ll);
        uint32_t addr = (uint32_t)(((d >> 3) + (j >> 6)*8)*1024 + (d & 7)*128 + (j & 63)*2);
        uint32_t so = SMEM_SWIZZLE_128B(addr);
        *(ushort_t*)(vh + so) = hh;
        *(ushort_t*)(vl + so) = ll;
    }
}

// ---------------- tcgen05 fused masked attention ------------------------------
#define ATT_QT 8
#define A_QHI 0
#define A_QLO 16384
#define A_KHI 32768
#define A_KLO 45056
#define A_VHI 57344
#define A_VLO 73728
#define A_PHI 90112
#define A_PLO 122880
#define ATTN_SMEM (2048 + 155648)
#define IDESC_S 0x08180490u   // M=128, N=96
#define IDESC_O 0x08100490u   // M=128, N=64

__global__ void __launch_bounds__(128) attn_tc()
{
#if HAS_TCGEN05
    extern __shared__ char smem[];
    const uint32_t sb = smem_to_u32(smem);
    const uint32_t ab = (sb + 1024 + 1023) & ~1023u;
    char* abp = smem + (ab - sb);
    int tid = threadIdx.x, wid = tid >> 5;
    int b = blockIdx.z, h = blockIdx.y, qg = blockIdx.x;
    int bh = b*NHEADS + h;

    if (wid == 0) TCGEN05_ALLOC(sb, 256);
    __syncthreads();
    uint32_t tmem;
    asm volatile("ld.shared.b32 %0, [%1];" : "=r"(tmem) : "r"(sb));
    if (wid == 0) TCGEN05_RELINQ();
    if (tid == 0) { MBARRIER_INIT(sb + 8, 1); MBARRIER_INIT(sb + 16, 1); }
    __syncthreads();

    {
        const uint4* skh = (const uint4*)(g_kimg_hi + (size_t)bh*96*64);
        const uint4* skl = (const uint4*)(g_kimg_lo + (size_t)bh*96*64);
        for (int u = tid; u < 768; u += 128) {
            ((uint4*)(abp + A_KHI))[u] = skh[u];
            ((uint4*)(abp + A_KLO))[u] = skl[u];
        }
        const uint4* svh = (const uint4*)(g_vimg_hi + (size_t)bh*64*128);
        const uint4* svl = (const uint4*)(g_vimg_lo + (size_t)bh*64*128);
        for (int u = tid; u < 1024; u += 128) {
            ((uint4*)(abp + A_VHI))[u] = svh[u];
            ((uint4*)(abp + A_VLO))[u] = svl[u];
        }
    }

    int par0 = 0, par1 = 0;
    for (int qt = 0; qt < ATT_QT; ++qt) {
        int qbase = (qg*ATT_QT + qt)*128;
        size_t qrow = (size_t)(b*NQ + qbase + tid)*INNER + h*DHEAD;
        {
            const uint4* qh = (const uint4*)(g_qhi + qrow);
            const uint4* ql = (const uint4*)(g_qlo + qrow);
#pragma unroll
            for (int v = 0; v < 8; ++v) {
                uint32_t so = SMEM_SWIZZLE_128B((uint32_t)(tid*128 + v*16));
                *(uint4*)(abp + A_QHI + so) = qh[v];
                *(uint4*)(abp + A_QLO + so) = ql[v];
            }
        }
        __syncthreads();
        if (wid == 0 && elect_one_pred()) {
            FENCE_ASYNC();
            uint64_t dqh = MAKE_SMEM_DESC(ab + A_QHI);
            uint64_t dql = MAKE_SMEM_DESC(ab + A_QLO);
            uint64_t dkh = MAKE_SMEM_DESC(ab + A_KHI);
            uint64_t dkl = MAKE_SMEM_DESC(ab + A_KLO);
#pragma unroll
            for (int ks = 0; ks < 4; ++ks)
                mma_f16_ss(tmem, dqh + ks*2, dkh + ks*2, IDESC_S, ks > 0);
#pragma unroll
            for (int ks = 0; ks < 4; ++ks)
                mma_f16_ss(tmem, dqh + ks*2, dkl + ks*2, IDESC_S, true);
#pragma unroll
            for (int ks = 0; ks < 4; ++ks)
                mma_f16_ss(tmem, dql + ks*2, dkh + ks*2, IDESC_S, true);
            TCGEN05_COMMIT(sb + 8);
        }
        MBARRIER_WAIT_PARITY(sb + 8, par0); par0 ^= 1;
        TCGEN05_FENCE_AFTER();

        float s[96];
#pragma unroll
        for (int cb = 0; cb < 3; ++cb) {
            uint32_t rr[32];
            TCGEN05_LD_32X32B_X32(rr, tmem + cb*32);
            TCGEN05_WAIT_LD();
#pragma unroll
            for (int i = 0; i < 32; ++i) s[cb*32 + i] = __uint_as_float(rr[i]);
        }
        TCGEN05_FENCE_BEFORE();
        int fg = g_fg[b*NQ + qbase + tid];
        float mx = -FLT_MAX;
#pragma unroll
        for (int j = 0; j < CTX; ++j) {
            float a = s[j] * 0.125f;
            bool valid = (j < 77) || ((j < 81) ? (fg != 0) : (fg == 0));
            a = valid ? a : -FLT_MAX;
            s[j] = a;
            mx = fmaxf(mx, a);
        }
        float sum = 0.f;
#pragma unroll
        for (int j = 0; j < CTX; ++j) {
            float e = (s[j] > -3.0e38f) ? __expf(s[j] - mx) : 0.f;
            s[j] = e;
            sum += e;
        }
        float inv = 1.f / sum;
#pragma unroll
        for (int j = CTX; j < 96; ++j) s[j] = 0.f;

        {
            int r = tid;
#pragma unroll
            for (int g = 0; g < 16; ++g) {
                int c0 = g*8;
                uint32_t hv[4], lv[4];
#pragma unroll
                for (int pe = 0; pe < 4; ++pe) {
                    int c = c0 + 2*pe;
                    float f0 = (c < 96) ? s[c] : 0.f;
                    float f1 = (c+1 < 96) ? s[c+1] : 0.f;
                    ushort_t h0, l0, h1, l1;
                    bf16split(f0, h0, l0);
                    bf16split(f1, h1, l1);
                    hv[pe] = ((uint32_t)h1 << 16) | h0;
                    lv[pe] = ((uint32_t)l1 << 16) | l0;
                }
                uint32_t addr = (uint32_t)(((r >> 3) + (c0 >> 6)*16)*1024 + (r & 7)*128 + (c0 & 63)*2);
                uint32_t so = SMEM_SWIZZLE_128B(addr);
                *(uint4*)(abp + A_PHI + so) = make_uint4(hv[0], hv[1], hv[2], hv[3]);
                *(uint4*)(abp + A_PLO + so) = make_uint4(lv[0], lv[1], lv[2], lv[3]);
            }
        }
        __syncthreads();
        if (wid == 0 && elect_one_pred()) {
            FENCE_ASYNC();
            uint64_t dph = MAKE_SMEM_DESC(ab + A_PHI);
            uint64_t dpl = MAKE_SMEM_DESC(ab + A_PLO);
            uint64_t dvh = MAKE_SMEM_DESC(ab + A_VHI);
            uint64_t dvl = MAKE_SMEM_DESC(ab + A_VLO);
#pragma unroll
            for (int ks = 0; ks < 8; ++ks) {
                uint64_t aoff = (ks < 4) ? ks*2 : 1024 + (ks-4)*2;
                uint64_t boff = (ks < 4) ? ks*2 : 512 + (ks-4)*2;
                mma_f16_ss(tmem + 96, dph + aoff, dvh + boff, IDESC_O, ks > 0);
            }
#pragma unroll
            for (int ks = 0; ks < 8; ++ks) {
                uint64_t aoff = (ks < 4) ? ks*2 : 1024 + (ks-4)*2;
                uint64_t boff = (ks < 4) ? ks*2 : 512 + (ks-4)*2;
                mma_f16_ss(tmem + 96, dph + aoff, dvl + boff, IDESC_O, true);
            }
#pragma unroll
            for (int ks = 0; ks < 8; ++ks) {
                uint64_t aoff = (ks < 4) ? ks*2 : 1024 + (ks-4)*2;
                uint64_t boff = (ks < 4) ? ks*2 : 512 + (ks-4)*2;
                mma_f16_ss(tmem + 96, dpl + aoff, dvh + boff, IDESC_O, true);
            }
            TCGEN05_COMMIT(sb + 16);
        }
        MBARRIER_WAIT_PARITY(sb + 16, par1); par1 ^= 1;
        TCGEN05_FENCE_AFTER();

        size_t obase = (size_t)(b*NQ + qbase + tid)*INNER + h*DHEAD;
#pragma unroll
        for (int cb = 0; cb < 2; ++cb) {
            uint32_t rr[32];
            TCGEN05_LD_32X32B_X32(rr, tmem + 96 + cb*32);
            TCGEN05_WAIT_LD();
#pragma unroll
            for (int g = 0; g < 4; ++g) {
                uint32_t hv[4], lv[4];
#pragma unroll
                for (int pe = 0; pe < 4; ++pe) {
                    float f0 = __uint_as_float(rr[g*8 + 2*pe])     * inv;
                    float f1 = __uint_as_float(rr[g*8 + 2*pe + 1]) * inv;
                    ushort_t h0, l0, h1, l1;
                    bf16split(f0, h0, l0);
                    bf16split(f1, h1, l1);
                    hv[pe] = ((uint32_t)h1 << 16) | h0;
                    lv[pe] = ((uint32_t)l1 << 16) | l0;
                }
                *(uint4*)(g_ao_hi + obase + cb*32 + g*8) = make_uint4(hv[0], hv[1], hv[2], hv[3]);
                *(uint4*)(g_ao_lo + obase + cb*32 + g*8) = make_uint4(lv[0], lv[1], lv[2], lv[3]);
            }
        }
        TCGEN05_FENCE_BEFORE();
        __syncthreads();
    }
    if (wid == 0) TCGEN05_DEALLOC(tmem, 256);
#endif
}

// ---------------- launch ------------------------------------------------------
extern "C" void kernel_launch(void* const* d_in, const int* in_sizes, int n_in,
                              void* d_out, int out_size)
{
    (void)in_sizes; (void)n_in; (void)out_size;
    const float* x    = (const float*)d_in[0];
    const float* ctxp = (const float*)d_in[1];
    const float* Wq   = (const float*)d_in[2];
    const float* Wk   = (const float*)d_in[3];
    const float* Wv   = (const float*)d_in[4];
    const float* Wo   = (const float*)d_in[5];
    const float* bo   = (const float*)d_in[6];
    const int*   mask = (const int*)d_in[7];
    float* out = (float*)d_out;

    float *k, *v;
    __nv_bfloat16 *qhi, *qlo, *aohi, *aolo;
    __nv_bfloat16 *wqth, *wqtl, *wkth, *wktl, *wvth, *wvtl, *woth, *wotl;
    cudaGetSymbolAddress((void**)&k,    g_k);
    cudaGetSymbolAddress((void**)&v,    g_v);
    cudaGetSymbolAddress((void**)&qhi,  g_qhi);
    cudaGetSymbolAddress((void**)&qlo,  g_qlo);
    cudaGetSymbolAddress((void**)&aohi, g_ao_hi);
    cudaGetSymbolAddress((void**)&aolo, g_ao_lo);
    cudaGetSymbolAddress((void**)&wqth, g_wqt_hi);
    cudaGetSymbolAddress((void**)&wqtl, g_wqt_lo);
    cudaGetSymbolAddress((void**)&wkth, g_wkt_hi);
    cudaGetSymbolAddress((void**)&wktl, g_wkt_lo);
    cudaGetSymbolAddress((void**)&wvth, g_wvt_hi);
    cudaGetSymbolAddress((void**)&wvtl, g_wvt_lo);
    cudaGetSymbolAddress((void**)&woth, g_wot_hi);
    cudaGetSymbolAddress((void**)&wotl, g_wot_lo);

    cudaFuncSetAttribute(gemm_bf16x3, cudaFuncAttributeMaxDynamicSharedMemorySize, G_SMEM);
    cudaFuncSetAttribute(attn_tc, cudaFuncAttributeMaxDynamicSharedMemorySize, ATTN_SMEM);

    dim3 blk(32, 8);

    // Profiler captures launch #4 -> keep the Q GEMM there.
    mask_kernel<<<(BB*NQ + 255)/256, 256>>>(mask);                              // 1
    wtrans_kernel<<<dim3(QD/32, INNER/32), blk>>>(Wq, wqth, wqtl, QD, INNER);   // 2
    wtrans_kernel<<<dim3(INNER/32, QD/32), blk>>>(Wo, woth, wotl, INNER, QD);   // 3

    // 4: Q projection (fp32 A, deferred-split prefetch) -> bf16 hi/lo [PROFILED]
    gemm_bf16x3<<<dim3(INNER/G_BN, (BB*NQ)/G_BM), 256, G_SMEM>>>(
        x, nullptr, nullptr, wqth, wqtl, nullptr, nullptr, qhi, qlo,
        BB*NQ, INNER, QD);

    // 5,6: remaining weight transposes
    wtrans_kernel<<<dim3(CD/32, INNER/32), blk>>>(Wk, wkth, wktl, CD, INNER);   // 5
    wtrans_kernel<<<dim3(CD/32, INNER/32), blk>>>(Wv, wvth, wvtl, CD, INNER);   // 6

    // 7,8: K, V projections (fp32 ctx A, deferred split + pad)
    gemm_bf16x3<<<dim3(INNER/G_BN, MKV/G_BM), 256, G_SMEM>>>(
        ctxp, nullptr, nullptr, wkth, wktl, nullptr, k, nullptr, nullptr,
        BB*CTX, INNER, CD);
    gemm_bf16x3<<<dim3(INNER/G_BN, MKV/G_BM), 256, G_SMEM>>>(
        ctxp, nullptr, nullptr, wvth, wvtl, nullptr, v, nullptr, nullptr,
        BB*CTX, INNER, CD);

    // 9: bake K / V^T swizzled images
    kv_image_kernel<<<NBH, 128>>>();

    // 10: tensor-core masked attention (8 q-tiles per CTA)
    attn_tc<<<dim3(NQ/(ATT_QT*128), NHEADS, BB), 128, ATTN_SMEM>>>();

    // 11: output projection + bias
    gemm_bf16x3<<<dim3(QD/G_BN, (BB*NQ)/G_BM), 256, G_SMEM>>>(
        nullptr, aohi, aolo, woth, wotl, bo, out, nullptr, nullptr,
        BB*NQ, QD, INNER);
}

// round 13
// speedup vs baseline: 1.6144x; 1.0499x over previous
#include <cuda_runtime.h>
#include <cuda_bf16.h>
#include <math.h>
#include <float.h>
#include <stdint.h>

#define BB 8
#define NQ 4096
#define QD 1280
#define CD 1024
#define CTX 85
#define NHEADS 20
#define DHEAD 64
#define INNER (NHEADS*DHEAD)   // 1280
#define KVN (2*INNER)          // 2560 (merged K|V projection)
#define MKV 768
#define NBH (BB*NHEADS)        // 160

typedef unsigned short ushort_t;

// ---------------- scratch (static device globals; no allocation) -------------
__device__ float g_kv[(size_t)MKV*KVN];              // [row][K(1280) | V(1280)]
__device__ __nv_bfloat16 g_qhi[(size_t)BB*NQ*INNER];
__device__ __nv_bfloat16 g_qlo[(size_t)BB*NQ*INNER];
__device__ __nv_bfloat16 g_ao_hi[(size_t)BB*NQ*INNER];
__device__ __nv_bfloat16 g_ao_lo[(size_t)BB*NQ*INNER];
__device__ __nv_bfloat16 g_wqt_hi[(size_t)INNER*QD];
__device__ __nv_bfloat16 g_wqt_lo[(size_t)INNER*QD];
__device__ __nv_bfloat16 g_wkvt_hi[(size_t)KVN*CD];  // rows 0..1279 Wk^T, 1280.. Wv^T
__device__ __nv_bfloat16 g_wkvt_lo[(size_t)KVN*CD];
__device__ __nv_bfloat16 g_wot_hi[(size_t)QD*INNER];
__device__ __nv_bfloat16 g_wot_lo[(size_t)QD*INNER];
__device__ __nv_bfloat16 g_kimg_hi[(size_t)NBH*96*64];
__device__ __nv_bfloat16 g_kimg_lo[(size_t)NBH*96*64];
__device__ __nv_bfloat16 g_vimg_hi[(size_t)NBH*64*128];
__device__ __nv_bfloat16 g_vimg_lo[(size_t)NBH*64*128];
__device__ unsigned char g_fg[BB*NQ];

// ============================ PTX helpers ====================================
__device__ __forceinline__ uint32_t smem_to_u32(const void* p) {
    uint32_t a;
    asm("{ .reg .u64 t; cvta.to.shared.u64 t, %1; cvt.u32.u64 %0, t; }"
        : "=r"(a) : "l"(p));
    return a;
}

#if defined(__CUDA_ARCH_FEAT_SM103_ALL)
#define HAS_TCGEN05 1
#else
#define HAS_TCGEN05 0
#endif

#if HAS_TCGEN05
__device__ __forceinline__ uint32_t elect_one_pred() {
    uint32_t pred;
    asm volatile(
        "{\n\t.reg .pred p;\n\t"
        "elect.sync _|p, 0xFFFFFFFF;\n\t"
        "selp.b32 %0, 1, 0, p;\n\t}"
        : "=r"(pred));
    return pred;
}
#define TCGEN05_ALLOC(sa, n) \
    asm volatile("tcgen05.alloc.cta_group::1.sync.aligned.shared::cta.b32 [%0], %1;" \
        :: "r"((uint32_t)(sa)), "r"((uint32_t)(n)) : "memory")
#define TCGEN05_DEALLOC(t, n) \
    asm volatile("tcgen05.dealloc.cta_group::1.sync.aligned.b32 %0, %1;" :: "r"(t), "r"((uint32_t)(n)))
#define TCGEN05_RELINQ() \
    asm volatile("tcgen05.relinquish_alloc_permit.cta_group::1.sync.aligned;")
#define TCGEN05_COMMIT(mb) \
    asm volatile("tcgen05.commit.cta_group::1.mbarrier::arrive::one.shared::cluster.b64 [%0];" \
        :: "r"((uint32_t)(mb)) : "memory")
#define TCGEN05_FENCE_AFTER() asm volatile("tcgen05.fence::after_thread_sync;" ::: "memory")
#define TCGEN05_FENCE_BEFORE() asm volatile("tcgen05.fence::before_thread_sync;" ::: "memory")
#define TCGEN05_WAIT_LD() asm volatile("tcgen05.wait::ld.sync.aligned;" ::: "memory")
#define FENCE_ASYNC() asm volatile("fence.proxy.async.shared::cta;" ::: "memory")
#define MBARRIER_INIT(mb, c) \
    asm volatile("mbarrier.init.shared.b64 [%0], %1;" :: "r"((uint32_t)(mb)), "r"((uint32_t)(c)) : "memory")
#define MBARRIER_WAIT_PARITY(mb, ph) do { \
    uint32_t _m = (uint32_t)(mb), _p = (uint32_t)(ph), _d; \
    asm volatile("{\n\t.reg .pred p;\n\t" \
        "mbarrier.try_wait.parity.acquire.cta.shared::cta.b64 p, [%1], %2;\n\t" \
        "selp.b32 %0, 1, 0, p;\n\t}" : "=r"(_d) : "r"(_m), "r"(_p) : "memory"); \
    if (!_d) { \
        asm volatile("{\n\t.reg .pred P1;\n\t" \
            "WL_%=:\n\t" \
            "mbarrier.try_wait.parity.acquire.cta.shared::cta.b64 P1, [%0], %1, 0x989680;\n\t" \
            "@P1 bra.uni WD_%=;\n\t" \
            "bra.uni WL_%=;\n\t" \
            "WD_%=:\n\t}" :: "r"(_m), "r"(_p) : "memory"); \
    } \
} while (0)
#define TCGEN05_LD_32X32B_X32(r, ta) \
    asm volatile("tcgen05.ld.sync.aligned.32x32b.x32.b32 " \
        "{%0, %1, %2, %3, %4, %5, %6, %7, %8, %9, %10, %11, %12, %13, %14, %15, " \
        " %16, %17, %18, %19, %20, %21, %22, %23, %24, %25, %26, %27, %28, %29, %30, %31}, [%32];" \
        : "=r"((r)[0]),  "=r"((r)[1]),  "=r"((r)[2]),  "=r"((r)[3]), \
          "=r"((r)[4]),  "=r"((r)[5]),  "=r"((r)[6]),  "=r"((r)[7]), \
          "=r"((r)[8]),  "=r"((r)[9]),  "=r"((r)[10]), "=r"((r)[11]), \
          "=r"((r)[12]), "=r"((r)[13]), "=r"((r)[14]), "=r"((r)[15]), \
          "=r"((r)[16]), "=r"((r)[17]), "=r"((r)[18]), "=r"((r)[19]), \
          "=r"((r)[20]), "=r"((r)[21]), "=r"((r)[22]), "=r"((r)[23]), \
          "=r"((r)[24]), "=r"((r)[25]), "=r"((r)[26]), "=r"((r)[27]), \
          "=r"((r)[28]), "=r"((r)[29]), "=r"((r)[30]), "=r"((r)[31]) \
        : "r"(ta))

__device__ __forceinline__ void mma_f16_ss(uint32_t d_tmem, uint64_t a_desc,
                                           uint64_t b_desc, uint32_t idesc, bool acc)
{
    uint32_t en = acc ? 1u : 0u;
    asm volatile(
        "{\n\t.reg .pred p;\n\t"
        "setp.ne.u32 p, %5, 0;\n\t"
        "tcgen05.mma.cta_group::1.kind::f16 [%0], %1, %2, %3, {%4, %4, %4, %4}, p;\n\t}"
        :: "r"(d_tmem), "l"(a_desc), "l"(b_desc), "r"(idesc), "r"(0u), "r"(en)
        : "memory");
}
#endif // HAS_TCGEN05

static constexpr uint64_t SMEM_DESC_BASE_SW128 =
    (uint64_t(2)  << 61) | (uint64_t(1) << 46) | (uint64_t(64) << 32) | (uint64_t(1) << 16);
#define MAKE_SMEM_DESC(ba) (SMEM_DESC_BASE_SW128 | ((uint64_t)((ba) >> 4) & 0x3FFF))
#define SMEM_SWIZZLE_128B(bo) ((bo) ^ (((bo) >> 3) & 0x70))

__device__ __forceinline__ void bf16split(float f, ushort_t& h, ushort_t& l)
{
    __nv_bfloat16 hh = __float2bfloat16(f);
    __nv_bfloat16 ll = __float2bfloat16(f - __bfloat162float(hh));
    h = __bfloat16_as_ushort(hh);
    l = __bfloat16_as_ushort(ll);
}

// ---------------- mask: exact integer bicubic-threshold ----------------------
__global__ void mask_kernel(const int* __restrict__ mask)
{
    int idx = blockIdx.x * blockDim.x + threadIdx.x;
    if (idx >= BB*NQ) return;
    int b = idx / NQ, n = idx % NQ;
    int o = n >> 6, p = n & 63;
    const int iw[4] = {-3, 19, 19, -3};
    const int* mb = mask + (size_t)b * 256 * 256;
    int acc = 0;
#pragma unroll
    for (int s = 0; s < 4; s++) {
        const int* row = mb + (4*o + s) * 256 + 4*p;
        int rw = iw[s];
#pragma unroll
        for (int t = 0; t < 4; t++) acc += rw * iw[t] * row[t];
    }
    g_fg[idx] = (acc != 0) ? 1 : 0;
}

// ---------------- weight transpose + bf16 split -------------------------------
__global__ void wtrans_kernel(const float* __restrict__ W,
                              __nv_bfloat16* __restrict__ Thi,
                              __nv_bfloat16* __restrict__ Tlo, int K, int N)
{
    __shared__ float t[32][33];
    int k0 = blockIdx.x * 32, n0 = blockIdx.y * 32;
    int tx = threadIdx.x, ty = threadIdx.y;
    for (int r = ty; r < 32; r += 8)
        t[r][tx] = W[(size_t)(k0 + r)*N + n0 + tx];
    __syncthreads();
    for (int r = ty; r < 32; r += 8) {
        float v = t[tx][r];
        ushort_t h, l; bf16split(v, h, l);
        Thi[(size_t)(n0 + r)*K + k0 + tx] = __ushort_as_bfloat16(h);
        Tlo[(size_t)(n0 + r)*K + k0 + tx] = __ushort_as_bfloat16(l);
    }
}

// ================= bf16x3 tcgen05 GEMM: C = A@B^T (+bias) ====================
// BK=64, BM=128, BN=256, double-buffered, register-prefetch with deferred
// fp32->bf16 conversion (R12 config — best).
#define G_BM 128
#define G_BN 256
#define G_BK 64
#define G_BUFSZ 98304
#define G_SMEM  (2048 + 2*G_BUFSZ)
#define G_IDESC 0x08400490u   // F32 acc, BF16xBF16, N=256, M=128

__global__ void __launch_bounds__(256)
gemm_bf16x3(const float* __restrict__ Af,
            const __nv_bfloat16* __restrict__ Ahi, const __nv_bfloat16* __restrict__ Alo,
            const __nv_bfloat16* __restrict__ Bhi, const __nv_bfloat16* __restrict__ Blo,
            const float* __restrict__ bias, float* __restrict__ C,
            __nv_bfloat16* __restrict__ Chi, __nv_bfloat16* __restrict__ Clo,
            int Mvalid, int N, int K)
{
#if HAS_TCGEN05
    extern __shared__ char smem[];
    const uint32_t sb = smem_to_u32(smem);
    const uint32_t ab = (sb + 1024 + 1023) & ~1023u;
    char* abp = smem + (ab - sb);
    const int tid = threadIdx.x;
    const int wid = tid >> 5, lane = tid & 31;
    const int brow = blockIdx.y * G_BM;
    const int bcol = blockIdx.x * G_BN;

    if (wid == 0) TCGEN05_ALLOC(sb, 256);
    __syncthreads();
    uint32_t tmem;
    asm volatile("ld.shared.b32 %0, [%1];" : "=r"(tmem) : "r"(sb));
    if (wid == 0) TCGEN05_RELINQ();
    if (tid == 0) { MBARRIER_INIT(sb + 8, 1); MBARRIER_INIT(sb + 16, 1); }
    __syncthreads();

    const int KCH = K / G_BK;
    int par0 = 0, par1 = 0;

    uint4 pa0[4], pa1[4], pbh[8], pbl[8];
    const int a_row = tid >> 3;
    const int a_v   = tid & 7;

    auto load_chunk = [&](int c) {
        const int k0 = c * G_BK;
        if (Af) {
#pragma unroll
            for (int i = 0; i < 4; ++i) {
                int gr = brow + a_row + i*32;
                if (gr < Mvalid) {
                    const uint4* src = (const uint4*)(Af + (size_t)gr*K + k0 + a_v*8);
                    pa0[i] = src[0];
                    pa1[i] = src[1];
                } else {
                    pa0[i] = make_uint4(0u,0u,0u,0u);
                    pa1[i] = make_uint4(0u,0u,0u,0u);
                }
            }
        } else {
#pragma unroll
            for (int i = 0; i < 4; ++i) {
                int gr = brow + a_row + i*32;
                pa0[i] = *(const uint4*)(Ahi + (size_t)gr*K + k0 + a_v*8);
                pa1[i] = *(const uint4*)(Alo + (size_t)gr*K + k0 + a_v*8);
            }
        }
#pragma unroll
        for (int i = 0; i < 8; ++i) {
            int row = a_row + i*32;
            pbh[i] = *(const uint4*)(Bhi + (size_t)(bcol + row)*K + k0 + a_v*8);
            pbl[i] = *(const uint4*)(Blo + (size_t)(bcol + row)*K + k0 + a_v*8);
        }
    };

    load_chunk(0);

    for (int c = 0; c < KCH; ++c) {
        int p = c & 1;
        if (c >= 2) {
            if (p == 0) { MBARRIER_WAIT_PARITY(sb + 8, par0); par0 ^= 1; }
            else        { MBARRIER_WAIT_PARITY(sb + 16, par1); par1 ^= 1; }
        }
        char* base = abp + p * G_BUFSZ;

#pragma unroll
        for (int i = 0; i < 4; ++i) {
            uint32_t so = SMEM_SWIZZLE_128B((uint32_t)((a_row + i*32)*128 + a_v*16));
            uint4 vh, vl;
            if (Af) {
                const float* f0 = (const float*)&pa0[i];
                const float* f1 = (const float*)&pa1[i];
                float fa[8] = {f0[0], f0[1], f0[2], f0[3], f1[0], f1[1], f1[2], f1[3]};
                uint32_t hw[4], lw[4];
#pragma unroll
                for (int e = 0; e < 4; ++e) {
                    ushort_t h0, l0, h1, l1;
                    bf16split(fa[2*e],   h0, l0);
                    bf16split(fa[2*e+1], h1, l1);
                    hw[e] = ((uint32_t)h1 << 16) | h0;
                    lw[e] = ((uint32_t)l1 << 16) | l0;
                }
                vh = make_uint4(hw[0], hw[1], hw[2], hw[3]);
                vl = make_uint4(lw[0], lw[1], lw[2], lw[3]);
            } else {
                vh = pa0[i];
                vl = pa1[i];
            }
            *(uint4*)(base + so) = vh;
            *(uint4*)(base + 16384 + so) = vl;
        }
#pragma unroll
        for (int i = 0; i < 8; ++i) {
            uint32_t so = SMEM_SWIZZLE_128B((uint32_t)((a_row + i*32)*128 + a_v*16));
            *(uint4*)(base + 32768 + so) = pbh[i];
            *(uint4*)(base + 65536 + so) = pbl[i];
        }
        __syncthreads();

        if (wid == 0 && elect_one_pred()) {
            FENCE_ASYNC();
            uint32_t bu = ab + p * G_BUFSZ;
            uint64_t dah = MAKE_SMEM_DESC(bu);
            uint64_t dal = MAKE_SMEM_DESC(bu + 16384);
            uint64_t dbh = MAKE_SMEM_DESC(bu + 32768);
            uint64_t dbl = MAKE_SMEM_DESC(bu + 65536);
#pragma unroll
            for (int ks = 0; ks < 4; ++ks)
                mma_f16_ss(tmem, dah + ks*2, dbh + ks*2, G_IDESC, !(c == 0 && ks == 0));
#pragma unroll
            for (int ks = 0; ks < 4; ++ks)
                mma_f16_ss(tmem, dah + ks*2, dbl + ks*2, G_IDESC, true);
#pragma unroll
            for (int ks = 0; ks < 4; ++ks)
                mma_f16_ss(tmem, dal + ks*2, dbh + ks*2, G_IDESC, true);
            TCGEN05_COMMIT(sb + 8 + p*8);
        }

        if (c + 1 < KCH) load_chunk(c + 1);
    }
    MBARRIER_WAIT_PARITY(sb + 8, par0);
    MBARRIER_WAIT_PARITY(sb + 16, par1);
    TCGEN05_FENCE_AFTER();

    if (wid < 4) {
        int row = brow + wid*32 + lane;
#pragma unroll
        for (int cb = 0; cb < G_BN/32; ++cb) {
            uint32_t r[32];
            TCGEN05_LD_32X32B_X32(r, tmem + cb*32);
            TCGEN05_WAIT_LD();
            int col0 = bcol + cb*32;
            if (Chi) {
                uint32_t hp[16], lp[16];
#pragma unroll
                for (int m = 0; m < 16; ++m) {
                    ushort_t h0, l0, h1, l1;
                    bf16split(__uint_as_float(r[2*m]),   h0, l0);
                    bf16split(__uint_as_float(r[2*m+1]), h1, l1);
                    hp[m] = ((uint32_t)h1 << 16) | h0;
                    lp[m] = ((uint32_t)l1 << 16) | l0;
                }
                uint32_t* dh = (uint32_t*)(Chi + (size_t)row*N + col0);
                uint32_t* dl = (uint32_t*)(Clo + (size_t)row*N + col0);
#pragma unroll
                for (int m = 0; m < 16; ++m) { dh[m] = hp[m]; dl[m] = lp[m]; }
            } else {
                float* cp = C + (size_t)row*N + col0;
                if (bias) {
#pragma unroll
                    for (int i = 0; i < 32; ++i) cp[i] = __uint_as_float(r[i]) + bias[col0 + i];
                } else {
#pragma unroll
                    for (int i = 0; i < 32; ++i) cp[i] = __uint_as_float(r[i]);
                }
            }
        }
        TCGEN05_FENCE_BEFORE();
    }
    __syncthreads();
    if (wid == 0) TCGEN05_DEALLOC(tmem, 256);
#endif
}

// ---------------- K / V^T image bake (from merged g_kv) -----------------------
__global__ void __launch_bounds__(128) kv_image_kernel()
{
    int bh = blockIdx.x;
    int b = bh / NHEADS, h = bh % NHEADS;
    int tid = threadIdx.x;
    char* kh = (char*)(g_kimg_hi + (size_t)bh*96*64);
    char* kl = (char*)(g_kimg_lo + (size_t)bh*96*64);
    char* vh = (char*)(g_vimg_hi + (size_t)bh*64*128);
    char* vl = (char*)(g_vimg_lo + (size_t)bh*64*128);

    for (int u = tid; u < 96*64; u += 128) {
        int j = u >> 6, d = u & 63;
        float f = (j < CTX) ? g_kv[(size_t)(b*CTX + j)*KVN + h*DHEAD + d] : 0.f;
        ushort_t hh, ll; bf16split(f, hh, ll);
        uint32_t so = SMEM_SWIZZLE_128B((uint32_t)(j*128 + d*2));
        *(ushort_t*)(kh + so) = hh;
        *(ushort_t*)(kl + so) = ll;
    }
    for (int u = tid; u < 64*128; u += 128) {
        int d = u >> 7, j = u & 127;
        float f = (j < CTX) ? g_kv[(size_t)(b*CTX + j)*KVN + INNER + h*DHEAD + d] : 0.f;
        ushort_t hh, ll; bf16split(f, hh, ll);
        uint32_t addr = (uint32_t)(((d >> 3) + (j >> 6)*8)*1024 + (d & 7)*128 + (j & 63)*2);
        uint32_t so = SMEM_SWIZZLE_128B(addr);
        *(ushort_t*)(vh + so) = hh;
        *(ushort_t*)(vl + so) = ll;
    }
}

// ---------------- tcgen05 fused masked attention (R5 pipelined) ---------------
// grid (4, 20, 8): 8 q-tiles of 128 per CTA, 128 threads.
#define ATT_QT 8
#define A_KHI 0
#define A_KLO 12288
#define A_VHI 24576
#define A_VLO 40960
#define A_Q0  57344        // +(t&1)*32768; hi at +0, lo at +16384
#define A_PHI 122880
#define A_PLO 155648
#define ATTN_SMEM (2048 + 188416)
#define IDESC_S 0x08180490u   // M=128, N=96
#define IDESC_O 0x08100490u   // M=128, N=64
// TMEM: S(t) at (t&1)*96 ; O(t) at 192 + (t&1)*64

#if HAS_TCGEN05
__device__ __forceinline__ void attn_issue_S(uint32_t tmem, uint32_t ab, int t)
{
    uint32_t qb = ab + A_Q0 + (uint32_t)(t & 1)*32768;
    uint64_t dqh = MAKE_SMEM_DESC(qb);
    uint64_t dql = MAKE_SMEM_DESC(qb + 16384);
    uint64_t dkh = MAKE_SMEM_DESC(ab + A_KHI);
    uint64_t dkl = MAKE_SMEM_DESC(ab + A_KLO);
    uint32_t dst = tmem + (uint32_t)(t & 1)*96;
#pragma unroll
    for (int ks = 0; ks < 4; ++ks)
        mma_f16_ss(dst, dqh + ks*2, dkh + ks*2, IDESC_S, ks > 0);
#pragma unroll
    for (int ks = 0; ks < 4; ++ks)
        mma_f16_ss(dst, dqh + ks*2, dkl + ks*2, IDESC_S, true);
#pragma unroll
    for (int ks = 0; ks < 4; ++ks)
        mma_f16_ss(dst, dql + ks*2, dkh + ks*2, IDESC_S, true);
}

__device__ __forceinline__ void attn_issue_O(uint32_t tmem, uint32_t ab, int t)
{
    uint64_t dph = MAKE_SMEM_DESC(ab + A_PHI);
    uint64_t dpl = MAKE_SMEM_DESC(ab + A_PLO);
    uint64_t dvh = MAKE_SMEM_DESC(ab + A_VHI);
    uint64_t dvl = MAKE_SMEM_DESC(ab + A_VLO);
    uint32_t dst = tmem + 192 + (uint32_t)(t & 1)*64;
#pragma unroll
    for (int ks = 0; ks < 8; ++ks) {
        uint64_t aoff = (ks < 4) ? ks*2 : 1024 + (ks-4)*2;
        uint64_t boff = (ks < 4) ? ks*2 : 512 + (ks-4)*2;
        mma_f16_ss(dst, dph + aoff, dvh + boff, IDESC_O, ks > 0);
    }
#pragma unroll
    for (int ks = 0; ks < 8; ++ks) {
        uint64_t aoff = (ks < 4) ? ks*2 : 1024 + (ks-4)*2;
        uint64_t boff = (ks < 4) ? ks*2 : 512 + (ks-4)*2;
        mma_f16_ss(dst, dph + aoff, dvl + boff, IDESC_O, true);
    }
#pragma unroll
    for (int ks = 0; ks < 8; ++ks) {
        uint64_t aoff = (ks < 4) ? ks*2 : 1024 + (ks-4)*2;
        uint64_t boff = (ks < 4) ? ks*2 : 512 + (ks-4)*2;
        mma_f16_ss(dst, dpl + aoff, dvh + boff, IDESC_O, true);
    }
}
#endif

__global__ void __launch_bounds__(128) attn_tc()
{
#if HAS_TCGEN05
    extern __shared__ char smem[];
    const uint32_t sb = smem_to_u32(smem);
    const uint32_t ab = (sb + 1024 + 1023) & ~1023u;
    char* abp = smem + (ab - sb);
    int tid = threadIdx.x, wid = tid >> 5;
    int b = blockIdx.z, h = blockIdx.y, qg = blockIdx.x;
    int bh = b*NHEADS + h;

    if (wid == 0) TCGEN05_ALLOC(sb, 512);
    __syncthreads();
    uint32_t tmem;
    asm volatile("ld.shared.b32 %0, [%1];" : "=r"(tmem) : "r"(sb));
    if (wid == 0) TCGEN05_RELINQ();
    if (tid == 0) { MBARRIER_INIT(sb + 8, 1); MBARRIER_INIT(sb + 16, 1); }
    __syncthreads();

    // K / V^T images (swizzle baked in)
    {
        const uint4* skh = (const uint4*)(g_kimg_hi + (size_t)bh*96*64);
        const uint4* skl = (const uint4*)(g_kimg_lo + (size_t)bh*96*64);
        for (int u = tid; u < 768; u += 128) {
            ((uint4*)(abp + A_KHI))[u] = skh[u];
            ((uint4*)(abp + A_KLO))[u] = skl[u];
        }
        const uint4* svh = (const uint4*)(g_vimg_hi + (size_t)bh*64*128);
        const uint4* svl = (const uint4*)(g_vimg_lo + (size_t)bh*64*128);
        for (int u = tid; u < 1024; u += 128) {
            ((uint4*)(abp + A_VHI))[u] = svh[u];
            ((uint4*)(abp + A_VLO))[u] = svl[u];
        }
    }
    // Q(0)
    {
        int qbase = qg*ATT_QT*128;
        size_t qrow = (size_t)(b*NQ + qbase + tid)*INNER + h*DHEAD;
        const uint4* qh = (const uint4*)(g_qhi + qrow);
        const uint4* ql = (const uint4*)(g_qlo + qrow);
#pragma unroll
        for (int v = 0; v < 8; ++v) {
            uint32_t so = SMEM_SWIZZLE_128B((uint32_t)(tid*128 + v*16));
            *(uint4*)(abp + A_Q0 + so) = qh[v];
            *(uint4*)(abp + A_Q0 + 16384 + so) = ql[v];
        }
    }
    __syncthreads();
    if (wid == 0 && elect_one_pred()) {
        FENCE_ASYNC();
        attn_issue_S(tmem, ab, 0);
        TCGEN05_COMMIT(sb + 8);
    }

    int ps = 0, po = 0;
    float inv_prev = 0.f;

    for (int t = 0; t < ATT_QT; ++t) {
        int qbase = (qg*ATT_QT + t)*128;

        // S(t) ready
        MBARRIER_WAIT_PARITY(sb + 8, ps); ps ^= 1;
        TCGEN05_FENCE_AFTER();
        float s[96];
#pragma unroll
        for (int cb = 0; cb < 3; ++cb) {
            uint32_t rr[32];
            TCGEN05_LD_32X32B_X32(rr, tmem + (t & 1)*96 + cb*32);
            TCGEN05_WAIT_LD();
#pragma unroll
            for (int i = 0; i < 32; ++i) s[cb*32 + i] = __uint_as_float(rr[i]);
        }
        TCGEN05_FENCE_BEFORE();

        // prefetch Q(t+1) into buf (t+1)&1, issue S(t+1)
        if (t + 1 < ATT_QT) {
            size_t qrow = (size_t)(b*NQ + qbase + 128 + tid)*INNER + h*DHEAD;
            const uint4* qh = (const uint4*)(g_qhi + qrow);
            const uint4* ql = (const uint4*)(g_qlo + qrow);
            uint32_t qoff = A_Q0 + (uint32_t)((t + 1) & 1)*32768;
#pragma unroll
            for (int v = 0; v < 8; ++v) {
                uint32_t so = SMEM_SWIZZLE_128B((uint32_t)(tid*128 + v*16));
                *(uint4*)(abp + qoff + so) = qh[v];
                *(uint4*)(abp + qoff + 16384 + so) = ql[v];
            }
            __syncthreads();
            if (wid == 0 && elect_one_pred()) {
                FENCE_ASYNC();
                attn_issue_S(tmem, ab, t + 1);
                TCGEN05_COMMIT(sb + 8);
            }
        }

        // softmax
        int fg = g_fg[b*NQ + qbase + tid];
        float mx = -FLT_MAX;
#pragma unroll
        for (int j = 0; j < CTX; ++j) {
            float a = s[j] * 0.125f;
            bool valid = (j < 77) || ((j < 81) ? (fg != 0) : (fg == 0));
            a = valid ? a : -FLT_MAX;
            s[j] = a;
            mx = fmaxf(mx, a);
        }
        float sum = 0.f;
#pragma unroll
        for (int j = 0; j < CTX; ++j) {
            float e = (s[j] > -3.0e38f) ? __expf(s[j] - mx) : 0.f;
            s[j] = e;
            sum += e;
        }
        float inv = 1.f / sum;
#pragma unroll
        for (int j = CTX; j < 96; ++j) s[j] = 0.f;

        // O(t-1) done -> read out
        if (t >= 1) {
            MBARRIER_WAIT_PARITY(sb + 16, po); po ^= 1;
            TCGEN05_FENCE_AFTER();
            size_t obase = (size_t)(b*NQ + qbase - 128 + tid)*INNER + h*DHEAD;
#pragma unroll
            for (int cb = 0; cb < 2; ++cb) {
                uint32_t rr[32];
                TCGEN05_LD_32X32B_X32(rr, tmem + 192 + ((t - 1) & 1)*64 + cb*32);
                TCGEN05_WAIT_LD();
#pragma unroll
                for (int g = 0; g < 4; ++g) {
                    uint32_t hv[4], lv[4];
#pragma unroll
                    for (int pe = 0; pe < 4; ++pe) {
                        float f0 = __uint_as_float(rr[g*8 + 2*pe])     * inv_prev;
                        float f1 = __uint_as_float(rr[g*8 + 2*pe + 1]) * inv_prev;
                        ushort_t h0, l0, h1, l1;
                        bf16split(f0, h0, l0);
                        bf16split(f1, h1, l1);
                        hv[pe] = ((uint32_t)h1 << 16) | h0;
                        lv[pe] = ((uint32_t)l1 << 16) | l0;
                    }
                    *(uint4*)(g_ao_hi + obase + cb*32 + g*8) = make_uint4(hv[0], hv[1], hv[2], hv[3]);
                    *(uint4*)(g_ao_lo + obase + cb*32 + g*8) = make_uint4(lv[0], lv[1], lv[2], lv[3]);
                }
            }
            TCGEN05_FENCE_BEFORE();
        }

        // store P(t), issue O(t)
        {
            int r = tid;
#pragma unroll
            for (int g = 0; g < 16; ++g) {
                int c0 = g*8;
                uint32_t hv[4], lv[4];
#pragma unroll
                for (int pe = 0; pe < 4; ++pe) {
                    int c = c0 + 2*pe;
                    float f0 = (c < 96) ? s[c] : 0.f;
                    float f1 = (c+1 < 96) ? s[c+1] : 0.f;
                    ushort_t h0, l0, h1, l1;
                    bf16split(f0, h0, l0);
                    bf16split(f1, h1, l1);
                    hv[pe] = ((uint32_t)h1 << 16) | h0;
                    lv[pe] = ((uint32_t)l1 << 16) | l0;
                }
                uint32_t addr = (uint32_t)(((r >> 3) + (c0 >> 6)*16)*1024 + (r & 7)*128 + (c0 & 63)*2);
                uint32_t so = SMEM_SWIZZLE_128B(addr);
                *(uint4*)(abp + A_PHI + so) = make_uint4(hv[0], hv[1], hv[2], hv[3]);
                *(uint4*)(abp + A_PLO + so) = make_uint4(lv[0], lv[1], lv[2], lv[3]);
            }
        }
        __syncthreads();
        if (wid == 0 && elect_one_pred()) {
            FENCE_ASYNC();
            attn_issue_O(tmem, ab, t);
            TCGEN05_COMMIT(sb + 16);
        }
        inv_prev = inv;
    }

    // final O readout
    MBARRIER_WAIT_PARITY(sb + 16, po);
    TCGEN05_FENCE_AFTER();
    {
        int qbase = (qg*ATT_QT + ATT_QT - 1)*128;
        size_t obase = (size_t)(b*NQ + qbase + tid)*INNER + h*DHEAD;
#pragma unroll
        for (int cb = 0; cb < 2; ++cb) {
            uint32_t rr[32];
            TCGEN05_LD_32X32B_X32(rr, tmem + 192 + ((ATT_QT - 1) & 1)*64 + cb*32);
            TCGEN05_WAIT_LD();
#pragma unroll
            for (int g = 0; g < 4; ++g) {
                uint32_t hv[4], lv[4];
#pragma unroll
                for (int pe = 0; pe < 4; ++pe) {
                    float f0 = __uint_as_float(rr[g*8 + 2*pe])     * inv_prev;
                    float f1 = __uint_as_float(rr[g*8 + 2*pe + 1]) * inv_prev;
                    ushort_t h0, l0, h1, l1;
                    bf16split(f0, h0, l0);
                    bf16split(f1, h1, l1);
                    hv[pe] = ((uint32_t)h1 << 16) | h0;
                    lv[pe] = ((uint32_t)l1 << 16) | l0;
                }
                *(uint4*)(g_ao_hi + obase + cb*32 + g*8) = make_uint4(hv[0], hv[1], hv[2], hv[3]);
                *(uint4*)(g_ao_lo + obase + cb*32 + g*8) = make_uint4(lv[0], lv[1], lv[2], lv[3]);
            }
        }
        TCGEN05_FENCE_BEFORE();
    }
    __syncthreads();
    if (wid == 0) TCGEN05_DEALLOC(tmem, 512);
#endif
}

// ---------------- launch ------------------------------------------------------
extern "C" void kernel_launch(void* const* d_in, const int* in_sizes, int n_in,
                              void* d_out, int out_size)
{
    (void)in_sizes; (void)n_in; (void)out_size;
    const float* x    = (const float*)d_in[0];
    const float* ctxp = (const float*)d_in[1];
    const float* Wq   = (const float*)d_in[2];
    const float* Wk   = (const float*)d_in[3];
    const float* Wv   = (const float*)d_in[4];
    const float* Wo   = (const float*)d_in[5];
    const float* bo   = (const float*)d_in[6];
    const int*   mask = (const int*)d_in[7];
    float* out = (float*)d_out;

    float *kv;
    __nv_bfloat16 *qhi, *qlo, *aohi, *aolo;
    __nv_bfloat16 *wqth, *wqtl, *wkvth, *wkvtl, *woth, *wotl;
    cudaGetSymbolAddress((void**)&kv,    g_kv);
    cudaGetSymbolAddress((void**)&qhi,   g_qhi);
    cudaGetSymbolAddress((void**)&qlo,   g_qlo);
    cudaGetSymbolAddress((void**)&aohi,  g_ao_hi);
    cudaGetSymbolAddress((void**)&aolo,  g_ao_lo);
    cudaGetSymbolAddress((void**)&wqth,  g_wqt_hi);
    cudaGetSymbolAddress((void**)&wqtl,  g_wqt_lo);
    cudaGetSymbolAddress((void**)&wkvth, g_wkvt_hi);
    cudaGetSymbolAddress((void**)&wkvtl, g_wkvt_lo);
    cudaGetSymbolAddress((void**)&woth,  g_wot_hi);
    cudaGetSymbolAddress((void**)&wotl,  g_wot_lo);

    cudaFuncSetAttribute(gemm_bf16x3, cudaFuncAttributeMaxDynamicSharedMemorySize, G_SMEM);
    cudaFuncSetAttribute(attn_tc, cudaFuncAttributeMaxDynamicSharedMemorySize, ATTN_SMEM);

    dim3 blk(32, 8);

    // Profiler captures launch #4 -> keep the Q GEMM there.
    mask_kernel<<<(BB*NQ + 255)/256, 256>>>(mask);                              // 1
    wtrans_kernel<<<dim3(QD/32, INNER/32), blk>>>(Wq, wqth, wqtl, QD, INNER);   // 2
    wtrans_kernel<<<dim3(INNER/32, QD/32), blk>>>(Wo, woth, wotl, INNER, QD);   // 3

    // 4: Q projection (fp32 A, deferred-split prefetch) -> bf16 hi/lo [PROFILED]
    gemm_bf16x3<<<dim3(INNER/G_BN, (BB*NQ)/G_BM), 256, G_SMEM>>>(
        x, nullptr, nullptr, wqth, wqtl, nullptr, nullptr, qhi, qlo,
        BB*NQ, INNER, QD);

    // 5,6: K and V weight transposes into merged [Wk|Wv]^T
    wtrans_kernel<<<dim3(CD/32, INNER/32), blk>>>(Wk, wkvth, wkvtl, CD, INNER);
    wtrans_kernel<<<dim3(CD/32, INNER/32), blk>>>(
        Wv, wkvth + (size_t)INNER*CD, wkvtl + (size_t)INNER*CD, CD, INNER);

    // 7: merged K|V projection: [768,1024] x [1024,2560] -> fp32 g_kv
    gemm_bf16x3<<<dim3(KVN/G_BN, MKV/G_BM), 256, G_SMEM>>>(
        ctxp, nullptr, nullptr, wkvth, wkvtl, nullptr, kv, nullptr, nullptr,
        BB*CTX, KVN, CD);

    // 8: bake K / V^T swizzled images
    kv_image_kernel<<<NBH, 128>>>();

    // 9: pipelined tensor-core masked attention
    attn_tc<<<dim3(NQ/(ATT_QT*128), NHEADS, BB), 128, ATTN_SMEM>>>();

    // 10: output projection + bias
    gemm_bf16x3<<<dim3(QD/G_BN, (BB*NQ)/G_BM), 256, G_SMEM>>>(
        nullptr, aohi, aolo, woth, wotl, bo, out, nullptr, nullptr,
        BB*NQ, QD, INNER);
}

// round 14
// speedup vs baseline: 1.6823x; 1.0421x over previous
#include <cuda_runtime.h>
#include <cuda_bf16.h>
#include <math.h>
#include <float.h>
#include <stdint.h>

#define BB 8
#define NQ 4096
#define QD 1280
#define CD 1024
#define CTX 85
#define NHEADS 20
#define DHEAD 64
#define INNER (NHEADS*DHEAD)   // 1280
#define KVN (2*INNER)          // 2560 (merged K|V projection)
#define MKV 768
#define NBH (BB*NHEADS)        // 160

typedef unsigned short ushort_t;

// ---------------- scratch (static device globals; no allocation) -------------
__device__ float g_kv[(size_t)MKV*KVN];              // [row][K(1280) | V(1280)]
__device__ __nv_bfloat16 g_qhi[(size_t)BB*NQ*INNER];
__device__ __nv_bfloat16 g_qlo[(size_t)BB*NQ*INNER];
__device__ __nv_bfloat16 g_ao_hi[(size_t)BB*NQ*INNER];
__device__ __nv_bfloat16 g_ao_lo[(size_t)BB*NQ*INNER];
__device__ __nv_bfloat16 g_wqt_hi[(size_t)INNER*QD];
__device__ __nv_bfloat16 g_wqt_lo[(size_t)INNER*QD];
__device__ __nv_bfloat16 g_wkvt_hi[(size_t)KVN*CD];  // rows 0..1279 Wk^T, 1280.. Wv^T
__device__ __nv_bfloat16 g_wkvt_lo[(size_t)KVN*CD];
__device__ __nv_bfloat16 g_wot_hi[(size_t)QD*INNER];
__device__ __nv_bfloat16 g_wot_lo[(size_t)QD*INNER];
__device__ __nv_bfloat16 g_kimg_hi[(size_t)NBH*96*64];
__device__ __nv_bfloat16 g_kimg_lo[(size_t)NBH*96*64];
__device__ __nv_bfloat16 g_vimg_hi[(size_t)NBH*64*128];
__device__ __nv_bfloat16 g_vimg_lo[(size_t)NBH*64*128];
__device__ unsigned char g_fg[BB*NQ];

// ============================ PTX helpers ====================================
__device__ __forceinline__ uint32_t smem_to_u32(const void* p) {
    uint32_t a;
    asm("{ .reg .u64 t; cvta.to.shared.u64 t, %1; cvt.u32.u64 %0, t; }"
        : "=r"(a) : "l"(p));
    return a;
}

#if defined(__CUDA_ARCH_FEAT_SM103_ALL)
#define HAS_TCGEN05 1
#else
#define HAS_TCGEN05 0
#endif

#if HAS_TCGEN05
__device__ __forceinline__ uint32_t elect_one_pred() {
    uint32_t pred;
    asm volatile(
        "{\n\t.reg .pred p;\n\t"
        "elect.sync _|p, 0xFFFFFFFF;\n\t"
        "selp.b32 %0, 1, 0, p;\n\t}"
        : "=r"(pred));
    return pred;
}
#define TCGEN05_ALLOC(sa, n) \
    asm volatile("tcgen05.alloc.cta_group::1.sync.aligned.shared::cta.b32 [%0], %1;" \
        :: "r"((uint32_t)(sa)), "r"((uint32_t)(n)) : "memory")
#define TCGEN05_DEALLOC(t, n) \
    asm volatile("tcgen05.dealloc.cta_group::1.sync.aligned.b32 %0, %1;" :: "r"(t), "r"((uint32_t)(n)))
#define TCGEN05_RELINQ() \
    asm volatile("tcgen05.relinquish_alloc_permit.cta_group::1.sync.aligned;")
#define TCGEN05_COMMIT(mb) \
    asm volatile("tcgen05.commit.cta_group::1.mbarrier::arrive::one.shared::cluster.b64 [%0];" \
        :: "r"((uint32_t)(mb)) : "memory")
#define TCGEN05_FENCE_AFTER() asm volatile("tcgen05.fence::after_thread_sync;" ::: "memory")
#define TCGEN05_FENCE_BEFORE() asm volatile("tcgen05.fence::before_thread_sync;" ::: "memory")
#define TCGEN05_WAIT_LD() asm volatile("tcgen05.wait::ld.sync.aligned;" ::: "memory")
#define FENCE_ASYNC() asm volatile("fence.proxy.async.shared::cta;" ::: "memory")
#define MBARRIER_INIT(mb, c) \
    asm volatile("mbarrier.init.shared.b64 [%0], %1;" :: "r"((uint32_t)(mb)), "r"((uint32_t)(c)) : "memory")
#define MBARRIER_WAIT_PARITY(mb, ph) do { \
    uint32_t _m = (uint32_t)(mb), _p = (uint32_t)(ph), _d; \
    asm volatile("{\n\t.reg .pred p;\n\t" \
        "mbarrier.try_wait.parity.acquire.cta.shared::cta.b64 p, [%1], %2;\n\t" \
        "selp.b32 %0, 1, 0, p;\n\t}" : "=r"(_d) : "r"(_m), "r"(_p) : "memory"); \
    if (!_d) { \
        asm volatile("{\n\t.reg .pred P1;\n\t" \
            "WL_%=:\n\t" \
            "mbarrier.try_wait.parity.acquire.cta.shared::cta.b64 P1, [%0], %1, 0x989680;\n\t" \
            "@P1 bra.uni WD_%=;\n\t" \
            "bra.uni WL_%=;\n\t" \
            "WD_%=:\n\t}" :: "r"(_m), "r"(_p) : "memory"); \
    } \
} while (0)
#define TCGEN05_LD_32X32B_X32(r, ta) \
    asm volatile("tcgen05.ld.sync.aligned.32x32b.x32.b32 " \
        "{%0, %1, %2, %3, %4, %5, %6, %7, %8, %9, %10, %11, %12, %13, %14, %15, " \
        " %16, %17, %18, %19, %20, %21, %22, %23, %24, %25, %26, %27, %28, %29, %30, %31}, [%32];" \
        : "=r"((r)[0]),  "=r"((r)[1]),  "=r"((r)[2]),  "=r"((r)[3]), \
          "=r"((r)[4]),  "=r"((r)[5]),  "=r"((r)[6]),  "=r"((r)[7]), \
          "=r"((r)[8]),  "=r"((r)[9]),  "=r"((r)[10]), "=r"((r)[11]), \
          "=r"((r)[12]), "=r"((r)[13]), "=r"((r)[14]), "=r"((r)[15]), \
          "=r"((r)[16]), "=r"((r)[17]), "=r"((r)[18]), "=r"((r)[19]), \
          "=r"((r)[20]), "=r"((r)[21]), "=r"((r)[22]), "=r"((r)[23]), \
          "=r"((r)[24]), "=r"((r)[25]), "=r"((r)[26]), "=r"((r)[27]), \
          "=r"((r)[28]), "=r"((r)[29]), "=r"((r)[30]), "=r"((r)[31]) \
        : "r"(ta))

__device__ __forceinline__ void mma_f16_ss(uint32_t d_tmem, uint64_t a_desc,
                                           uint64_t b_desc, uint32_t idesc, bool acc)
{
    uint32_t en = acc ? 1u : 0u;
    asm volatile(
        "{\n\t.reg .pred p;\n\t"
        "setp.ne.u32 p, %5, 0;\n\t"
        "tcgen05.mma.cta_group::1.kind::f16 [%0], %1, %2, %3, {%4, %4, %4, %4}, p;\n\t}"
        :: "r"(d_tmem), "l"(a_desc), "l"(b_desc), "r"(idesc), "r"(0u), "r"(en)
        : "memory");
}
#endif // HAS_TCGEN05

static constexpr uint64_t SMEM_DESC_BASE_SW128 =
    (uint64_t(2)  << 61) | (uint64_t(1) << 46) | (uint64_t(64) << 32) | (uint64_t(1) << 16);
#define MAKE_SMEM_DESC(ba) (SMEM_DESC_BASE_SW128 | ((uint64_t)((ba) >> 4) & 0x3FFF))
#define SMEM_SWIZZLE_128B(bo) ((bo) ^ (((bo) >> 3) & 0x70))

__device__ __forceinline__ void bf16split(float f, ushort_t& h, ushort_t& l)
{
    __nv_bfloat16 hh = __float2bfloat16(f);
    __nv_bfloat16 ll = __float2bfloat16(f - __bfloat162float(hh));
    h = __bfloat16_as_ushort(hh);
    l = __bfloat16_as_ushort(ll);
}

// ---------------- mask: exact integer bicubic-threshold ----------------------
__global__ void mask_kernel(const int* __restrict__ mask)
{
    int idx = blockIdx.x * blockDim.x + threadIdx.x;
    if (idx >= BB*NQ) return;
    int b = idx / NQ, n = idx % NQ;
    int o = n >> 6, p = n & 63;
    const int iw[4] = {-3, 19, 19, -3};
    const int* mb = mask + (size_t)b * 256 * 256;
    int acc = 0;
#pragma unroll
    for (int s = 0; s < 4; s++) {
        const int* row = mb + (4*o + s) * 256 + 4*p;
        int rw = iw[s];
#pragma unroll
        for (int t = 0; t < 4; t++) acc += rw * iw[t] * row[t];
    }
    g_fg[idx] = (acc != 0) ? 1 : 0;
}

// ---------------- weight transpose + bf16 split -------------------------------
__global__ void wtrans_kernel(const float* __restrict__ W,
                              __nv_bfloat16* __restrict__ Thi,
                              __nv_bfloat16* __restrict__ Tlo, int K, int N)
{
    __shared__ float t[32][33];
    int k0 = blockIdx.x * 32, n0 = blockIdx.y * 32;
    int tx = threadIdx.x, ty = threadIdx.y;
    for (int r = ty; r < 32; r += 8)
        t[r][tx] = W[(size_t)(k0 + r)*N + n0 + tx];
    __syncthreads();
    for (int r = ty; r < 32; r += 8) {
        float v = t[tx][r];
        ushort_t h, l; bf16split(v, h, l);
        Thi[(size_t)(n0 + r)*K + k0 + tx] = __ushort_as_bfloat16(h);
        Tlo[(size_t)(n0 + r)*K + k0 + tx] = __ushort_as_bfloat16(l);
    }
}

// ================= bf16x3 tcgen05 GEMM: C = A@B^T (+bias) ====================
#define G_BM 128
#define G_BN 256
#define G_BK 64
#define G_BUFSZ 98304
#define G_SMEM  (2048 + 2*G_BUFSZ)
#define G_IDESC 0x08400490u   // F32 acc, BF16xBF16, N=256, M=128

__global__ void __launch_bounds__(256)
gemm_bf16x3(const float* __restrict__ Af,
            const __nv_bfloat16* __restrict__ Ahi, const __nv_bfloat16* __restrict__ Alo,
            const __nv_bfloat16* __restrict__ Bhi, const __nv_bfloat16* __restrict__ Blo,
            const float* __restrict__ bias, float* __restrict__ C,
            __nv_bfloat16* __restrict__ Chi, __nv_bfloat16* __restrict__ Clo,
            int Mvalid, int N, int K)
{
#if HAS_TCGEN05
    extern __shared__ char smem[];
    const uint32_t sb = smem_to_u32(smem);
    const uint32_t ab = (sb + 1024 + 1023) & ~1023u;
    char* abp = smem + (ab - sb);
    const int tid = threadIdx.x;
    const int wid = tid >> 5, lane = tid & 31;
    const int brow = blockIdx.y * G_BM;
    const int bcol = blockIdx.x * G_BN;

    if (wid == 0) TCGEN05_ALLOC(sb, 256);
    __syncthreads();
    uint32_t tmem;
    asm volatile("ld.shared.b32 %0, [%1];" : "=r"(tmem) : "r"(sb));
    if (wid == 0) TCGEN05_RELINQ();
    if (tid == 0) { MBARRIER_INIT(sb + 8, 1); MBARRIER_INIT(sb + 16, 1); }
    __syncthreads();

    const int KCH = K / G_BK;
    int par0 = 0, par1 = 0;

    uint4 pa0[4], pa1[4], pbh[8], pbl[8];
    const int a_row = tid >> 3;
    const int a_v   = tid & 7;

    auto load_chunk = [&](int c) {
        const int k0 = c * G_BK;
        if (Af) {
#pragma unroll
            for (int i = 0; i < 4; ++i) {
                int gr = brow + a_row + i*32;
                if (gr < Mvalid) {
                    const uint4* src = (const uint4*)(Af + (size_t)gr*K + k0 + a_v*8);
                    pa0[i] = src[0];
                    pa1[i] = src[1];
                } else {
                    pa0[i] = make_uint4(0u,0u,0u,0u);
                    pa1[i] = make_uint4(0u,0u,0u,0u);
                }
            }
        } else {
#pragma unroll
            for (int i = 0; i < 4; ++i) {
                int gr = brow + a_row + i*32;
                pa0[i] = *(const uint4*)(Ahi + (size_t)gr*K + k0 + a_v*8);
                pa1[i] = *(const uint4*)(Alo + (size_t)gr*K + k0 + a_v*8);
            }
        }
#pragma unroll
        for (int i = 0; i < 8; ++i) {
            int row = a_row + i*32;
            pbh[i] = *(const uint4*)(Bhi + (size_t)(bcol + row)*K + k0 + a_v*8);
            pbl[i] = *(const uint4*)(Blo + (size_t)(bcol + row)*K + k0 + a_v*8);
        }
    };

    load_chunk(0);

    for (int c = 0; c < KCH; ++c) {
        int p = c & 1;
        if (c >= 2) {
            if (p == 0) { MBARRIER_WAIT_PARITY(sb + 8, par0); par0 ^= 1; }
            else        { MBARRIER_WAIT_PARITY(sb + 16, par1); par1 ^= 1; }
        }
        char* base = abp + p * G_BUFSZ;

#pragma unroll
        for (int i = 0; i < 4; ++i) {
            uint32_t so = SMEM_SWIZZLE_128B((uint32_t)((a_row + i*32)*128 + a_v*16));
            uint4 vh, vl;
            if (Af) {
                const float* f0 = (const float*)&pa0[i];
                const float* f1 = (const float*)&pa1[i];
                float fa[8] = {f0[0], f0[1], f0[2], f0[3], f1[0], f1[1], f1[2], f1[3]};
                uint32_t hw[4], lw[4];
#pragma unroll
                for (int e = 0; e < 4; ++e) {
                    ushort_t h0, l0, h1, l1;
                    bf16split(fa[2*e],   h0, l0);
                    bf16split(fa[2*e+1], h1, l1);
                    hw[e] = ((uint32_t)h1 << 16) | h0;
                    lw[e] = ((uint32_t)l1 << 16) | l0;
                }
                vh = make_uint4(hw[0], hw[1], hw[2], hw[3]);
                vl = make_uint4(lw[0], lw[1], lw[2], lw[3]);
            } else {
                vh = pa0[i];
                vl = pa1[i];
            }
            *(uint4*)(base + so) = vh;
            *(uint4*)(base + 16384 + so) = vl;
        }
#pragma unroll
        for (int i = 0; i < 8; ++i) {
            uint32_t so = SMEM_SWIZZLE_128B((uint32_t)((a_row + i*32)*128 + a_v*16));
            *(uint4*)(base + 32768 + so) = pbh[i];
            *(uint4*)(base + 65536 + so) = pbl[i];
        }
        __syncthreads();

        if (wid == 0 && elect_one_pred()) {
            FENCE_ASYNC();
            uint32_t bu = ab + p * G_BUFSZ;
            uint64_t dah = MAKE_SMEM_DESC(bu);
            uint64_t dal = MAKE_SMEM_DESC(bu + 16384);
            uint64_t dbh = MAKE_SMEM_DESC(bu + 32768);
            uint64_t dbl = MAKE_SMEM_DESC(bu + 65536);
#pragma unroll
            for (int ks = 0; ks < 4; ++ks)
                mma_f16_ss(tmem, dah + ks*2, dbh + ks*2, G_IDESC, !(c == 0 && ks == 0));
#pragma unroll
            for (int ks = 0; ks < 4; ++ks)
                mma_f16_ss(tmem, dah + ks*2, dbl + ks*2, G_IDESC, true);
#pragma unroll
            for (int ks = 0; ks < 4; ++ks)
                mma_f16_ss(tmem, dal + ks*2, dbh + ks*2, G_IDESC, true);
            TCGEN05_COMMIT(sb + 8 + p*8);
        }

        if (c + 1 < KCH) load_chunk(c + 1);
    }
    MBARRIER_WAIT_PARITY(sb + 8, par0);
    MBARRIER_WAIT_PARITY(sb + 16, par1);
    TCGEN05_FENCE_AFTER();

    if (wid < 4) {
        int row = brow + wid*32 + lane;
#pragma unroll
        for (int cb = 0; cb < G_BN/32; ++cb) {
            uint32_t r[32];
            TCGEN05_LD_32X32B_X32(r, tmem + cb*32);
            TCGEN05_WAIT_LD();
            int col0 = bcol + cb*32;
            if (Chi) {
                uint32_t hp[16], lp[16];
#pragma unroll
                for (int m = 0; m < 16; ++m) {
                    ushort_t h0, l0, h1, l1;
                    bf16split(__uint_as_float(r[2*m]),   h0, l0);
                    bf16split(__uint_as_float(r[2*m+1]), h1, l1);
                    hp[m] = ((uint32_t)h1 << 16) | h0;
                    lp[m] = ((uint32_t)l1 << 16) | l0;
                }
                uint32_t* dh = (uint32_t*)(Chi + (size_t)row*N + col0);
                uint32_t* dl = (uint32_t*)(Clo + (size_t)row*N + col0);
#pragma unroll
                for (int m = 0; m < 16; ++m) { dh[m] = hp[m]; dl[m] = lp[m]; }
            } else {
                float* cp = C + (size_t)row*N + col0;
                if (bias) {
#pragma unroll
                    for (int i = 0; i < 32; ++i) cp[i] = __uint_as_float(r[i]) + bias[col0 + i];
                } else {
#pragma unroll
                    for (int i = 0; i < 32; ++i) cp[i] = __uint_as_float(r[i]);
                }
            }
        }
        TCGEN05_FENCE_BEFORE();
    }
    __syncthreads();
    if (wid == 0) TCGEN05_DEALLOC(tmem, 256);
#endif
}

// ---------------- K / V^T image bake (from merged g_kv) -----------------------
__global__ void __launch_bounds__(128) kv_image_kernel()
{
    int bh = blockIdx.x;
    int b = bh / NHEADS, h = bh % NHEADS;
    int tid = threadIdx.x;
    char* kh = (char*)(g_kimg_hi + (size_t)bh*96*64);
    char* kl = (char*)(g_kimg_lo + (size_t)bh*96*64);
    char* vh = (char*)(g_vimg_hi + (size_t)bh*64*128);
    char* vl = (char*)(g_vimg_lo + (size_t)bh*64*128);

    for (int u = tid; u < 96*64; u += 128) {
        int j = u >> 6, d = u & 63;
        float f = (j < CTX) ? g_kv[(size_t)(b*CTX + j)*KVN + h*DHEAD + d] : 0.f;
        ushort_t hh, ll; bf16split(f, hh, ll);
        uint32_t so = SMEM_SWIZZLE_128B((uint32_t)(j*128 + d*2));
        *(ushort_t*)(kh + so) = hh;
        *(ushort_t*)(kl + so) = ll;
    }
    for (int u = tid; u < 64*128; u += 128) {
        int d = u >> 7, j = u & 127;
        float f = (j < CTX) ? g_kv[(size_t)(b*CTX + j)*KVN + INNER + h*DHEAD + d] : 0.f;
        ushort_t hh, ll; bf16split(f, hh, ll);
        uint32_t addr = (uint32_t)(((d >> 3) + (j >> 6)*8)*1024 + (d & 7)*128 + (j & 63)*2);
        uint32_t so = SMEM_SWIZZLE_128B(addr);
        *(ushort_t*)(vh + so) = hh;
        *(ushort_t*)(vl + so) = ll;
    }
}

// ---------------- tcgen05 fused masked attention (pipelined) ------------------
#define ATT_QT 8
#define A_KHI 0
#define A_KLO 12288
#define A_VHI 24576
#define A_VLO 40960
#define A_Q0  57344        // +(t&1)*32768; hi at +0, lo at +16384
#define A_PHI 122880
#define A_PLO 155648
#define ATTN_SMEM (2048 + 188416)
#define IDESC_S 0x08180490u   // M=128, N=96
#define IDESC_O 0x08100490u   // M=128, N=64
// TMEM: S(t) at (t&1)*96 ; O(t) at 192 + (t&1)*64

#if HAS_TCGEN05
__device__ __forceinline__ void attn_issue_S(uint32_t tmem, uint32_t ab, int t)
{
    uint32_t qb = ab + A_Q0 + (uint32_t)(t & 1)*32768;
    uint64_t dqh = MAKE_SMEM_DESC(qb);
    uint64_t dql = MAKE_SMEM_DESC(qb + 16384);
    uint64_t dkh = MAKE_SMEM_DESC(ab + A_KHI);
    uint64_t dkl = MAKE_SMEM_DESC(ab + A_KLO);
    uint32_t dst = tmem + (uint32_t)(t & 1)*96;
#pragma unroll
    for (int ks = 0; ks < 4; ++ks)
        mma_f16_ss(dst, dqh + ks*2, dkh + ks*2, IDESC_S, ks > 0);
#pragma unroll
    for (int ks = 0; ks < 4; ++ks)
        mma_f16_ss(dst, dqh + ks*2, dkl + ks*2, IDESC_S, true);
#pragma unroll
    for (int ks = 0; ks < 4; ++ks)
        mma_f16_ss(dst, dql + ks*2, dkh + ks*2, IDESC_S, true);
}

__device__ __forceinline__ void attn_issue_O(uint32_t tmem, uint32_t ab, int t)
{
    uint64_t dph = MAKE_SMEM_DESC(ab + A_PHI);
    uint64_t dpl = MAKE_SMEM_DESC(ab + A_PLO);
    uint64_t dvh = MAKE_SMEM_DESC(ab + A_VHI);
    uint64_t dvl = MAKE_SMEM_DESC(ab + A_VLO);
    uint32_t dst = tmem + 192 + (uint32_t)(t & 1)*64;
#pragma unroll
    for (int ks = 0; ks < 8; ++ks) {
        uint64_t aoff = (ks < 4) ? ks*2 : 1024 + (ks-4)*2;
        uint64_t boff = (ks < 4) ? ks*2 : 512 + (ks-4)*2;
        mma_f16_ss(dst, dph + aoff, dvh + boff, IDESC_O, ks > 0);
    }
#pragma unroll
    for (int ks = 0; ks < 8; ++ks) {
        uint64_t aoff = (ks < 4) ? ks*2 : 1024 + (ks-4)*2;
        uint64_t boff = (ks < 4) ? ks*2 : 512 + (ks-4)*2;
        mma_f16_ss(dst, dph + aoff, dvl + boff, IDESC_O, true);
    }
#pragma unroll
    for (int ks = 0; ks < 8; ++ks) {
        uint64_t aoff = (ks < 4) ? ks*2 : 1024 + (ks-4)*2;
        uint64_t boff = (ks < 4) ? ks*2 : 512 + (ks-4)*2;
        mma_f16_ss(dst, dpl + aoff, dvh + boff, IDESC_O, true);
    }
}
#endif

__global__ void __launch_bounds__(128) attn_tc()
{
#if HAS_TCGEN05
    extern __shared__ char smem[];
    const uint32_t sb = smem_to_u32(smem);
    const uint32_t ab = (sb + 1024 + 1023) & ~1023u;
    char* abp = smem + (ab - sb);
    int tid = threadIdx.x, wid = tid >> 5;
    int b = blockIdx.z, h = blockIdx.y, qg = blockIdx.x;
    int bh = b*NHEADS + h;

    if (wid == 0) TCGEN05_ALLOC(sb, 512);
    __syncthreads();
    uint32_t tmem;
    asm volatile("ld.shared.b32 %0, [%1];" : "=r"(tmem) : "r"(sb));
    if (wid == 0) TCGEN05_RELINQ();
    if (tid == 0) { MBARRIER_INIT(sb + 8, 1); MBARRIER_INIT(sb + 16, 1); }
    __syncthreads();

    {
        const uint4* skh = (const uint4*)(g_kimg_hi + (size_t)bh*96*64);
        const uint4* skl = (const uint4*)(g_kimg_lo + (size_t)bh*96*64);
        for (int u = tid; u < 768; u += 128) {
            ((uint4*)(abp + A_KHI))[u] = skh[u];
            ((uint4*)(abp + A_KLO))[u] = skl[u];
        }
        const uint4* svh = (const uint4*)(g_vimg_hi + (size_t)bh*64*128);
        const uint4* svl = (const uint4*)(g_vimg_lo + (size_t)bh*64*128);
        for (int u = tid; u < 1024; u += 128) {
            ((uint4*)(abp + A_VHI))[u] = svh[u];
            ((uint4*)(abp + A_VLO))[u] = svl[u];
        }
    }
    {
        int qbase = qg*ATT_QT*128;
        size_t qrow = (size_t)(b*NQ + qbase + tid)*INNER + h*DHEAD;
        const uint4* qh = (const uint4*)(g_qhi + qrow);
        const uint4* ql = (const uint4*)(g_qlo + qrow);
#pragma unroll
        for (int v = 0; v < 8; ++v) {
            uint32_t so = SMEM_SWIZZLE_128B((uint32_t)(tid*128 + v*16));
            *(uint4*)(abp + A_Q0 + so) = qh[v];
            *(uint4*)(abp + A_Q0 + 16384 + so) = ql[v];
        }
    }
    __syncthreads();
    if (wid == 0 && elect_one_pred()) {
        FENCE_ASYNC();
        attn_issue_S(tmem, ab, 0);
        TCGEN05_COMMIT(sb + 8);
    }

    int ps = 0, po = 0;
    float inv_prev = 0.f;

    for (int t = 0; t < ATT_QT; ++t) {
        int qbase = (qg*ATT_QT + t)*128;

        MBARRIER_WAIT_PARITY(sb + 8, ps); ps ^= 1;
        TCGEN05_FENCE_AFTER();
        float s[96];
#pragma unroll
        for (int cb = 0; cb < 3; ++cb) {
            uint32_t rr[32];
            TCGEN05_LD_32X32B_X32(rr, tmem + (t & 1)*96 + cb*32);
            TCGEN05_WAIT_LD();
#pragma unroll
            for (int i = 0; i < 32; ++i) s[cb*32 + i] = __uint_as_float(rr[i]);
        }
        TCGEN05_FENCE_BEFORE();

        if (t + 1 < ATT_QT) {
            size_t qrow = (size_t)(b*NQ + qbase + 128 + tid)*INNER + h*DHEAD;
            const uint4* qh = (const uint4*)(g_qhi + qrow);
            const uint4* ql = (const uint4*)(g_qlo + qrow);
            uint32_t qoff = A_Q0 + (uint32_t)((t + 1) & 1)*32768;
#pragma unroll
            for (int v = 0; v < 8; ++v) {
                uint32_t so = SMEM_SWIZZLE_128B((uint32_t)(tid*128 + v*16));
                *(uint4*)(abp + qoff + so) = qh[v];
                *(uint4*)(abp + qoff + 16384 + so) = ql[v];
            }
            __syncthreads();
            if (wid == 0 && elect_one_pred()) {
                FENCE_ASYNC();
                attn_issue_S(tmem, ab, t + 1);
                TCGEN05_COMMIT(sb + 8);
            }
        }

        int fg = g_fg[b*NQ + qbase + tid];
        float mx = -FLT_MAX;
#pragma unroll
        for (int j = 0; j < CTX; ++j) {
            float a = s[j] * 0.125f;
            bool valid = (j < 77) || ((j < 81) ? (fg != 0) : (fg == 0));
            a = valid ? a : -FLT_MAX;
            s[j] = a;
            mx = fmaxf(mx, a);
        }
        float sum = 0.f;
#pragma unroll
        for (int j = 0; j < CTX; ++j) {
            float e = (s[j] > -3.0e38f) ? __expf(s[j] - mx) : 0.f;
            s[j] = e;
            sum += e;
        }
        float inv = 1.f / sum;
#pragma unroll
        for (int j = CTX; j < 96; ++j) s[j] = 0.f;

        if (t >= 1) {
            MBARRIER_WAIT_PARITY(sb + 16, po); po ^= 1;
            TCGEN05_FENCE_AFTER();
            size_t obase = (size_t)(b*NQ + qbase - 128 + tid)*INNER + h*DHEAD;
#pragma unroll
            for (int cb = 0; cb < 2; ++cb) {
                uint32_t rr[32];
                TCGEN05_LD_32X32B_X32(rr, tmem + 192 + ((t - 1) & 1)*64 + cb*32);
                TCGEN05_WAIT_LD();
#pragma unroll
                for (int g = 0; g < 4; ++g) {
                    uint32_t hv[4], lv[4];
#pragma unroll
                    for (int pe = 0; pe < 4; ++pe) {
                        float f0 = __uint_as_float(rr[g*8 + 2*pe])     * inv_prev;
                        float f1 = __uint_as_float(rr[g*8 + 2*pe + 1]) * inv_prev;
                        ushort_t h0, l0, h1, l1;
                        bf16split(f0, h0, l0);
                        bf16split(f1, h1, l1);
                        hv[pe] = ((uint32_t)h1 << 16) | h0;
                        lv[pe] = ((uint32_t)l1 << 16) | l0;
                    }
                    *(uint4*)(g_ao_hi + obase + cb*32 + g*8) = make_uint4(hv[0], hv[1], hv[2], hv[3]);
                    *(uint4*)(g_ao_lo + obase + cb*32 + g*8) = make_uint4(lv[0], lv[1], lv[2], lv[3]);
                }
            }
            TCGEN05_FENCE_BEFORE();
        }

        {
            int r = tid;
#pragma unroll
            for (int g = 0; g < 16; ++g) {
                int c0 = g*8;
                uint32_t hv[4], lv[4];
#pragma unroll
                for (int pe = 0; pe < 4; ++pe) {
                    int c = c0 + 2*pe;
                    float f0 = (c < 96) ? s[c] : 0.f;
                    float f1 = (c+1 < 96) ? s[c+1] : 0.f;
                    ushort_t h0, l0, h1, l1;
                    bf16split(f0, h0, l0);
                    bf16split(f1, h1, l1);
                    hv[pe] = ((uint32_t)h1 << 16) | h0;
                    lv[pe] = ((uint32_t)l1 << 16) | l0;
                }
                uint32_t addr = (uint32_t)(((r >> 3) + (c0 >> 6)*16)*1024 + (r & 7)*128 + (c0 & 63)*2);
                uint32_t so = SMEM_SWIZZLE_128B(addr);
                *(uint4*)(abp + A_PHI + so) = make_uint4(hv[0], hv[1], hv[2], hv[3]);
                *(uint4*)(abp + A_PLO + so) = make_uint4(lv[0], lv[1], lv[2], lv[3]);
            }
        }
        __syncthreads();
        if (wid == 0 && elect_one_pred()) {
            FENCE_ASYNC();
            attn_issue_O(tmem, ab, t);
            TCGEN05_COMMIT(sb + 16);
        }
        inv_prev = inv;
    }

    MBARRIER_WAIT_PARITY(sb + 16, po);
    TCGEN05_FENCE_AFTER();
    {
        int qbase = (qg*ATT_QT + ATT_QT - 1)*128;
        size_t obase = (size_t)(b*NQ + qbase + tid)*INNER + h*DHEAD;
#pragma unroll
        for (int cb = 0; cb < 2; ++cb) {
            uint32_t rr[32];
            TCGEN05_LD_32X32B_X32(rr, tmem + 192 + ((ATT_QT - 1) & 1)*64 + cb*32);
            TCGEN05_WAIT_LD();
#pragma unroll
            for (int g = 0; g < 4; ++g) {
                uint32_t hv[4], lv[4];
#pragma unroll
                for (int pe = 0; pe < 4; ++pe) {
                    float f0 = __uint_as_float(rr[g*8 + 2*pe])     * inv_prev;
                    float f1 = __uint_as_float(rr[g*8 + 2*pe + 1]) * inv_prev;
                    ushort_t h0, l0, h1, l1;
                    bf16split(f0, h0, l0);
                    bf16split(f1, h1, l1);
                    hv[pe] = ((uint32_t)h1 << 16) | h0;
                    lv[pe] = ((uint32_t)l1 << 16) | l0;
                }
                *(uint4*)(g_ao_hi + obase + cb*32 + g*8) = make_uint4(hv[0], hv[1], hv[2], hv[3]);
                *(uint4*)(g_ao_lo + obase + cb*32 + g*8) = make_uint4(lv[0], lv[1], lv[2], lv[3]);
            }
        }
        TCGEN05_FENCE_BEFORE();
    }
    __syncthreads();
    if (wid == 0) TCGEN05_DEALLOC(tmem, 512);
#endif
}

// ---------------- launch ------------------------------------------------------
extern "C" void kernel_launch(void* const* d_in, const int* in_sizes, int n_in,
                              void* d_out, int out_size)
{
    (void)in_sizes; (void)n_in; (void)out_size;
    const float* x    = (const float*)d_in[0];
    const float* ctxp = (const float*)d_in[1];
    const float* Wq   = (const float*)d_in[2];
    const float* Wk   = (const float*)d_in[3];
    const float* Wv   = (const float*)d_in[4];
    const float* Wo   = (const float*)d_in[5];
    const float* bo   = (const float*)d_in[6];
    const int*   mask = (const int*)d_in[7];
    float* out = (float*)d_out;

    float *kv;
    __nv_bfloat16 *qhi, *qlo, *aohi, *aolo;
    __nv_bfloat16 *wqth, *wqtl, *wkvth, *wkvtl, *woth, *wotl;
    cudaGetSymbolAddress((void**)&kv,    g_kv);
    cudaGetSymbolAddress((void**)&qhi,   g_qhi);
    cudaGetSymbolAddress((void**)&qlo,   g_qlo);
    cudaGetSymbolAddress((void**)&aohi,  g_ao_hi);
    cudaGetSymbolAddress((void**)&aolo,  g_ao_lo);
    cudaGetSymbolAddress((void**)&wqth,  g_wqt_hi);
    cudaGetSymbolAddress((void**)&wqtl,  g_wqt_lo);
    cudaGetSymbolAddress((void**)&wkvth, g_wkvt_hi);
    cudaGetSymbolAddress((void**)&wkvtl, g_wkvt_lo);
    cudaGetSymbolAddress((void**)&woth,  g_wot_hi);
    cudaGetSymbolAddress((void**)&wotl,  g_wot_lo);

    cudaFuncSetAttribute(gemm_bf16x3, cudaFuncAttributeMaxDynamicSharedMemorySize, G_SMEM);
    cudaFuncSetAttribute(attn_tc, cudaFuncAttributeMaxDynamicSharedMemorySize, ATTN_SMEM);

    dim3 blk(32, 8);

    // fork: side-chain (mask, Wk/Wv/Wo transposes, KV GEMM, KV image) runs on a
    // separate stream concurrent with wtrans(Wq) -> Q GEMM on the main stream.
    // Streams/events are host-side objects (no device memory); created fresh per
    // call and leaked intentionally (kernel_launch runs only a handful of times).
    cudaStream_t s2;
    cudaEvent_t evFork, evJoin;
    cudaStreamCreateWithFlags(&s2, cudaStreamNonBlocking);
    cudaEventCreateWithFlags(&evFork, cudaEventDisableTiming);
    cudaEventCreateWithFlags(&evJoin, cudaEventDisableTiming);

    cudaEventRecord(evFork, 0);
    cudaStreamWaitEvent(s2, evFork, 0);

    // side chain on s2
    mask_kernel<<<(BB*NQ + 255)/256, 256, 0, s2>>>(mask);
    wtrans_kernel<<<dim3(CD/32, INNER/32), blk, 0, s2>>>(Wk, wkvth, wkvtl, CD, INNER);
    wtrans_kernel<<<dim3(CD/32, INNER/32), blk, 0, s2>>>(
        Wv, wkvth + (size_t)INNER*CD, wkvtl + (size_t)INNER*CD, CD, INNER);
    wtrans_kernel<<<dim3(INNER/32, QD/32), blk, 0, s2>>>(Wo, woth, wotl, INNER, QD);
    gemm_bf16x3<<<dim3(KVN/G_BN, MKV/G_BM), 256, G_SMEM, s2>>>(
        ctxp, nullptr, nullptr, wkvth, wkvtl, nullptr, kv, nullptr, nullptr,
        BB*CTX, KVN, CD);
    kv_image_kernel<<<NBH, 128, 0, s2>>>();
    cudaEventRecord(evJoin, s2);

    // main chain on capture stream
    wtrans_kernel<<<dim3(QD/32, INNER/32), blk>>>(Wq, wqth, wqtl, QD, INNER);
    gemm_bf16x3<<<dim3(INNER/G_BN, (BB*NQ)/G_BM), 256, G_SMEM>>>(
        x, nullptr, nullptr, wqth, wqtl, nullptr, nullptr, qhi, qlo,
        BB*NQ, INNER, QD);

    cudaStreamWaitEvent(0, evJoin, 0);

    // attention + output projection
    attn_tc<<<dim3(NQ/(ATT_QT*128), NHEADS, BB), 128, ATTN_SMEM>>>();
    gemm_bf16x3<<<dim3(QD/G_BN, (BB*NQ)/G_BM), 256, G_SMEM>>>(
        nullptr, aohi, aolo, woth, wotl, bo, out, nullptr, nullptr,
        BB*NQ, QD, INNER);
}